// round 1
// baseline (speedup 1.0000x reference)
#include <cuda_runtime.h>
#include <cstdint>

// ----------------------------------------------------------------------------
// TextClassifier: 16-qubit "QFNet" classifier.
//
// Key algebra:
//  - 16 commuting 1-qubit gates = (A over seq bits) kron (B over embed bits)
//    -> two butterfly passes (7 stages over 128-dim rows, 9 stages over
//       512-dim columns) instead of dense GEMMs.
//  - CNOT ring = prefix-XOR permutation, decomposed as:
//       col perm:  e -> pxe(e)                (folded into row-butterfly write)
//       row perm:  s -> pxs(s)                (folded into col-butterfly epilogue)
//       cross:     e'' = pxe(e) ^ (par(s)?127:0);  s'' = pxs(s) ^ ((e''&1)<<8)
//  - abs() kills phases; block2 output only feeds a mean over s, so block2
//    accumulates column sums instead of writing 64MB.
// ----------------------------------------------------------------------------

#define NB   256        // batch
#define NS   512        // seq
#define NE   128        // embed
#define NDIM 65536      // NS*NE

__device__ float  g_x[NB * NDIM];            // 64 MB: embedding / x1 (in-place)
__device__ float2 g_state[NB * NDIM];        // 128 MB: complex state scratch
__device__ float  g_norms[2][NB];            // sumsq per batch, per block
__device__ float  g_m[NB * NE];              // column sums -> mean
__device__ float  g_gmats[2 * 16 * 8];       // 2x2 complex gate per (block, wire)

// ---------------- helpers ----------------

__device__ __forceinline__ void gpair(const float* g, float2& lo, float2& hi) {
    // [lo';hi'] = [[m00 m01],[m10 m11]] [lo;hi], complex
    float2 l = lo, h = hi;
    lo = make_float2(g[0]*l.x - g[1]*l.y + g[2]*h.x - g[3]*h.y,
                     g[0]*l.y + g[1]*l.x + g[2]*h.y + g[3]*h.x);
    hi = make_float2(g[4]*l.x - g[5]*l.y + g[6]*h.x - g[7]*h.y,
                     g[4]*l.y + g[5]*l.x + g[6]*h.y + g[7]*h.x);
}

__device__ __forceinline__ float2 gshuf(const float* g, float2 v, int ls, int lane) {
    float2 p;
    p.x = __shfl_xor_sync(0xffffffffu, v.x, ls);
    p.y = __shfl_xor_sync(0xffffffffu, v.y, ls);
    if (lane & ls) {
        // I'm the 'hi' element: partner p is 'lo'
        return make_float2(g[4]*p.x - g[5]*p.y + g[6]*v.x - g[7]*v.y,
                           g[4]*p.y + g[5]*p.x + g[6]*v.y + g[7]*v.x);
    } else {
        return make_float2(g[0]*v.x - g[1]*v.y + g[2]*p.x - g[3]*p.y,
                           g[0]*v.y + g[1]*v.x + g[2]*p.y + g[3]*p.x);
    }
}

// ---------------- tiny setup kernels ----------------

__global__ void k_zero() {
    int i = blockIdx.x * blockDim.x + threadIdx.x;
    if (i < NB * NE) g_m[i] = 0.f;
    if (i < 2 * NB)  ((float*)g_norms)[i] = 0.f;
}

__global__ void k_rot(const float* __restrict__ rp) {
    int t = threadIdx.x;                     // t = blk*16 + wire, 32 threads
    if (t >= 32) return;
    float th = rp[t*3+0], ph = rp[t*3+1], om = rp[t*3+2];
    float c, s;  sincosf(0.5f * th, &s, &c);
    float ap = -0.5f * (ph + om);
    float am = -0.5f * (ph - om);
    float cap, sap; sincosf(ap, &sap, &cap);
    float cam, sam; sincosf(am, &sam, &cam);
    float* o = g_gmats + t * 8;
    o[0] =  cap * c;  o[1] =  sap * c;     // m00 = e^{-i(p+w)/2} c
    o[2] = -cam * s;  o[3] =  sam * s;     // m01 = -e^{+i(p-w)/2} s
    o[4] =  cam * s;  o[5] =  sam * s;     // m10 = e^{-i(p-w)/2} s
    o[6] =  cap * c;  o[7] = -sap * c;     // m11 = e^{+i(p+w)/2} c
}

// ---------------- embedding + norm for block 0 ----------------

__global__ void k_embed(const int* __restrict__ tokens,
                        const float* __restrict__ temb,
                        const float* __restrict__ pemb) {
    int bs = blockIdx.x;                 // 0 .. 131071
    int tid = threadIdx.x;               // 0 .. 127
    int b = bs >> 9, s = bs & 511;
    int tok = tokens[bs];
    float val = __ldg(&temb[tok * NE + tid]) + pemb[s * NE + tid];
    g_x[bs * NE + tid] = val;
    float ss = val * val;
    #pragma unroll
    for (int o = 16; o; o >>= 1) ss += __shfl_down_sync(0xffffffffu, ss, o);
    __shared__ float sw[4];
    if ((tid & 31) == 0) sw[tid >> 5] = ss;
    __syncthreads();
    if (tid == 0) atomicAdd(&g_norms[0][b], sw[0] + sw[1] + sw[2] + sw[3]);
}

// ---------------- row butterfly: wires 9..15 (embed axis) ----------------
// Normalizes, applies 7 butterfly stages in registers/shuffles, writes the
// state with the embed prefix-xor permutation already applied (via smem).

__global__ __launch_bounds__(256) void k_rowfly(int blk) {
    __shared__ __align__(16) float gm[56];
    __shared__ float2 buf[8][128];
    int tid = threadIdx.x;
    if (tid < 56) gm[tid] = g_gmats[blk * 128 + 72 + tid];   // wires 9..15
    __syncthreads();
    int warp = tid >> 5, lane = tid & 31;
    int row = blockIdx.x * 8 + warp;            // 0 .. 131071 (b*512 + s)
    int b = row >> 9;
    float inv = rsqrtf(g_norms[blk][b]);
    const float* src = g_x + row * NE;
    float2 v[4];
    #pragma unroll
    for (int j = 0; j < 4; j++) {
        float t = src[lane + 32 * j] * inv;
        v[j] = make_float2(t, 0.f);
    }
    // wire 9 (stride 64), wire 10 (stride 32): in-register pairs
    gpair(&gm[0], v[0], v[2]);  gpair(&gm[0], v[1], v[3]);
    gpair(&gm[8], v[0], v[1]);  gpair(&gm[8], v[2], v[3]);
    // wires 11..15: lane strides 16,8,4,2,1
    #pragma unroll
    for (int st = 0; st < 5; st++) {
        int ls = 16 >> st;
        const float* g = &gm[16 + st * 8];
        #pragma unroll
        for (int j = 0; j < 4; j++) v[j] = gshuf(g, v[j], ls, lane);
    }
    // embed prefix-xor permutation via smem staging, then coalesced write
    #pragma unroll
    for (int j = 0; j < 4; j++) {
        int e = lane + 32 * j;
        int pe = e; pe ^= pe >> 1; pe ^= pe >> 2; pe ^= pe >> 4;
        buf[warp][pe] = v[j];
    }
    __syncwarp();
    float2* dst = g_state + (size_t)row * NE;
    #pragma unroll
    for (int j = 0; j < 4; j++) dst[lane + 32 * j] = buf[warp][lane + 32 * j];
}

// ---------------- column butterfly: wires 0..8 (seq axis) + epilogue -------
// CTA = one batch x one column group {c0..c0+3} U {124-c0..127-c0}
// (mirror pair so the conditional e^=127 stays inside the tile).
// mode 0 (block 1): permute + abs + residual (in place into g_x) + sumsq +
//                   column-sum accumulation.
// mode 1 (block 2): abs -> column-sum accumulation only (no 64MB write).

__global__ __launch_bounds__(256) void k_colfly(int blk, int mode) {
    __shared__ __align__(16) float gm[72];
    __shared__ float2 tin[8][513];
    __shared__ float scol[8];
    int tid = threadIdx.x;
    if (tid < 72) gm[tid] = g_gmats[blk * 128 + tid];        // wires 0..8
    if (tid < 8)  scol[tid] = 0.f;
    int b = blockIdx.x >> 4, grp = blockIdx.x & 15, c0 = grp * 4;
    int i = tid & 3, strip = (tid >> 2) & 1, rb = tid >> 3;
    int gcolL = strip ? (124 - c0 + i) : (c0 + i);
    int cidxL = strip * 4 + i;
    const float2* st = g_state + (size_t)b * NDIM;
    #pragma unroll
    for (int it = 0; it < 16; it++) {
        int r = rb + it * 32;
        tin[cidxL][r] = st[r * NE + gcolL];
    }
    __syncthreads();
    int w = tid >> 5, lane = tid & 31;
    float2 v[16];
    #pragma unroll
    for (int j = 0; j < 16; j++) v[j] = tin[w][lane + 32 * j];
    __syncthreads();   // tin registers captured; smem reusable below
    // wires 0..3: row strides 256,128,64,32 -> register-index strides 8,4,2,1
    #pragma unroll
    for (int wi = 0; wi < 4; wi++) {
        int js = 8 >> wi;
        const float* g = &gm[wi * 8];
        #pragma unroll
        for (int j = 0; j < 16; j++)
            if (!(j & js)) gpair(g, v[j], v[j + js]);
    }
    // wires 4..8: lane strides 16,8,4,2,1
    #pragma unroll
    for (int st2 = 0; st2 < 5; st2++) {
        int ls = 16 >> st2;
        const float* g = &gm[(4 + st2) * 8];
        #pragma unroll
        for (int j = 0; j < 16; j++) v[j] = gshuf(g, v[j], ls, lane);
    }
    int colw = (w < 4) ? (c0 + w) : (120 - c0 + w);   // physical column label
    if (mode == 0) {
        float* tf = reinterpret_cast<float*>(tin);
        #pragma unroll
        for (int j = 0; j < 16; j++) {
            int s = lane + 32 * j;
            int sp = s; sp ^= sp >> 1; sp ^= sp >> 2; sp ^= sp >> 4; sp ^= sp >> 8;
            int par = sp & 1;                           // parity of seq bits
            int cO    = par ? (7 - w) : w;              // tile idx of e''
            int gcolO = par ? (colw ^ 127) : colw;      // e''
            int sdd   = sp ^ ((gcolO & 1) << 8);        // s''
            float mag = sqrtf(v[j].x * v[j].x + v[j].y * v[j].y);
            tf[cO * 513 + sdd] = mag;
        }
        __syncthreads();
        float* xio = g_x + (size_t)b * NDIM;
        float ss = 0.f, cs = 0.f;
        #pragma unroll
        for (int it = 0; it < 16; it++) {
            int r = rb + it * 32;
            float val = tf[cidxL * 513 + r] + xio[r * NE + gcolL];
            xio[r * NE + gcolL] = val;                  // x1 in place
            ss += val * val;
            cs += val;
        }
        atomicAdd(&scol[cidxL], cs);
        #pragma unroll
        for (int o = 16; o; o >>= 1) ss += __shfl_down_sync(0xffffffffu, ss, o);
        if (lane == 0) atomicAdd(&g_norms[1][b], ss);
        __syncthreads();
        if (tid < 8) {
            int gc = (tid < 4) ? (c0 + tid) : (120 - c0 + tid);
            atomicAdd(&g_m[b * NE + gc], scol[tid]);
        }
    } else {
        // block 2: only column sums of |state| matter (mean over s)
        float aO = 0.f, aM = 0.f;
        #pragma unroll
        for (int j = 0; j < 16; j++) {
            int s = lane + 32 * j;
            float mag = sqrtf(v[j].x * v[j].x + v[j].y * v[j].y);
            if (__popc(s) & 1) aM += mag; else aO += mag;
        }
        #pragma unroll
        for (int o = 16; o; o >>= 1) {
            aO += __shfl_down_sync(0xffffffffu, aO, o);
            aM += __shfl_down_sync(0xffffffffu, aM, o);
        }
        if (lane == 0) {
            atomicAdd(&g_m[b * NE + colw], aO);
            atomicAdd(&g_m[b * NE + (colw ^ 127)], aM);
        }
    }
}

// ---------------- final linear + mean + classifier ----------------

__global__ void k_final(const float* __restrict__ ffw, const float* __restrict__ ffb,
                        const float* __restrict__ clsw, float* __restrict__ out) {
    int b = blockIdx.x, tid = threadIdx.x;
    __shared__ float mm[128], f[128];
    mm[tid] = g_m[b * NE + tid] * (1.f / 512.f);
    __syncthreads();
    float acc = ffb[tid];
    #pragma unroll 8
    for (int e = 0; e < 128; e++) acc += mm[e] * ffw[tid * 128 + e];
    f[tid] = acc;
    __syncthreads();
    if (tid < 4) {
        float o = 0.f;
        #pragma unroll 8
        for (int j = 0; j < 128; j++) o += f[j] * clsw[tid * 128 + j];
        out[b * 4 + tid] = o;
    }
}

// ---------------- launch ----------------

extern "C" void kernel_launch(void* const* d_in, const int* in_sizes, int n_in,
                              void* d_out, int out_size) {
    const int*   tokens = (const int*)  d_in[0];
    const float* temb   = (const float*)d_in[1];
    const float* pemb   = (const float*)d_in[2];
    const float* rotp   = (const float*)d_in[3];
    const float* ffw    = (const float*)d_in[4];
    const float* ffb    = (const float*)d_in[5];
    const float* clsw   = (const float*)d_in[6];
    float* out = (float*)d_out;

    k_zero<<<(NB * NE + 255) / 256, 256>>>();
    k_rot<<<1, 32>>>(rotp);
    k_embed<<<NB * NS, NE>>>(tokens, temb, pemb);

    // block 1
    k_rowfly<<<NB * NS / 8, 256>>>(0);
    k_colfly<<<NB * 16, 256>>>(0, 0);
    // block 2
    k_rowfly<<<NB * NS / 8, 256>>>(1);
    k_colfly<<<NB * 16, 256>>>(1, 1);

    k_final<<<NB, 128>>>(ffw, ffb, clsw, out);
}

// round 3
// speedup vs baseline: 1.6259x; 1.6259x over previous
#include <cuda_runtime.h>
#include <cstdint>

// ----------------------------------------------------------------------------
// QFNet classifier, round 2: f32x2-packed butterflies + fused pipeline.
//   k_init       : zero accumulators, build 2x2 gate matrices
//   k_embed_row  : embed gather -> write x0 -> B1 embed butterfly -> g_state
//                  (un-normalized, unpermuted; norm deferred, perm at read)
//   k_colA       : A1 seq butterfly -> CNOT perm -> |.|*inv_n0 + x0 = x1 (smem
//                  only) -> stats -> A2 seq butterfly (block 2) -> g_state
//   k_rowB       : B2 embed butterfly -> |.|*inv_n1 -> column sums into g_m
//   k_final      : mean + linear + classifier
// ----------------------------------------------------------------------------

#define NB   256
#define NS   512
#define NE   128
#define NDIM 65536

typedef unsigned long long u64;

__device__ float  g_x[NB * NDIM];        // x0 (embedding), natural layout
__device__ float2 g_state[NB * NDIM];    // complex scratch
__device__ float  g_norms[2][NB];
__device__ float  g_m[NB * NE];
__device__ float  g_gmats[2 * 16 * 8];   // [blk][wire][m00r,m00i,m01r,m01i,m10r,m10i,m11r,m11i]

// ---------------- f32x2 primitives ----------------

__device__ __forceinline__ u64 pk2(float lo, float hi) {
    u64 r; asm("mov.b64 %0, {%1, %2};" : "=l"(r) : "f"(lo), "f"(hi)); return r;
}
__device__ __forceinline__ void up2(u64 v, float& lo, float& hi) {
    asm("mov.b64 {%0, %1}, %2;" : "=f"(lo), "=f"(hi) : "l"(v));
}
__device__ __forceinline__ u64 sp2(float v) { return pk2(v, v); }
__device__ __forceinline__ u64 ffma2(u64 a, u64 b, u64 c) {
    u64 d; asm("fma.rn.f32x2 %0, %1, %2, %3;" : "=l"(d) : "l"(a), "l"(b), "l"(c)); return d;
}
__device__ __forceinline__ u64 fmul2(u64 a, u64 b) {
    u64 d; asm("mul.rn.f32x2 %0, %1, %2;" : "=l"(d) : "l"(a), "l"(b)); return d;
}
__device__ __forceinline__ u64 swp2(u64 v) {
    float a, b; up2(v, a, b); return pk2(b, a);
}

// gate = [[a,b],[c,d]] complex; splatted with negated imags pre-folded
struct C8 { u64 ar,ai,nai,br,bi,nbi,cr,ci,nci,dr,di,ndi; };
__device__ __forceinline__ C8 mkreg(const float* g) {
    C8 c;
    c.ar=sp2(g[0]); c.ai=sp2(g[1]); c.nai=sp2(-g[1]);
    c.br=sp2(g[2]); c.bi=sp2(g[3]); c.nbi=sp2(-g[3]);
    c.cr=sp2(g[4]); c.ci=sp2(g[5]); c.nci=sp2(-g[5]);
    c.dr=sp2(g[6]); c.di=sp2(g[7]); c.ndi=sp2(-g[7]);
    return c;
}
// L' = a*L + b*H ; H' = c*L + d*H  (complex, 2 elems per pack)
__device__ __forceinline__ void bpair(const C8& g, u64& Lx, u64& Ly, u64& Hx, u64& Hy) {
    u64 ox = ffma2(g.ar,Lx, ffma2(g.nai,Ly, ffma2(g.br,Hx, fmul2(g.nbi,Hy))));
    u64 oy = ffma2(g.ar,Ly, ffma2(g.ai, Lx, ffma2(g.br,Hy, fmul2(g.bi, Hx))));
    u64 px = ffma2(g.cr,Lx, ffma2(g.nci,Ly, ffma2(g.dr,Hx, fmul2(g.ndi,Hy))));
    u64 py = ffma2(g.cr,Ly, ffma2(g.ci, Lx, ffma2(g.dr,Hy, fmul2(g.di, Hx))));
    Lx = ox; Ly = oy; Hx = px; Hy = py;
}

struct C6 { u64 csr,csi,ncsi,cpr,cpi,ncpi; };
// per-lane role coeffs for a shuffle stage (hoisted: once per stage)
__device__ __forceinline__ C6 mkshuf(const float* g, int hibit) {
    float s0, s1, p0, p1;
    if (hibit) { s0=g[6]; s1=g[7]; p0=g[4]; p1=g[5]; }
    else       { s0=g[0]; s1=g[1]; p0=g[2]; p1=g[3]; }
    C6 c; c.csr=sp2(s0); c.csi=sp2(s1); c.ncsi=sp2(-s1);
          c.cpr=sp2(p0); c.cpi=sp2(p1); c.ncpi=sp2(-p1);
    return c;
}
// within-pack stage: even elem = lo, odd = hi
__device__ __forceinline__ C6 mkpk(const float* g) {
    C6 c; c.csr=pk2(g[0],g[6]); c.csi=pk2(g[1],g[7]); c.ncsi=pk2(-g[1],-g[7]);
          c.cpr=pk2(g[2],g[4]); c.cpi=pk2(g[3],g[5]); c.ncpi=pk2(-g[3],-g[5]);
    return c;
}
__device__ __forceinline__ void bshuf(const C6& c, u64& X, u64& Y, int ls) {
    u64 px = __shfl_xor_sync(0xffffffffu, X, ls);
    u64 py = __shfl_xor_sync(0xffffffffu, Y, ls);
    u64 ox = ffma2(c.csr,X, ffma2(c.ncsi,Y, ffma2(c.cpr,px, fmul2(c.ncpi,py))));
    u64 oy = ffma2(c.csr,Y, ffma2(c.csi,X, ffma2(c.cpr,py, fmul2(c.cpi,px))));
    X = ox; Y = oy;
}
__device__ __forceinline__ void bpack(const C6& c, u64& X, u64& Y) {
    u64 sx = swp2(X), sy = swp2(Y);
    u64 ox = ffma2(c.csr,X, ffma2(c.ncsi,Y, ffma2(c.cpr,sx, fmul2(c.ncpi,sy))));
    u64 oy = ffma2(c.csr,Y, ffma2(c.csi,X, ffma2(c.cpr,sy, fmul2(c.cpi,sx))));
    X = ox; Y = oy;
}

// 7-stage embed butterfly. Layout: e = 16*t + j (t = lane&7), packs k: j=2k,2k+1.
// gm = 7 gates, wires 9..15 at offsets 0,8,...,48.
__device__ __forceinline__ void row_butterfly(const float* gm, u64 Px[8], u64 Py[8], int t) {
    { C8 c = mkreg(gm+24);                                  // wire12, e3
      #pragma unroll
      for (int k = 0; k < 4; k++) bpair(c, Px[k],Py[k], Px[k+4],Py[k+4]); }
    { C8 c = mkreg(gm+32);                                  // wire13, e2
      bpair(c,Px[0],Py[0],Px[2],Py[2]); bpair(c,Px[1],Py[1],Px[3],Py[3]);
      bpair(c,Px[4],Py[4],Px[6],Py[6]); bpair(c,Px[5],Py[5],Px[7],Py[7]); }
    { C8 c = mkreg(gm+40);                                  // wire14, e1
      bpair(c,Px[0],Py[0],Px[1],Py[1]); bpair(c,Px[2],Py[2],Px[3],Py[3]);
      bpair(c,Px[4],Py[4],Px[5],Py[5]); bpair(c,Px[6],Py[6],Px[7],Py[7]); }
    { C6 c = mkpk(gm+48);                                   // wire15, e0
      #pragma unroll
      for (int k = 0; k < 8; k++) bpack(c, Px[k], Py[k]); }
    { C6 c = mkshuf(gm+16, t&1);                            // wire11, e4
      #pragma unroll
      for (int k = 0; k < 8; k++) bshuf(c, Px[k], Py[k], 1); }
    { C6 c = mkshuf(gm+8, t&2);                             // wire10, e5
      #pragma unroll
      for (int k = 0; k < 8; k++) bshuf(c, Px[k], Py[k], 2); }
    { C6 c = mkshuf(gm+0, t&4);                             // wire9, e6
      #pragma unroll
      for (int k = 0; k < 8; k++) bshuf(c, Px[k], Py[k], 4); }
}

// 9-stage seq butterfly. Layout: s = lane + 32*j, packs k: j=2k,2k+1.
// gm = 9 gates, wires 0..8 at offsets 0..64.
__device__ __forceinline__ void col_butterfly(const float* gm, u64 Px[8], u64 Py[8], int lane) {
    { C8 c = mkreg(gm+0);                                   // wire0, s8
      #pragma unroll
      for (int k = 0; k < 4; k++) bpair(c, Px[k],Py[k], Px[k+4],Py[k+4]); }
    { C8 c = mkreg(gm+8);                                   // wire1, s7
      bpair(c,Px[0],Py[0],Px[2],Py[2]); bpair(c,Px[1],Py[1],Px[3],Py[3]);
      bpair(c,Px[4],Py[4],Px[6],Py[6]); bpair(c,Px[5],Py[5],Px[7],Py[7]); }
    { C8 c = mkreg(gm+16);                                  // wire2, s6
      bpair(c,Px[0],Py[0],Px[1],Py[1]); bpair(c,Px[2],Py[2],Px[3],Py[3]);
      bpair(c,Px[4],Py[4],Px[5],Py[5]); bpair(c,Px[6],Py[6],Px[7],Py[7]); }
    { C6 c = mkpk(gm+24);                                   // wire3, s5
      #pragma unroll
      for (int k = 0; k < 8; k++) bpack(c, Px[k], Py[k]); }
    #pragma unroll
    for (int st = 0; st < 5; st++) {                        // wires 4..8, ls 16..1
        int ls = 16 >> st;
        C6 c = mkshuf(gm + 32 + st*8, lane & ls);
        #pragma unroll
        for (int k = 0; k < 8; k++) bshuf(c, Px[k], Py[k], ls);
    }
}

// ---------------- init: zero accumulators + build gates ----------------

__global__ void k_init(const float* __restrict__ rp) {
    int i = blockIdx.x * blockDim.x + threadIdx.x;
    if (i < NB * NE) g_m[i] = 0.f;
    if (i < 2 * NB)  ((float*)g_norms)[i] = 0.f;
    if (i < 32) {
        float th = rp[i*3+0], ph = rp[i*3+1], om = rp[i*3+2];
        float c, s;  sincosf(0.5f * th, &s, &c);
        float cap, sap; sincosf(-0.5f * (ph + om), &sap, &cap);
        float cam, sam; sincosf(-0.5f * (ph - om), &sam, &cam);
        float* o = g_gmats + i * 8;
        o[0] =  cap * c;  o[1] =  sap * c;
        o[2] = -cam * s;  o[3] =  sam * s;
        o[4] =  cam * s;  o[5] =  sam * s;
        o[6] =  cap * c;  o[7] = -sap * c;
    }
}

// ---------------- embed + B1 row butterfly ----------------
// warp = 4 rows; lane = 8*rl + t; e = 16t + j. Writes x0 and un-normalized,
// unpermuted complex state. Accumulates norm0.

__global__ __launch_bounds__(256) void k_embed_row(const int* __restrict__ tokens,
                                                   const float* __restrict__ temb,
                                                   const float* __restrict__ pemb) {
    __shared__ float gm[56];
    __shared__ float wss[8];
    int tid = threadIdx.x;
    if (tid < 56) gm[tid] = g_gmats[72 + tid];      // block0 wires 9..15
    __syncthreads();
    int warp = tid >> 5, lane = tid & 31, rl = lane >> 3, t = lane & 7;
    int row = blockIdx.x * 32 + warp * 4 + rl;
    int s = row & (NS - 1);
    int tok = tokens[row];
    const float4* te  = (const float4*)(temb + (size_t)tok * NE + 16 * t);
    const float4* pe4 = (const float4*)(pemb + (size_t)s * NE + 16 * t);
    float4* gx = (float4*)(g_x + (size_t)row * NE + 16 * t);
    u64 Px[8], Py[8];
    float ss = 0.f;
    #pragma unroll
    for (int q = 0; q < 4; q++) {
        float4 a = te[q], b = pe4[q];
        float v0 = a.x + b.x, v1 = a.y + b.y, v2 = a.z + b.z, v3 = a.w + b.w;
        gx[q] = make_float4(v0, v1, v2, v3);
        ss += v0*v0 + v1*v1 + v2*v2 + v3*v3;
        Px[2*q]   = pk2(v0, v1);  Px[2*q+1] = pk2(v2, v3);
        Py[2*q]   = 0ull;         Py[2*q+1] = 0ull;
    }
    // norm0 reduction
    #pragma unroll
    for (int o = 16; o; o >>= 1) ss += __shfl_down_sync(0xffffffffu, ss, o);
    if (lane == 0) wss[warp] = ss;

    row_butterfly(gm, Px, Py, t);

    float4* dst = (float4*)(g_state + (size_t)row * NE + 16 * t);
    #pragma unroll
    for (int k = 0; k < 8; k++) {
        float x0, x1, y0, y1;
        up2(Px[k], x0, x1);  up2(Py[k], y0, y1);
        dst[k] = make_float4(x0, y0, x1, y1);
    }
    __syncthreads();
    if (tid == 0) {
        float tot = 0.f;
        #pragma unroll
        for (int q = 0; q < 8; q++) tot += wss[q];
        atomicAdd(&g_norms[0][blockIdx.x >> 4], tot);
    }
}

// ---------------- colA: A1 + perm + residual + A2 ----------------
// CTA: batch b, column group {c0..c0+3} U {124-c0..127-c0} (permuted-space
// labels). Reads source column via peinv(c) = c ^ (c>>1).

__global__ __launch_bounds__(256) void k_colA() {
    __shared__ float gmA[72], gmB[72];
    __shared__ float2 tin[8][513];
    __shared__ float scol[8];
    __shared__ float ssacc;
    int tid = threadIdx.x;
    if (tid < 72) { gmA[tid] = g_gmats[tid]; gmB[tid] = g_gmats[128 + tid]; }
    if (tid < 8)  scol[tid] = 0.f;
    if (tid == 0) ssacc = 0.f;
    int b = blockIdx.x >> 4, grp = blockIdx.x & 15, c0 = grp * 4;
    int i = tid & 3, strip = (tid >> 2) & 1, rb = tid >> 3;
    int gcolL = strip ? (124 - c0 + i) : (c0 + i);
    int cidxL = strip * 4 + i;
    int srcCol = gcolL ^ (gcolL >> 1);               // inverse suffix-xor
    float inv0 = rsqrtf(g_norms[0][b]);
    const float2* st = g_state + (size_t)b * NDIM;
    #pragma unroll
    for (int it = 0; it < 16; it++) {
        int r = rb + it * 32;
        tin[cidxL][r] = st[r * NE + srcCol];
    }
    __syncthreads();
    int w = tid >> 5, lane = tid & 31;
    u64 Px[8], Py[8];
    #pragma unroll
    for (int k = 0; k < 8; k++) {
        float2 a = tin[w][lane + 64*k], c = tin[w][lane + 64*k + 32];
        Px[k] = pk2(a.x, c.x);  Py[k] = pk2(a.y, c.y);
    }
    __syncthreads();

    col_butterfly(gmA, Px, Py, lane);

    // CNOT permutation + |.|*inv_n0 scatter (round-1 verified formulas)
    int colw = (w < 4) ? (c0 + w) : (120 - c0 + w);
    float* tf = (float*)tin;
    #pragma unroll
    for (int k = 0; k < 8; k++) {
        float xr0, xr1, yi0, yi1;
        up2(Px[k], xr0, xr1);  up2(Py[k], yi0, yi1);
        #pragma unroll
        for (int h = 0; h < 2; h++) {
            int ss = lane + 64*k + 32*h;
            float xr = h ? xr1 : xr0, yi = h ? yi1 : yi0;
            int sp = ss; sp ^= sp >> 1; sp ^= sp >> 2; sp ^= sp >> 4; sp ^= sp >> 8;
            int par = sp & 1;
            int cO    = par ? (7 - w) : w;
            int gcolO = par ? (colw ^ 127) : colw;
            int sdd   = sp ^ ((gcolO & 1) << 8);
            tf[cO * 513 + sdd] = sqrtf(xr*xr + yi*yi) * inv0;
        }
    }
    __syncthreads();

    // residual + stats (in place, thread owns its slots)
    const float* x0p = g_x + (size_t)b * NDIM;
    float cs = 0.f, sq = 0.f;
    #pragma unroll
    for (int it = 0; it < 16; it++) {
        int r = rb + it * 32;
        float v = tf[cidxL * 513 + r] + x0p[r * NE + gcolL];
        tf[cidxL * 513 + r] = v;
        cs += v;  sq += v * v;
    }
    atomicAdd(&scol[cidxL], cs);
    #pragma unroll
    for (int o = 16; o; o >>= 1) sq += __shfl_down_sync(0xffffffffu, sq, o);
    if (lane == 0) atomicAdd(&ssacc, sq);
    __syncthreads();

    // reload x1 (real) in butterfly layout
    #pragma unroll
    for (int k = 0; k < 8; k++) {
        float a = tf[w * 513 + lane + 64*k];
        float c = tf[w * 513 + lane + 64*k + 32];
        Px[k] = pk2(a, c);  Py[k] = 0ull;
    }
    __syncthreads();
    if (tid == 0) atomicAdd(&g_norms[1][b], ssacc);
    if (tid < 8) {
        int gc = (tid < 4) ? (c0 + tid) : (120 - c0 + tid);
        atomicAdd(&g_m[b * NE + gc], scol[tid]);
    }

    col_butterfly(gmB, Px, Py, lane);

    #pragma unroll
    for (int k = 0; k < 8; k++) {
        float x0, x1, y0, y1;
        up2(Px[k], x0, x1);  up2(Py[k], y0, y1);
        tin[w][lane + 64*k]      = make_float2(x0, y0);
        tin[w][lane + 64*k + 32] = make_float2(x1, y1);
    }
    __syncthreads();
    float2* yp = g_state + (size_t)b * NDIM;
    #pragma unroll
    for (int it = 0; it < 16; it++) {
        int r = rb + it * 32;
        yp[r * NE + gcolL] = tin[cidxL][r];
    }
}

// ---------------- rowB: B2 butterfly + column-sum reduction ----------------

__global__ __launch_bounds__(256) void k_rowB() {
    __shared__ float gm[56];
    __shared__ float srow[32][128];
    int tid = threadIdx.x;
    if (tid < 56) gm[tid] = g_gmats[128 + 72 + tid];  // block1 wires 9..15
    __syncthreads();
    int warp = tid >> 5, lane = tid & 31, rl = lane >> 3, t = lane & 7;
    int row = blockIdx.x * 32 + warp * 4 + rl;
    int b = row >> 9, s = row & (NS - 1);
    float inv1 = rsqrtf(g_norms[1][b]);
    const float4* src = (const float4*)(g_state + (size_t)row * NE + 16 * t);
    u64 Px[8], Py[8];
    #pragma unroll
    for (int k = 0; k < 8; k++) {
        float4 f = src[k];
        Px[k] = pk2(f.x, f.z);  Py[k] = pk2(f.y, f.w);
    }

    row_butterfly(gm, Px, Py, t);

    int mask = (__popc(s) & 1) ? 127 : 0;
    int rls = warp * 4 + rl;
    #pragma unroll
    for (int k = 0; k < 8; k++) {
        float xr0, xr1, yi0, yi1;
        up2(Px[k], xr0, xr1);  up2(Py[k], yi0, yi1);
        #pragma unroll
        for (int h = 0; h < 2; h++) {
            int e = 16 * t + 2 * k + h;
            float xr = h ? xr1 : xr0, yi = h ? yi1 : yi0;
            int pe = e; pe ^= pe >> 1; pe ^= pe >> 2; pe ^= pe >> 4;
            srow[rls][pe ^ mask] = sqrtf(xr*xr + yi*yi) * inv1;
        }
    }
    __syncthreads();
    int e = tid & 127, half = tid >> 7;
    float acc = 0.f;
    #pragma unroll
    for (int q = 0; q < 16; q++) acc += srow[half * 16 + q][e];
    atomicAdd(&g_m[b * NE + e], acc);
}

// ---------------- final ----------------

__global__ void k_final(const float* __restrict__ ffw, const float* __restrict__ ffb,
                        const float* __restrict__ clsw, float* __restrict__ out) {
    int b = blockIdx.x, tid = threadIdx.x;
    __shared__ float mm[128], f[128];
    mm[tid] = g_m[b * NE + tid] * (1.f / 512.f);
    __syncthreads();
    float acc = ffb[tid];
    #pragma unroll 8
    for (int e = 0; e < 128; e++) acc += mm[e] * ffw[tid * 128 + e];
    f[tid] = acc;
    __syncthreads();
    if (tid < 4) {
        float o = 0.f;
        #pragma unroll 8
        for (int j = 0; j < 128; j++) o += f[j] * clsw[tid * 128 + j];
        out[b * 4 + tid] = o;
    }
}

// ---------------- launch ----------------

extern "C" void kernel_launch(void* const* d_in, const int* in_sizes, int n_in,
                              void* d_out, int out_size) {
    const int*   tokens = (const int*)  d_in[0];
    const float* temb   = (const float*)d_in[1];
    const float* pemb   = (const float*)d_in[2];
    const float* rotp   = (const float*)d_in[3];
    const float* ffw    = (const float*)d_in[4];
    const float* ffb    = (const float*)d_in[5];
    const float* clsw   = (const float*)d_in[6];
    float* out = (float*)d_out;

    k_init<<<128, 256>>>(rotp);
    k_embed_row<<<NB * NS / 32, 256>>>(tokens, temb, pemb);
    k_colA<<<NB * 16, 256>>>();
    k_rowB<<<NB * NS / 32, 256>>>();
    k_final<<<NB, 128>>>(ffw, ffb, clsw, out);
}

// round 4
// speedup vs baseline: 1.9284x; 1.1860x over previous
#include <cuda_runtime.h>
#include <cuda_fp16.h>
#include <cstdint>

// ----------------------------------------------------------------------------
// QFNet classifier, round 4:
//  - g_state stored as fp16 half2(re,im) -> half the state traffic
//  - colA: 16-column CTAs (8 + 8 mirror) -> full 32B sectors for x0 + state
//  - rowB: linear STS + gray-permuted LDS (kills 16-way bank conflicts)
// ----------------------------------------------------------------------------

#define NB   256
#define NS   512
#define NE   128
#define NDIM 65536

typedef unsigned long long u64;
typedef unsigned int u32;

__device__ float g_x[NB * NDIM];         // x0 (embedding), fp32, natural layout
__device__ u32   g_state[NB * NDIM];     // half2(re,im) per element, 64 MB
__device__ float g_norms[2][NB];
__device__ float g_m[NB * NE];
__device__ float g_gmats[2 * 16 * 8];

// ---------------- fp16 helpers ----------------

__device__ __forceinline__ u32 f2h2(float re, float im) {
    __half2 h = __floats2half2_rn(re, im);
    return *reinterpret_cast<u32*>(&h);
}
__device__ __forceinline__ float2 h22f2(u32 u) {
    __half2 h = *reinterpret_cast<__half2*>(&u);
    return __half22float2(h);
}

// ---------------- f32x2 primitives ----------------

__device__ __forceinline__ u64 pk2(float lo, float hi) {
    u64 r; asm("mov.b64 %0, {%1, %2};" : "=l"(r) : "f"(lo), "f"(hi)); return r;
}
__device__ __forceinline__ void up2(u64 v, float& lo, float& hi) {
    asm("mov.b64 {%0, %1}, %2;" : "=f"(lo), "=f"(hi) : "l"(v));
}
__device__ __forceinline__ u64 sp2(float v) { return pk2(v, v); }
__device__ __forceinline__ u64 ffma2(u64 a, u64 b, u64 c) {
    u64 d; asm("fma.rn.f32x2 %0, %1, %2, %3;" : "=l"(d) : "l"(a), "l"(b), "l"(c)); return d;
}
__device__ __forceinline__ u64 fmul2(u64 a, u64 b) {
    u64 d; asm("mul.rn.f32x2 %0, %1, %2;" : "=l"(d) : "l"(a), "l"(b)); return d;
}
__device__ __forceinline__ u64 swp2(u64 v) {
    float a, b; up2(v, a, b); return pk2(b, a);
}

struct C8 { u64 ar,ai,nai,br,bi,nbi,cr,ci,nci,dr,di,ndi; };
__device__ __forceinline__ C8 mkreg(const float* g) {
    C8 c;
    c.ar=sp2(g[0]); c.ai=sp2(g[1]); c.nai=sp2(-g[1]);
    c.br=sp2(g[2]); c.bi=sp2(g[3]); c.nbi=sp2(-g[3]);
    c.cr=sp2(g[4]); c.ci=sp2(g[5]); c.nci=sp2(-g[5]);
    c.dr=sp2(g[6]); c.di=sp2(g[7]); c.ndi=sp2(-g[7]);
    return c;
}
__device__ __forceinline__ void bpair(const C8& g, u64& Lx, u64& Ly, u64& Hx, u64& Hy) {
    u64 ox = ffma2(g.ar,Lx, ffma2(g.nai,Ly, ffma2(g.br,Hx, fmul2(g.nbi,Hy))));
    u64 oy = ffma2(g.ar,Ly, ffma2(g.ai, Lx, ffma2(g.br,Hy, fmul2(g.bi, Hx))));
    u64 px = ffma2(g.cr,Lx, ffma2(g.nci,Ly, ffma2(g.dr,Hx, fmul2(g.ndi,Hy))));
    u64 py = ffma2(g.cr,Ly, ffma2(g.ci, Lx, ffma2(g.dr,Hy, fmul2(g.di, Hx))));
    Lx = ox; Ly = oy; Hx = px; Hy = py;
}

struct C6 { u64 csr,csi,ncsi,cpr,cpi,ncpi; };
__device__ __forceinline__ C6 mkshuf(const float* g, int hibit) {
    float s0, s1, p0, p1;
    if (hibit) { s0=g[6]; s1=g[7]; p0=g[4]; p1=g[5]; }
    else       { s0=g[0]; s1=g[1]; p0=g[2]; p1=g[3]; }
    C6 c; c.csr=sp2(s0); c.csi=sp2(s1); c.ncsi=sp2(-s1);
          c.cpr=sp2(p0); c.cpi=sp2(p1); c.ncpi=sp2(-p1);
    return c;
}
__device__ __forceinline__ C6 mkpk(const float* g) {
    C6 c; c.csr=pk2(g[0],g[6]); c.csi=pk2(g[1],g[7]); c.ncsi=pk2(-g[1],-g[7]);
          c.cpr=pk2(g[2],g[4]); c.cpi=pk2(g[3],g[5]); c.ncpi=pk2(-g[3],-g[5]);
    return c;
}
__device__ __forceinline__ void bshuf(const C6& c, u64& X, u64& Y, int ls) {
    u64 px = __shfl_xor_sync(0xffffffffu, X, ls);
    u64 py = __shfl_xor_sync(0xffffffffu, Y, ls);
    u64 ox = ffma2(c.csr,X, ffma2(c.ncsi,Y, ffma2(c.cpr,px, fmul2(c.ncpi,py))));
    u64 oy = ffma2(c.csr,Y, ffma2(c.csi,X, ffma2(c.cpr,py, fmul2(c.cpi,px))));
    X = ox; Y = oy;
}
__device__ __forceinline__ void bpack(const C6& c, u64& X, u64& Y) {
    u64 sx = swp2(X), sy = swp2(Y);
    u64 ox = ffma2(c.csr,X, ffma2(c.ncsi,Y, ffma2(c.cpr,sx, fmul2(c.ncpi,sy))));
    u64 oy = ffma2(c.csr,Y, ffma2(c.csi,X, ffma2(c.cpr,sy, fmul2(c.cpi,sx))));
    X = ox; Y = oy;
}

// 7-stage embed butterfly. e = 16*t + j (t = lane&7), packs k: j=2k,2k+1.
__device__ __forceinline__ void row_butterfly(const float* gm, u64 Px[8], u64 Py[8], int t) {
    { C8 c = mkreg(gm+24);
      #pragma unroll
      for (int k = 0; k < 4; k++) bpair(c, Px[k],Py[k], Px[k+4],Py[k+4]); }
    { C8 c = mkreg(gm+32);
      bpair(c,Px[0],Py[0],Px[2],Py[2]); bpair(c,Px[1],Py[1],Px[3],Py[3]);
      bpair(c,Px[4],Py[4],Px[6],Py[6]); bpair(c,Px[5],Py[5],Px[7],Py[7]); }
    { C8 c = mkreg(gm+40);
      bpair(c,Px[0],Py[0],Px[1],Py[1]); bpair(c,Px[2],Py[2],Px[3],Py[3]);
      bpair(c,Px[4],Py[4],Px[5],Py[5]); bpair(c,Px[6],Py[6],Px[7],Py[7]); }
    { C6 c = mkpk(gm+48);
      #pragma unroll
      for (int k = 0; k < 8; k++) bpack(c, Px[k], Py[k]); }
    { C6 c = mkshuf(gm+16, t&1);
      #pragma unroll
      for (int k = 0; k < 8; k++) bshuf(c, Px[k], Py[k], 1); }
    { C6 c = mkshuf(gm+8, t&2);
      #pragma unroll
      for (int k = 0; k < 8; k++) bshuf(c, Px[k], Py[k], 2); }
    { C6 c = mkshuf(gm+0, t&4);
      #pragma unroll
      for (int k = 0; k < 8; k++) bshuf(c, Px[k], Py[k], 4); }
}

// 9-stage seq butterfly. s = lane + 32*j, packs k: j=2k,2k+1.
__device__ __forceinline__ void col_butterfly(const float* gm, u64 Px[8], u64 Py[8], int lane) {
    { C8 c = mkreg(gm+0);
      #pragma unroll
      for (int k = 0; k < 4; k++) bpair(c, Px[k],Py[k], Px[k+4],Py[k+4]); }
    { C8 c = mkreg(gm+8);
      bpair(c,Px[0],Py[0],Px[2],Py[2]); bpair(c,Px[1],Py[1],Px[3],Py[3]);
      bpair(c,Px[4],Py[4],Px[6],Py[6]); bpair(c,Px[5],Py[5],Px[7],Py[7]); }
    { C8 c = mkreg(gm+16);
      bpair(c,Px[0],Py[0],Px[1],Py[1]); bpair(c,Px[2],Py[2],Px[3],Py[3]);
      bpair(c,Px[4],Py[4],Px[5],Py[5]); bpair(c,Px[6],Py[6],Px[7],Py[7]); }
    { C6 c = mkpk(gm+24);
      #pragma unroll
      for (int k = 0; k < 8; k++) bpack(c, Px[k], Py[k]); }
    #pragma unroll
    for (int st = 0; st < 5; st++) {
        int ls = 16 >> st;
        C6 c = mkshuf(gm + 32 + st*8, lane & ls);
        #pragma unroll
        for (int k = 0; k < 8; k++) bshuf(c, Px[k], Py[k], ls);
    }
}

// ---------------- init ----------------

__global__ void k_init(const float* __restrict__ rp) {
    int i = blockIdx.x * blockDim.x + threadIdx.x;
    if (i < NB * NE) g_m[i] = 0.f;
    if (i < 2 * NB)  ((float*)g_norms)[i] = 0.f;
    if (i < 32) {
        float th = rp[i*3+0], ph = rp[i*3+1], om = rp[i*3+2];
        float c, s;  sincosf(0.5f * th, &s, &c);
        float cap, sap; sincosf(-0.5f * (ph + om), &sap, &cap);
        float cam, sam; sincosf(-0.5f * (ph - om), &sam, &cam);
        float* o = g_gmats + i * 8;
        o[0] =  cap * c;  o[1] =  sap * c;
        o[2] = -cam * s;  o[3] =  sam * s;
        o[4] =  cam * s;  o[5] =  sam * s;
        o[6] =  cap * c;  o[7] = -sap * c;
    }
}

// ---------------- embed + B1 row butterfly, fp16 state out ----------------

__global__ __launch_bounds__(256) void k_embed_row(const int* __restrict__ tokens,
                                                   const float* __restrict__ temb,
                                                   const float* __restrict__ pemb) {
    __shared__ float gm[56];
    __shared__ float wss[8];
    int tid = threadIdx.x;
    if (tid < 56) gm[tid] = g_gmats[72 + tid];
    __syncthreads();
    int warp = tid >> 5, lane = tid & 31, rl = lane >> 3, t = lane & 7;
    int row = blockIdx.x * 32 + warp * 4 + rl;
    int s = row & (NS - 1);
    int tok = tokens[row];
    const float4* te  = (const float4*)(temb + (size_t)tok * NE + 16 * t);
    const float4* pe4 = (const float4*)(pemb + (size_t)s * NE + 16 * t);
    float4* gx = (float4*)(g_x + (size_t)row * NE + 16 * t);
    u64 Px[8], Py[8];
    float ss = 0.f;
    #pragma unroll
    for (int q = 0; q < 4; q++) {
        float4 a = te[q], b = pe4[q];
        float v0 = a.x + b.x, v1 = a.y + b.y, v2 = a.z + b.z, v3 = a.w + b.w;
        gx[q] = make_float4(v0, v1, v2, v3);
        ss += v0*v0 + v1*v1 + v2*v2 + v3*v3;
        Px[2*q]   = pk2(v0, v1);  Px[2*q+1] = pk2(v2, v3);
        Py[2*q]   = 0ull;         Py[2*q+1] = 0ull;
    }
    #pragma unroll
    for (int o = 16; o; o >>= 1) ss += __shfl_down_sync(0xffffffffu, ss, o);
    if (lane == 0) wss[warp] = ss;

    row_butterfly(gm, Px, Py, t);

    u32 hv[16];
    #pragma unroll
    for (int k = 0; k < 8; k++) {
        float x0, x1, y0, y1;
        up2(Px[k], x0, x1);  up2(Py[k], y0, y1);
        hv[2*k]   = f2h2(x0, y0);
        hv[2*k+1] = f2h2(x1, y1);
    }
    uint4* dst = (uint4*)(g_state + (size_t)row * NE + 16 * t);
    #pragma unroll
    for (int q = 0; q < 4; q++)
        dst[q] = make_uint4(hv[4*q], hv[4*q+1], hv[4*q+2], hv[4*q+3]);

    __syncthreads();
    if (tid == 0) {
        float tot = 0.f;
        #pragma unroll
        for (int q = 0; q < 8; q++) tot += wss[q];
        atomicAdd(&g_norms[0][blockIdx.x >> 4], tot);
    }
}

// ---------------- colA: A1 + perm + residual + A2 (16-column CTAs) --------
// CTA: batch b, columns {c0..c0+7} U {120-c0..127-c0}, c0 = grp*8.
// 512 threads; warp w (0..15) owns permuted-space column colw.

__global__ __launch_bounds__(512) void k_colA() {
    __shared__ float gmA[72], gmB[72];
    __shared__ u32  tin[16 * 513];      // raw half2 staging / reused as tf floats
    __shared__ float scol[16];
    __shared__ float ssacc;
    float* tf = reinterpret_cast<float*>(tin);

    int tid = threadIdx.x;
    if (tid < 72)  { gmA[tid] = g_gmats[tid]; gmB[tid] = g_gmats[128 + tid]; }
    if (tid < 16)  scol[tid] = 0.f;
    if (tid == 0)  ssacc = 0.f;
    int b = blockIdx.x >> 3, grp = blockIdx.x & 7, c0 = grp * 8;
    int i = tid & 7, strip = (tid >> 3) & 1, rb = tid >> 4;     // rb: 0..31
    int gcolL = strip ? (120 - c0 + i) : (c0 + i);
    int cidxL = strip * 8 + i;
    int srcCol = gcolL ^ (gcolL >> 1);
    float inv0 = rsqrtf(g_norms[0][b]);
    const u32* st = g_state + (size_t)b * NDIM;
    #pragma unroll
    for (int it = 0; it < 16; it++) {
        int r = rb + it * 32;
        tin[cidxL * 513 + r] = st[r * NE + srcCol];
    }
    __syncthreads();
    int w = tid >> 5, lane = tid & 31;
    u64 Px[8], Py[8];
    #pragma unroll
    for (int k = 0; k < 8; k++) {
        float2 a = h22f2(tin[w * 513 + lane + 64*k]);
        float2 c = h22f2(tin[w * 513 + lane + 64*k + 32]);
        Px[k] = pk2(a.x, c.x);  Py[k] = pk2(a.y, c.y);
    }
    __syncthreads();

    col_butterfly(gmA, Px, Py, lane);

    // CNOT permutation + |.|*inv0 scatter into tf (float)
    int colw = (w < 8) ? (c0 + w) : (112 - c0 + w);
    #pragma unroll
    for (int k = 0; k < 8; k++) {
        float xr0, xr1, yi0, yi1;
        up2(Px[k], xr0, xr1);  up2(Py[k], yi0, yi1);
        #pragma unroll
        for (int h = 0; h < 2; h++) {
            int ss = lane + 64*k + 32*h;
            float xr = h ? xr1 : xr0, yi = h ? yi1 : yi0;
            int sp = ss; sp ^= sp >> 1; sp ^= sp >> 2; sp ^= sp >> 4; sp ^= sp >> 8;
            int par = sp & 1;
            int cO    = par ? (15 - w) : w;
            int gcolO = par ? (colw ^ 127) : colw;
            int sdd   = sp ^ ((gcolO & 1) << 8);
            tf[cO * 513 + sdd] = sqrtf(xr*xr + yi*yi) * inv0;
        }
    }
    __syncthreads();

    // residual + stats, in place in tf
    const float* x0p = g_x + (size_t)b * NDIM;
    float cs = 0.f, sq = 0.f;
    #pragma unroll
    for (int it = 0; it < 16; it++) {
        int r = rb + it * 32;
        float v = tf[cidxL * 513 + r] + x0p[r * NE + gcolL];
        tf[cidxL * 513 + r] = v;
        cs += v;  sq += v * v;
    }
    atomicAdd(&scol[cidxL], cs);
    #pragma unroll
    for (int o = 16; o; o >>= 1) sq += __shfl_down_sync(0xffffffffu, sq, o);
    if (lane == 0) atomicAdd(&ssacc, sq);
    __syncthreads();

    // reload x1 in butterfly layout (warp w holds column colw)
    #pragma unroll
    for (int k = 0; k < 8; k++) {
        float a = tf[w * 513 + lane + 64*k];
        float c = tf[w * 513 + lane + 64*k + 32];
        Px[k] = pk2(a, c);  Py[k] = 0ull;
    }
    __syncthreads();
    if (tid == 0) atomicAdd(&g_norms[1][b], ssacc);
    if (tid < 16) {
        int gc = (tid < 8) ? (c0 + tid) : (112 - c0 + tid);
        atomicAdd(&g_m[b * NE + gc], scol[tid]);
    }

    col_butterfly(gmB, Px, Py, lane);

    // stash as half2 and write transposed (coalesced 32B clusters)
    #pragma unroll
    for (int k = 0; k < 8; k++) {
        float x0, x1, y0, y1;
        up2(Px[k], x0, x1);  up2(Py[k], y0, y1);
        tin[w * 513 + lane + 64*k]      = f2h2(x0, y0);
        tin[w * 513 + lane + 64*k + 32] = f2h2(x1, y1);
    }
    __syncthreads();
    u32* yp = g_state + (size_t)b * NDIM;
    #pragma unroll
    for (int it = 0; it < 16; it++) {
        int r = rb + it * 32;
        yp[r * NE + gcolL] = tin[cidxL * 513 + r];
    }
}

// ---------------- rowB: B2 butterfly + column-sum reduction ----------------
// Linear smem write (pad 136, float4 -> structural-min phases), permutation
// folded into the reduction read via gray decode: e_src = g ^ (g>>1).

__global__ __launch_bounds__(256) void k_rowB() {
    __shared__ float gm[56];
    __shared__ float srow[32][136];
    int tid = threadIdx.x;
    if (tid < 56) gm[tid] = g_gmats[128 + 72 + tid];
    __syncthreads();
    int warp = tid >> 5, lane = tid & 31, rl = lane >> 3, t = lane & 7;
    int rls = warp * 4 + rl;
    int row = blockIdx.x * 32 + rls;
    int b = row >> 9;
    float inv1 = rsqrtf(g_norms[1][b]);
    const uint4* src = (const uint4*)(g_state + (size_t)row * NE + 16 * t);
    u64 Px[8], Py[8];
    #pragma unroll
    for (int q = 0; q < 4; q++) {
        uint4 U = src[q];
        float2 f0 = h22f2(U.x), f1 = h22f2(U.y), f2 = h22f2(U.z), f3 = h22f2(U.w);
        Px[2*q]   = pk2(f0.x, f1.x);  Py[2*q]   = pk2(f0.y, f1.y);
        Px[2*q+1] = pk2(f2.x, f3.x);  Py[2*q+1] = pk2(f2.y, f3.y);
    }

    row_butterfly(gm, Px, Py, t);

    float m[16];
    #pragma unroll
    for (int k = 0; k < 8; k++) {
        float xr0, xr1, yi0, yi1;
        up2(Px[k], xr0, xr1);  up2(Py[k], yi0, yi1);
        m[2*k]   = sqrtf(xr0*xr0 + yi0*yi0) * inv1;
        m[2*k+1] = sqrtf(xr1*xr1 + yi1*yi1) * inv1;
    }
    float4* wp = (float4*)&srow[rls][16 * t];
    #pragma unroll
    for (int q = 0; q < 4; q++)
        wp[q] = make_float4(m[4*q], m[4*q+1], m[4*q+2], m[4*q+3]);
    __syncthreads();

    int e = tid & 127, half = tid >> 7;
    int sbase = (blockIdx.x * 32) & (NS - 1);
    float acc = 0.f;
    #pragma unroll
    for (int q = 0; q < 16; q++) {
        int r = half * 16 + q;
        int s = sbase + r;
        int mask = (__popc(s) & 1) ? 127 : 0;
        int g = e ^ mask;
        int es = g ^ (g >> 1);
        acc += srow[r][es];
    }
    atomicAdd(&g_m[b * NE + e], acc);
}

// ---------------- final ----------------

__global__ void k_final(const float* __restrict__ ffw, const float* __restrict__ ffb,
                        const float* __restrict__ clsw, float* __restrict__ out) {
    int b = blockIdx.x, tid = threadIdx.x;
    __shared__ float mm[128], f[128];
    mm[tid] = g_m[b * NE + tid] * (1.f / 512.f);
    __syncthreads();
    float acc = ffb[tid];
    #pragma unroll 8
    for (int e = 0; e < 128; e++) acc += mm[e] * ffw[tid * 128 + e];
    f[tid] = acc;
    __syncthreads();
    if (tid < 4) {
        float o = 0.f;
        #pragma unroll 8
        for (int j = 0; j < 128; j++) o += f[j] * clsw[tid * 128 + j];
        out[b * 4 + tid] = o;
    }
}

// ---------------- launch ----------------

extern "C" void kernel_launch(void* const* d_in, const int* in_sizes, int n_in,
                              void* d_out, int out_size) {
    const int*   tokens = (const int*)  d_in[0];
    const float* temb   = (const float*)d_in[1];
    const float* pemb   = (const float*)d_in[2];
    const float* rotp   = (const float*)d_in[3];
    const float* ffw    = (const float*)d_in[4];
    const float* ffb    = (const float*)d_in[5];
    const float* clsw   = (const float*)d_in[6];
    float* out = (float*)d_out;

    k_init<<<128, 256>>>(rotp);
    k_embed_row<<<NB * NS / 32, 256>>>(tokens, temb, pemb);
    k_colA<<<NB * 8, 512>>>();
    k_rowB<<<NB * NS / 32, 256>>>();
    k_final<<<NB, 128>>>(ffw, ffb, clsw, out);
}

// round 7
// speedup vs baseline: 2.5085x; 1.3009x over previous
#include <cuda_runtime.h>
#include <cuda_fp16.h>
#include <cstdint>

// ----------------------------------------------------------------------------
// QFNet classifier, round 7: Rot = Rz(omega)*Ry(theta)*Rz(phi) factorization.
//  - D(omega) dies under abs() -> zero cost
//  - D(phi): separable phase tables ps[512], pe[128], applied once per block
//  - all 32 butterfly stages are REAL Ry rotations: 2 f32x2 slots/elem/stage
// R7 fix: __align__(16) on shared arrays accessed with 128-bit ld/st (srow
// was 8-aligned after the gate array shrank 56->14 floats -> STS.128 fault).
// ----------------------------------------------------------------------------

#define NB   256
#define NS   512
#define NE   128
#define NDIM 65536

typedef unsigned long long u64;
typedef unsigned int u32;

__device__ float  g_x[NB * NDIM];
__device__ u32    g_state[NB * NDIM];
__device__ float  g_norms[2][NB];
__device__ float  g_m[NB * NE];
__device__ float  g_ry[2 * 32];          // [blk][wire]{c,s}, c=cos(th/2)
__device__ float2 g_ps[2][NS];           // seq D(phi) phase (cos,sin)
__device__ float2 g_pe[2][NE];           // emb D(phi) phase

// ---------------- helpers ----------------

__device__ __forceinline__ u32 f2h2(float re, float im) {
    __half2 h = __floats2half2_rn(re, im);
    return *reinterpret_cast<u32*>(&h);
}
__device__ __forceinline__ float2 h22f2(u32 u) {
    __half2 h = *reinterpret_cast<__half2*>(&u);
    return __half22float2(h);
}
__device__ __forceinline__ u64 pk2(float lo, float hi) {
    u64 r; asm("mov.b64 %0, {%1, %2};" : "=l"(r) : "f"(lo), "f"(hi)); return r;
}
__device__ __forceinline__ void up2(u64 v, float& lo, float& hi) {
    asm("mov.b64 {%0, %1}, %2;" : "=f"(lo), "=f"(hi) : "l"(v));
}
__device__ __forceinline__ u64 sp2(float v) { return pk2(v, v); }
__device__ __forceinline__ u64 ffma2(u64 a, u64 b, u64 c) {
    u64 d; asm("fma.rn.f32x2 %0, %1, %2, %3;" : "=l"(d) : "l"(a), "l"(b), "l"(c)); return d;
}
__device__ __forceinline__ u64 fmul2(u64 a, u64 b) {
    u64 d; asm("mul.rn.f32x2 %0, %1, %2;" : "=l"(d) : "l"(a), "l"(b)); return d;
}
__device__ __forceinline__ u64 swp2(u64 v) {
    float a, b; up2(v, a, b); return pk2(b, a);
}

// ---------------- real Ry butterfly primitives ----------------
// lo' = c*lo - s*hi ; hi' = s*lo + c*hi   (componentwise on re/im packs)

__device__ __forceinline__ void bpairR(u64 c2, u64 s2, u64 ns2,
                                       u64& Lx, u64& Ly, u64& Hx, u64& Hy) {
    u64 ox = ffma2(c2, Lx, fmul2(ns2, Hx));
    u64 oy = ffma2(c2, Ly, fmul2(ns2, Hy));
    u64 px = ffma2(c2, Hx, fmul2(s2,  Lx));
    u64 py = ffma2(c2, Hy, fmul2(s2,  Ly));
    Lx = ox; Ly = oy; Hx = px; Hy = py;
}
__device__ __forceinline__ void bshufR(u64 c2, u64 B2, u64& X, u64& Y, int ls) {
    u64 px = __shfl_xor_sync(0xffffffffu, X, ls);
    u64 py = __shfl_xor_sync(0xffffffffu, Y, ls);
    X = ffma2(c2, X, fmul2(B2, px));
    Y = ffma2(c2, Y, fmul2(B2, py));
}
__device__ __forceinline__ void bpackR(u64 c2, u64 Bp, u64& X, u64& Y) {
    X = ffma2(c2, X, fmul2(Bp, swp2(X)));
    Y = ffma2(c2, Y, fmul2(Bp, swp2(Y)));
}

// 7-stage embed Ry butterfly. e = 16*t + j (t = lane&7), pack k: j=2k,2k+1.
// ry = 14 floats: (c,s) wires 9..15 at offsets 0,2,...,12.
__device__ __forceinline__ void row_butterflyR(const float* ry, u64 Px[8], u64 Py[8], int t) {
    { u64 c2=sp2(ry[6]), s2=sp2(ry[7]), ns2=sp2(-ry[7]);       // wire12, e bit3
      #pragma unroll
      for (int k = 0; k < 4; k++) bpairR(c2,s2,ns2, Px[k],Py[k], Px[k+4],Py[k+4]); }
    { u64 c2=sp2(ry[8]), s2=sp2(ry[9]), ns2=sp2(-ry[9]);       // wire13, e bit2
      bpairR(c2,s2,ns2,Px[0],Py[0],Px[2],Py[2]); bpairR(c2,s2,ns2,Px[1],Py[1],Px[3],Py[3]);
      bpairR(c2,s2,ns2,Px[4],Py[4],Px[6],Py[6]); bpairR(c2,s2,ns2,Px[5],Py[5],Px[7],Py[7]); }
    { u64 c2=sp2(ry[10]), s2=sp2(ry[11]), ns2=sp2(-ry[11]);    // wire14, e bit1
      bpairR(c2,s2,ns2,Px[0],Py[0],Px[1],Py[1]); bpairR(c2,s2,ns2,Px[2],Py[2],Px[3],Py[3]);
      bpairR(c2,s2,ns2,Px[4],Py[4],Px[5],Py[5]); bpairR(c2,s2,ns2,Px[6],Py[6],Px[7],Py[7]); }
    { u64 c2 = sp2(ry[12]); u64 Bp = pk2(-ry[13], ry[13]);     // wire15, e bit0
      #pragma unroll
      for (int k = 0; k < 8; k++) bpackR(c2, Bp, Px[k], Py[k]); }
    { u64 c2 = sp2(ry[4]); u64 B2 = sp2((t&1) ? ry[5] : -ry[5]);   // wire11, bit4
      #pragma unroll
      for (int k = 0; k < 8; k++) bshufR(c2, B2, Px[k], Py[k], 1); }
    { u64 c2 = sp2(ry[2]); u64 B2 = sp2((t&2) ? ry[3] : -ry[3]);   // wire10, bit5
      #pragma unroll
      for (int k = 0; k < 8; k++) bshufR(c2, B2, Px[k], Py[k], 2); }
    { u64 c2 = sp2(ry[0]); u64 B2 = sp2((t&4) ? ry[1] : -ry[1]);   // wire9, bit6
      #pragma unroll
      for (int k = 0; k < 8; k++) bshufR(c2, B2, Px[k], Py[k], 4); }
}

// 9-stage seq Ry butterfly. s = lane + 32*j, pack k: j=2k,2k+1.
// ry = 18 floats: (c,s) wires 0..8 at offsets 0..16.
__device__ __forceinline__ void col_butterflyR(const float* ry, u64 Px[8], u64 Py[8], int lane) {
    { u64 c2=sp2(ry[0]), s2=sp2(ry[1]), ns2=sp2(-ry[1]);       // wire0, s bit8
      #pragma unroll
      for (int k = 0; k < 4; k++) bpairR(c2,s2,ns2, Px[k],Py[k], Px[k+4],Py[k+4]); }
    { u64 c2=sp2(ry[2]), s2=sp2(ry[3]), ns2=sp2(-ry[3]);       // wire1, s bit7
      bpairR(c2,s2,ns2,Px[0],Py[0],Px[2],Py[2]); bpairR(c2,s2,ns2,Px[1],Py[1],Px[3],Py[3]);
      bpairR(c2,s2,ns2,Px[4],Py[4],Px[6],Py[6]); bpairR(c2,s2,ns2,Px[5],Py[5],Px[7],Py[7]); }
    { u64 c2=sp2(ry[4]), s2=sp2(ry[5]), ns2=sp2(-ry[5]);       // wire2, s bit6
      bpairR(c2,s2,ns2,Px[0],Py[0],Px[1],Py[1]); bpairR(c2,s2,ns2,Px[2],Py[2],Px[3],Py[3]);
      bpairR(c2,s2,ns2,Px[4],Py[4],Px[5],Py[5]); bpairR(c2,s2,ns2,Px[6],Py[6],Px[7],Py[7]); }
    { u64 c2 = sp2(ry[6]); u64 Bp = pk2(-ry[7], ry[7]);        // wire3, s bit5
      #pragma unroll
      for (int k = 0; k < 8; k++) bpackR(c2, Bp, Px[k], Py[k]); }
    #pragma unroll
    for (int st = 0; st < 5; st++) {                            // wires 4..8
        int ls = 16 >> st;
        const float* p = ry + 8 + st * 2;
        u64 c2 = sp2(p[0]); u64 B2 = sp2((lane & ls) ? p[1] : -p[1]);
        #pragma unroll
        for (int k = 0; k < 8; k++) bshufR(c2, B2, Px[k], Py[k], ls);
    }
}

// ---------------- init ----------------

__global__ void k_init(const float* __restrict__ rp) {
    int i = blockIdx.x * 256 + threadIdx.x;
    if (i < NB * NE) g_m[i] = 0.f;
    if (i < 2 * NB)  ((float*)g_norms)[i] = 0.f;
    if (blockIdx.x < 2) {
        int blk = blockIdx.x, tid = threadIdx.x;
        for (int s = tid; s < NS; s += 256) {
            float ang = 0.f;
            #pragma unroll
            for (int w = 0; w < 9; w++) {
                float ph = rp[blk * 48 + w * 3 + 1];
                ang += ((s >> (8 - w)) & 1) ? ph : -ph;
            }
            float c, sn; sincosf(0.5f * ang, &sn, &c);
            g_ps[blk][s] = make_float2(c, sn);
        }
        if (tid < NE) {
            float ang = 0.f;
            #pragma unroll
            for (int w = 9; w < 16; w++) {
                float ph = rp[blk * 48 + w * 3 + 1];
                ang += ((tid >> (15 - w)) & 1) ? ph : -ph;
            }
            float c, sn; sincosf(0.5f * ang, &sn, &c);
            g_pe[blk][tid] = make_float2(c, sn);
        }
        if (tid < 16) {
            float c, sn; sincosf(0.5f * rp[blk * 48 + tid * 3], &sn, &c);
            g_ry[blk * 32 + tid * 2]     = c;
            g_ry[blk * 32 + tid * 2 + 1] = sn;
        }
    }
}

// ---------------- embed + D(phi)_1 + B1 emb Ry butterfly ----------------

__global__ __launch_bounds__(256) void k_embed_row(const int* __restrict__ tokens,
                                                   const float* __restrict__ temb,
                                                   const float* __restrict__ pemb) {
    __shared__ __align__(16) float ry[14];
    __shared__ __align__(16) u64 epc[64], eps_[64];   // packed emb-phase, idx t*8+k
    __shared__ float wss[8];
    int tid = threadIdx.x;
    if (tid < 14) ry[tid] = g_ry[18 + tid];          // block0 wires 9..15
    if (tid < 64) {
        int t0 = tid >> 3, k0 = tid & 7, e0 = 16 * t0 + 2 * k0;
        float2 A = g_pe[0][e0], B = g_pe[0][e0 + 1];
        epc[tid]  = pk2(A.x, B.x);
        eps_[tid] = pk2(A.y, B.y);
    }
    __syncthreads();
    int warp = tid >> 5, lane = tid & 31, rl = lane >> 3, t = lane & 7;
    int row = blockIdx.x * 32 + warp * 4 + rl;
    int s = row & (NS - 1);
    int tok = tokens[row];
    const float4* te  = (const float4*)(temb + (size_t)tok * NE + 16 * t);
    const float4* pe4 = (const float4*)(pemb + (size_t)s * NE + 16 * t);
    float4* gx = (float4*)(g_x + (size_t)row * NE + 16 * t);
    float v[16];
    float ss = 0.f;
    #pragma unroll
    for (int q = 0; q < 4; q++) {
        float4 a = te[q], b = pe4[q];
        float v0 = a.x + b.x, v1 = a.y + b.y, v2 = a.z + b.z, v3 = a.w + b.w;
        gx[q] = make_float4(v0, v1, v2, v3);
        ss += v0*v0 + v1*v1 + v2*v2 + v3*v3;
        v[4*q] = v0; v[4*q+1] = v1; v[4*q+2] = v2; v[4*q+3] = v3;
    }
    #pragma unroll
    for (int o = 16; o; o >>= 1) ss += __shfl_down_sync(0xffffffffu, ss, o);
    if (lane == 0) wss[warp] = ss;

    // D(phi)_1: state = v * e^{i(ps[s]+pe[e])}
    float2 psv = g_ps[0][s];
    u64 a2 = sp2(psv.x), b2 = sp2(psv.y), nb2 = sp2(-psv.y);
    u64 Px[8], Py[8];
    #pragma unroll
    for (int k = 0; k < 8; k++) {
        u64 xp = pk2(v[2*k], v[2*k+1]);
        u64 tc = epc[t*8+k], ts = eps_[t*8+k];
        u64 c1 = ffma2(a2, tc, fmul2(nb2, ts));
        u64 s1 = ffma2(b2, tc, fmul2(a2,  ts));
        Px[k] = fmul2(xp, c1);
        Py[k] = fmul2(xp, s1);
    }

    row_butterflyR(ry, Px, Py, t);

    u32 hv[16];
    #pragma unroll
    for (int k = 0; k < 8; k++) {
        float x0, x1, y0, y1;
        up2(Px[k], x0, x1);  up2(Py[k], y0, y1);
        hv[2*k]   = f2h2(x0, y0);
        hv[2*k+1] = f2h2(x1, y1);
    }
    uint4* dst = (uint4*)(g_state + (size_t)row * NE + 16 * t);
    #pragma unroll
    for (int q = 0; q < 4; q++)
        dst[q] = make_uint4(hv[4*q], hv[4*q+1], hv[4*q+2], hv[4*q+3]);

    __syncthreads();
    if (tid == 0) {
        float tot = 0.f;
        #pragma unroll
        for (int q = 0; q < 8; q++) tot += wss[q];
        atomicAdd(&g_norms[0][blockIdx.x >> 4], tot);
    }
}

// ---------------- colA: A1 + perm + residual + D(phi)_2 + A2 ----------------
// R4 16-column structure: CTA = batch b, columns {c0..c0+7} U {120-c0..127-c0}.

__global__ __launch_bounds__(512) void k_colA() {
    __shared__ __align__(16) float ryA[18], ryB[18];
    __shared__ __align__(16) u64 tsc[256], tss[256];   // seq-phase blk2, idx k*32+lane
    __shared__ __align__(16) u32 tin[16 * 513];
    __shared__ float scol[16];
    __shared__ float ssacc;
    float* tf = reinterpret_cast<float*>(tin);

    int tid = threadIdx.x;
    if (tid < 18)  { ryA[tid] = g_ry[tid]; ryB[tid] = g_ry[32 + tid]; }
    if (tid < 16)  scol[tid] = 0.f;
    if (tid == 0)  ssacc = 0.f;
    if (tid < 256) {
        int k = tid >> 5, l = tid & 31;
        float2 A = g_ps[1][l + 64*k], B = g_ps[1][l + 64*k + 32];
        tsc[tid] = pk2(A.x, B.x);
        tss[tid] = pk2(A.y, B.y);
    }
    int b = blockIdx.x >> 3, grp = blockIdx.x & 7, c0 = grp * 8;
    int i = tid & 7, strip = (tid >> 3) & 1, rb = tid >> 4;
    int gcolL = strip ? (120 - c0 + i) : (c0 + i);
    int cidxL = strip * 8 + i;
    int srcCol = gcolL ^ (gcolL >> 1);
    float inv0 = rsqrtf(g_norms[0][b]);
    const u32* st = g_state + (size_t)b * NDIM;
    #pragma unroll
    for (int it = 0; it < 16; it++) {
        int r = rb + it * 32;
        tin[cidxL * 513 + r] = st[r * NE + srcCol];
    }
    __syncthreads();
    int w = tid >> 5, lane = tid & 31;
    u64 Px[8], Py[8];
    #pragma unroll
    for (int k = 0; k < 8; k++) {
        float2 fa = h22f2(tin[w * 513 + lane + 64*k]);
        float2 fc = h22f2(tin[w * 513 + lane + 64*k + 32]);
        Px[k] = pk2(fa.x, fc.x);  Py[k] = pk2(fa.y, fc.y);
    }
    __syncthreads();

    col_butterflyR(ryA, Px, Py, lane);

    // CNOT perm + |.|*inv0 scatter (R4-verified 16-col formulas)
    int colw = (w < 8) ? (c0 + w) : (112 - c0 + w);
    #pragma unroll
    for (int k = 0; k < 8; k++) {
        float xr0, xr1, yi0, yi1;
        up2(Px[k], xr0, xr1);  up2(Py[k], yi0, yi1);
        #pragma unroll
        for (int h = 0; h < 2; h++) {
            int ss = lane + 64*k + 32*h;
            float xr = h ? xr1 : xr0, yi = h ? yi1 : yi0;
            int sp = ss; sp ^= sp >> 1; sp ^= sp >> 2; sp ^= sp >> 4; sp ^= sp >> 8;
            int par = sp & 1;
            int cO    = par ? (15 - w) : w;
            int gcolO = par ? (colw ^ 127) : colw;
            int sdd   = sp ^ ((gcolO & 1) << 8);
            tf[cO * 513 + sdd] = sqrtf(xr*xr + yi*yi) * inv0;
        }
    }
    __syncthreads();

    // residual + stats, in place
    const float* x0p = g_x + (size_t)b * NDIM;
    float cs = 0.f, sq = 0.f;
    #pragma unroll
    for (int it = 0; it < 16; it++) {
        int r = rb + it * 32;
        float v = tf[cidxL * 513 + r] + x0p[r * NE + gcolL];
        tf[cidxL * 513 + r] = v;
        cs += v;  sq += v * v;
    }
    atomicAdd(&scol[cidxL], cs);
    #pragma unroll
    for (int o = 16; o; o >>= 1) sq += __shfl_down_sync(0xffffffffu, sq, o);
    if (lane == 0) atomicAdd(&ssacc, sq);
    __syncthreads();

    if (tid == 0) atomicAdd(&g_norms[1][b], ssacc);
    if (tid < 16) {
        int gc = (tid < 8) ? (c0 + tid) : (112 - c0 + tid);
        atomicAdd(&g_m[b * NE + gc], scol[tid]);
    }

    // reload x1 + D(phi)_2: phase = ps2[s] * pe2[colw]
    float2 pev = g_pe[1][colw];
    u64 a2 = sp2(pev.x), b2 = sp2(pev.y), nb2 = sp2(-pev.y);
    #pragma unroll
    for (int k = 0; k < 8; k++) {
        u64 x1p = pk2(tf[w * 513 + lane + 64*k], tf[w * 513 + lane + 64*k + 32]);
        u64 tc = tsc[k*32 + lane], ts = tss[k*32 + lane];
        u64 c12 = ffma2(a2, tc, fmul2(nb2, ts));
        u64 s12 = ffma2(b2, tc, fmul2(a2,  ts));
        Px[k] = fmul2(x1p, c12);
        Py[k] = fmul2(x1p, s12);
    }
    __syncthreads();

    col_butterflyR(ryB, Px, Py, lane);

    #pragma unroll
    for (int k = 0; k < 8; k++) {
        float x0, x1, y0, y1;
        up2(Px[k], x0, x1);  up2(Py[k], y0, y1);
        tin[w * 513 + lane + 64*k]      = f2h2(x0, y0);
        tin[w * 513 + lane + 64*k + 32] = f2h2(x1, y1);
    }
    __syncthreads();
    u32* yp = g_state + (size_t)b * NDIM;
    #pragma unroll
    for (int it = 0; it < 16; it++) {
        int r = rb + it * 32;
        yp[r * NE + gcolL] = tin[cidxL * 513 + r];
    }
}

// ---------------- rowB: B2 emb Ry butterfly + column-sum reduction ---------

__global__ __launch_bounds__(256) void k_rowB() {
    __shared__ __align__(16) float srow[32][136];
    __shared__ __align__(16) float ry[14];
    int tid = threadIdx.x;
    if (tid < 14) ry[tid] = g_ry[32 + 18 + tid];     // block1 wires 9..15
    __syncthreads();
    int warp = tid >> 5, lane = tid & 31, rl = lane >> 3, t = lane & 7;
    int rls = warp * 4 + rl;
    int row = blockIdx.x * 32 + rls;
    int b = row >> 9;
    float inv1 = rsqrtf(g_norms[1][b]);
    const uint4* src = (const uint4*)(g_state + (size_t)row * NE + 16 * t);
    u64 Px[8], Py[8];
    #pragma unroll
    for (int q = 0; q < 4; q++) {
        uint4 U = src[q];
        float2 f0 = h22f2(U.x), f1 = h22f2(U.y), f2 = h22f2(U.z), f3 = h22f2(U.w);
        Px[2*q]   = pk2(f0.x, f1.x);  Py[2*q]   = pk2(f0.y, f1.y);
        Px[2*q+1] = pk2(f2.x, f3.x);  Py[2*q+1] = pk2(f2.y, f3.y);
    }

    row_butterflyR(ry, Px, Py, t);

    float m[16];
    #pragma unroll
    for (int k = 0; k < 8; k++) {
        float xr0, xr1, yi0, yi1;
        up2(Px[k], xr0, xr1);  up2(Py[k], yi0, yi1);
        m[2*k]   = sqrtf(xr0*xr0 + yi0*yi0) * inv1;
        m[2*k+1] = sqrtf(xr1*xr1 + yi1*yi1) * inv1;
    }
    float4* wp = (float4*)&srow[rls][16 * t];
    #pragma unroll
    for (int q = 0; q < 4; q++)
        wp[q] = make_float4(m[4*q], m[4*q+1], m[4*q+2], m[4*q+3]);
    __syncthreads();

    int e = tid & 127, half = tid >> 7;
    int sbase = (blockIdx.x * 32) & (NS - 1);
    float acc = 0.f;
    #pragma unroll
    for (int q = 0; q < 16; q++) {
        int r = half * 16 + q;
        int s = sbase + r;
        int mask = (__popc(s) & 1) ? 127 : 0;
        int g = e ^ mask;
        int es = g ^ (g >> 1);
        acc += srow[r][es];
    }
    atomicAdd(&g_m[b * NE + e], acc);
}

// ---------------- final ----------------

__global__ void k_final(const float* __restrict__ ffw, const float* __restrict__ ffb,
                        const float* __restrict__ clsw, float* __restrict__ out) {
    int b = blockIdx.x, tid = threadIdx.x;
    __shared__ float mm[128], f[128];
    mm[tid] = g_m[b * NE + tid] * (1.f / 512.f);
    __syncthreads();
    float acc = ffb[tid];
    #pragma unroll 8
    for (int e = 0; e < 128; e++) acc += mm[e] * ffw[tid * 128 + e];
    f[tid] = acc;
    __syncthreads();
    if (tid < 4) {
        float o = 0.f;
        #pragma unroll 8
        for (int j = 0; j < 128; j++) o += f[j] * clsw[tid * 128 + j];
        out[b * 4 + tid] = o;
    }
}

// ---------------- launch ----------------

extern "C" void kernel_launch(void* const* d_in, const int* in_sizes, int n_in,
                              void* d_out, int out_size) {
    const int*   tokens = (const int*)  d_in[0];
    const float* temb   = (const float*)d_in[1];
    const float* pemb   = (const float*)d_in[2];
    const float* rotp   = (const float*)d_in[3];
    const float* ffw    = (const float*)d_in[4];
    const float* ffb    = (const float*)d_in[5];
    const float* clsw   = (const float*)d_in[6];
    float* out = (float*)d_out;

    k_init<<<128, 256>>>(rotp);
    k_embed_row<<<NB * NS / 32, 256>>>(tokens, temb, pemb);
    k_colA<<<NB * 8, 512>>>();
    k_rowB<<<NB * NS / 32, 256>>>();
    k_final<<<NB, 128>>>(ffw, ffb, clsw, out);
}

// round 8
// speedup vs baseline: 2.7617x; 1.1009x over previous
#include <cuda_runtime.h>
#include <cuda_fp16.h>
#include <cstdint>

// ----------------------------------------------------------------------------
// QFNet classifier, round 8:
//  - embed + rowB butterflies in HALF2 arithmetic (state already fp16):
//    halves SHFL count, halves registers, kills input/output cvts (PRMT instead)
//  - x0 stored fp16 (-48..64MB DRAM)
//  - colA keeps fp32 f32x2 butterflies + verified perm (only x0 read changes)
// ----------------------------------------------------------------------------

#define NB   256
#define NS   512
#define NE   128
#define NDIM 65536

typedef unsigned long long u64;
typedef unsigned int u32;

__device__ __align__(16) __half g_x0h[NB * NDIM];   // x0 fp16, 32 MB
__device__ u32    g_state[NB * NDIM];               // half2(re,im) per element
__device__ float  g_norms[2][NB];
__device__ float  g_m[NB * NE];
__device__ float  g_ry[2 * 32];          // [blk][wire]{c,s}, c=cos(th/2)
__device__ float2 g_ps[2][NS];           // seq D(phi) phase (cos,sin)
__device__ float2 g_pe[2][NE];           // emb D(phi) phase

// ---------------- helpers ----------------

__device__ __forceinline__ u32 h2u(__half2 h) { return *reinterpret_cast<u32*>(&h); }
__device__ __forceinline__ __half2 u2h(u32 u) { return *reinterpret_cast<__half2*>(&u); }
__device__ __forceinline__ float2 h22f2(u32 u) { return __half22float2(u2h(u)); }
__device__ __forceinline__ u64 pk2(float lo, float hi) {
    u64 r; asm("mov.b64 %0, {%1, %2};" : "=l"(r) : "f"(lo), "f"(hi)); return r;
}
__device__ __forceinline__ void up2(u64 v, float& lo, float& hi) {
    asm("mov.b64 {%0, %1}, %2;" : "=f"(lo), "=f"(hi) : "l"(v));
}
__device__ __forceinline__ u64 sp2(float v) { return pk2(v, v); }
__device__ __forceinline__ u64 ffma2(u64 a, u64 b, u64 c) {
    u64 d; asm("fma.rn.f32x2 %0, %1, %2, %3;" : "=l"(d) : "l"(a), "l"(b), "l"(c)); return d;
}
__device__ __forceinline__ u64 fmul2(u64 a, u64 b) {
    u64 d; asm("mul.rn.f32x2 %0, %1, %2;" : "=l"(d) : "l"(a), "l"(b)); return d;
}
__device__ __forceinline__ u64 swp2(u64 v) {
    float a, b; up2(v, a, b); return pk2(b, a);
}

// ---------------- half2 Ry butterfly primitives ----------------

__device__ __forceinline__ u32 hfma2u(u32 a, u32 b, u32 c) {
    return h2u(__hfma2(u2h(a), u2h(b), u2h(c)));
}
__device__ __forceinline__ u32 hmul2u(u32 a, u32 b) {
    return h2u(__hmul2(u2h(a), u2h(b)));
}
__device__ __forceinline__ u32 hswap(u32 v) { return (v >> 16) | (v << 16); }
__device__ __forceinline__ u32 hsplat(float v) { return h2u(__float2half2_rn(v)); }
__device__ __forceinline__ u32 hpack(float lo, float hi) {
    return h2u(__floats2half2_rn(lo, hi));
}

__device__ __forceinline__ void bpairH(u32 c2, u32 s2, u32 ns2,
                                       u32& Lx, u32& Ly, u32& Hx, u32& Hy) {
    u32 ox = hfma2u(c2, Lx, hmul2u(ns2, Hx));
    u32 oy = hfma2u(c2, Ly, hmul2u(ns2, Hy));
    u32 px = hfma2u(c2, Hx, hmul2u(s2,  Lx));
    u32 py = hfma2u(c2, Hy, hmul2u(s2,  Ly));
    Lx = ox; Ly = oy; Hx = px; Hy = py;
}
__device__ __forceinline__ void bshufH(u32 c2, u32 B2, u32& X, u32& Y, int ls) {
    u32 px = __shfl_xor_sync(0xffffffffu, X, ls);
    u32 py = __shfl_xor_sync(0xffffffffu, Y, ls);
    X = hfma2u(c2, X, hmul2u(B2, px));
    Y = hfma2u(c2, Y, hmul2u(B2, py));
}
__device__ __forceinline__ void bpackH(u32 c2, u32 Bp, u32& X, u32& Y) {
    X = hfma2u(c2, X, hmul2u(Bp, hswap(X)));
    Y = hfma2u(c2, Y, hmul2u(Bp, hswap(Y)));
}

// 7-stage embed Ry butterfly in half2. e = 16*t + j (t = lane&7), pack k: j=2k,2k+1.
// ry = 14 floats: (c,s) wires 9..15 at offsets 0..12.
__device__ __forceinline__ void row_butterflyH(const float* ry, u32 Hx[8], u32 Hy[8], int t) {
    { u32 c2=hsplat(ry[6]), s2=hsplat(ry[7]), ns2=hsplat(-ry[7]);   // wire12, e bit3
      #pragma unroll
      for (int k = 0; k < 4; k++) bpairH(c2,s2,ns2, Hx[k],Hy[k], Hx[k+4],Hy[k+4]); }
    { u32 c2=hsplat(ry[8]), s2=hsplat(ry[9]), ns2=hsplat(-ry[9]);   // wire13, e bit2
      bpairH(c2,s2,ns2,Hx[0],Hy[0],Hx[2],Hy[2]); bpairH(c2,s2,ns2,Hx[1],Hy[1],Hx[3],Hy[3]);
      bpairH(c2,s2,ns2,Hx[4],Hy[4],Hx[6],Hy[6]); bpairH(c2,s2,ns2,Hx[5],Hy[5],Hx[7],Hy[7]); }
    { u32 c2=hsplat(ry[10]), s2=hsplat(ry[11]), ns2=hsplat(-ry[11]); // wire14, e bit1
      bpairH(c2,s2,ns2,Hx[0],Hy[0],Hx[1],Hy[1]); bpairH(c2,s2,ns2,Hx[2],Hy[2],Hx[3],Hy[3]);
      bpairH(c2,s2,ns2,Hx[4],Hy[4],Hx[5],Hy[5]); bpairH(c2,s2,ns2,Hx[6],Hy[6],Hx[7],Hy[7]); }
    { u32 c2 = hsplat(ry[12]); u32 Bp = hpack(-ry[13], ry[13]);      // wire15, e bit0
      #pragma unroll
      for (int k = 0; k < 8; k++) bpackH(c2, Bp, Hx[k], Hy[k]); }
    { u32 c2 = hsplat(ry[4]); u32 B2 = hsplat((t&1) ? ry[5] : -ry[5]);  // wire11, bit4
      #pragma unroll
      for (int k = 0; k < 8; k++) bshufH(c2, B2, Hx[k], Hy[k], 1); }
    { u32 c2 = hsplat(ry[2]); u32 B2 = hsplat((t&2) ? ry[3] : -ry[3]);  // wire10, bit5
      #pragma unroll
      for (int k = 0; k < 8; k++) bshufH(c2, B2, Hx[k], Hy[k], 2); }
    { u32 c2 = hsplat(ry[0]); u32 B2 = hsplat((t&4) ? ry[1] : -ry[1]);  // wire9, bit6
      #pragma unroll
      for (int k = 0; k < 8; k++) bshufH(c2, B2, Hx[k], Hy[k], 4); }
}

// 9-stage seq Ry butterfly, fp32 f32x2 (colA only). s = lane + 32*j, pack k: j=2k,2k+1.
__device__ __forceinline__ void bpairR(u64 c2, u64 s2, u64 ns2,
                                       u64& Lx, u64& Ly, u64& Hx, u64& Hy) {
    u64 ox = ffma2(c2, Lx, fmul2(ns2, Hx));
    u64 oy = ffma2(c2, Ly, fmul2(ns2, Hy));
    u64 px = ffma2(c2, Hx, fmul2(s2,  Lx));
    u64 py = ffma2(c2, Hy, fmul2(s2,  Ly));
    Lx = ox; Ly = oy; Hx = px; Hy = py;
}
__device__ __forceinline__ void bshufR(u64 c2, u64 B2, u64& X, u64& Y, int ls) {
    u64 px = __shfl_xor_sync(0xffffffffu, X, ls);
    u64 py = __shfl_xor_sync(0xffffffffu, Y, ls);
    X = ffma2(c2, X, fmul2(B2, px));
    Y = ffma2(c2, Y, fmul2(B2, py));
}
__device__ __forceinline__ void bpackR(u64 c2, u64 Bp, u64& X, u64& Y) {
    X = ffma2(c2, X, fmul2(Bp, swp2(X)));
    Y = ffma2(c2, Y, fmul2(Bp, swp2(Y)));
}
__device__ __forceinline__ void col_butterflyR(const float* ry, u64 Px[8], u64 Py[8], int lane) {
    { u64 c2=sp2(ry[0]), s2=sp2(ry[1]), ns2=sp2(-ry[1]);
      #pragma unroll
      for (int k = 0; k < 4; k++) bpairR(c2,s2,ns2, Px[k],Py[k], Px[k+4],Py[k+4]); }
    { u64 c2=sp2(ry[2]), s2=sp2(ry[3]), ns2=sp2(-ry[3]);
      bpairR(c2,s2,ns2,Px[0],Py[0],Px[2],Py[2]); bpairR(c2,s2,ns2,Px[1],Py[1],Px[3],Py[3]);
      bpairR(c2,s2,ns2,Px[4],Py[4],Px[6],Py[6]); bpairR(c2,s2,ns2,Px[5],Py[5],Px[7],Py[7]); }
    { u64 c2=sp2(ry[4]), s2=sp2(ry[5]), ns2=sp2(-ry[5]);
      bpairR(c2,s2,ns2,Px[0],Py[0],Px[1],Py[1]); bpairR(c2,s2,ns2,Px[2],Py[2],Px[3],Py[3]);
      bpairR(c2,s2,ns2,Px[4],Py[4],Px[5],Py[5]); bpairR(c2,s2,ns2,Px[6],Py[6],Px[7],Py[7]); }
    { u64 c2 = sp2(ry[6]); u64 Bp = pk2(-ry[7], ry[7]);
      #pragma unroll
      for (int k = 0; k < 8; k++) bpackR(c2, Bp, Px[k], Py[k]); }
    #pragma unroll
    for (int st = 0; st < 5; st++) {
        int ls = 16 >> st;
        const float* p = ry + 8 + st * 2;
        u64 c2 = sp2(p[0]); u64 B2 = sp2((lane & ls) ? p[1] : -p[1]);
        #pragma unroll
        for (int k = 0; k < 8; k++) bshufR(c2, B2, Px[k], Py[k], ls);
    }
}

// ---------------- init ----------------

__global__ void k_init(const float* __restrict__ rp) {
    int i = blockIdx.x * 256 + threadIdx.x;
    if (i < NB * NE) g_m[i] = 0.f;
    if (i < 2 * NB)  ((float*)g_norms)[i] = 0.f;
    if (blockIdx.x < 2) {
        int blk = blockIdx.x, tid = threadIdx.x;
        for (int s = tid; s < NS; s += 256) {
            float ang = 0.f;
            #pragma unroll
            for (int w = 0; w < 9; w++) {
                float ph = rp[blk * 48 + w * 3 + 1];
                ang += ((s >> (8 - w)) & 1) ? ph : -ph;
            }
            float c, sn; sincosf(0.5f * ang, &sn, &c);
            g_ps[blk][s] = make_float2(c, sn);
        }
        if (tid < NE) {
            float ang = 0.f;
            #pragma unroll
            for (int w = 9; w < 16; w++) {
                float ph = rp[blk * 48 + w * 3 + 1];
                ang += ((tid >> (15 - w)) & 1) ? ph : -ph;
            }
            float c, sn; sincosf(0.5f * ang, &sn, &c);
            g_pe[blk][tid] = make_float2(c, sn);
        }
        if (tid < 16) {
            float c, sn; sincosf(0.5f * rp[blk * 48 + tid * 3], &sn, &c);
            g_ry[blk * 32 + tid * 2]     = c;
            g_ry[blk * 32 + tid * 2 + 1] = sn;
        }
    }
}

// ---------------- embed + D(phi)_1 + B1 emb butterfly (half2) ----------------

__global__ __launch_bounds__(256) void k_embed_row(const int* __restrict__ tokens,
                                                   const float* __restrict__ temb,
                                                   const float* __restrict__ pemb) {
    __shared__ __align__(16) float ry[14];
    __shared__ __align__(16) u64 epc[64], eps_[64];   // packed emb-phase, idx t*8+k
    __shared__ float wss[8];
    int tid = threadIdx.x;
    if (tid < 14) ry[tid] = g_ry[18 + tid];          // block0 wires 9..15
    if (tid < 64) {
        int t0 = tid >> 3, k0 = tid & 7, e0 = 16 * t0 + 2 * k0;
        float2 A = g_pe[0][e0], B = g_pe[0][e0 + 1];
        epc[tid]  = pk2(A.x, B.x);
        eps_[tid] = pk2(A.y, B.y);
    }
    __syncthreads();
    int warp = tid >> 5, lane = tid & 31, rl = lane >> 3, t = lane & 7;
    int row = blockIdx.x * 32 + warp * 4 + rl;
    int s = row & (NS - 1);
    int tok = tokens[row];
    const float4* te  = (const float4*)(temb + (size_t)tok * NE + 16 * t);
    const float4* pe4 = (const float4*)(pemb + (size_t)s * NE + 16 * t);
    float v[16];
    float ss = 0.f;
    #pragma unroll
    for (int q = 0; q < 4; q++) {
        float4 a = te[q], b = pe4[q];
        float v0 = a.x + b.x, v1 = a.y + b.y, v2 = a.z + b.z, v3 = a.w + b.w;
        ss += v0*v0 + v1*v1 + v2*v2 + v3*v3;
        v[4*q] = v0; v[4*q+1] = v1; v[4*q+2] = v2; v[4*q+3] = v3;
    }
    // x0 store (fp16)
    u32 xh[8];
    #pragma unroll
    for (int k = 0; k < 8; k++) xh[k] = hpack(v[2*k], v[2*k+1]);
    uint4* gx = (uint4*)(g_x0h + (size_t)row * NE + 16 * t);
    gx[0] = make_uint4(xh[0], xh[1], xh[2], xh[3]);
    gx[1] = make_uint4(xh[4], xh[5], xh[6], xh[7]);

    #pragma unroll
    for (int o = 16; o; o >>= 1) ss += __shfl_down_sync(0xffffffffu, ss, o);
    if (lane == 0) wss[warp] = ss;

    // D(phi)_1 in fp32, then convert to half2 packs
    float2 psv = g_ps[0][s];
    u64 a2 = sp2(psv.x), b2 = sp2(psv.y), nb2 = sp2(-psv.y);
    u32 Hx[8], Hy[8];
    #pragma unroll
    for (int k = 0; k < 8; k++) {
        u64 xp = pk2(v[2*k], v[2*k+1]);
        u64 tc = epc[t*8+k], ts = eps_[t*8+k];
        u64 c1 = ffma2(a2, tc, fmul2(nb2, ts));
        u64 s1 = ffma2(b2, tc, fmul2(a2,  ts));
        u64 Pr = fmul2(xp, c1), Pi = fmul2(xp, s1);
        float r0, r1, i0, i1;
        up2(Pr, r0, r1);  up2(Pi, i0, i1);
        Hx[k] = hpack(r0, r1);
        Hy[k] = hpack(i0, i1);
    }

    row_butterflyH(ry, Hx, Hy, t);

    // interleave (re,im) per element and store
    u32 hv[16];
    #pragma unroll
    for (int k = 0; k < 8; k++) {
        hv[2*k]   = __byte_perm(Hx[k], Hy[k], 0x5410);
        hv[2*k+1] = __byte_perm(Hx[k], Hy[k], 0x7632);
    }
    uint4* dst = (uint4*)(g_state + (size_t)row * NE + 16 * t);
    #pragma unroll
    for (int q = 0; q < 4; q++)
        dst[q] = make_uint4(hv[4*q], hv[4*q+1], hv[4*q+2], hv[4*q+3]);

    __syncthreads();
    if (tid == 0) {
        float tot = 0.f;
        #pragma unroll
        for (int q = 0; q < 8; q++) tot += wss[q];
        atomicAdd(&g_norms[0][blockIdx.x >> 4], tot);
    }
}

// ---------------- colA: A1 + perm + residual + D(phi)_2 + A2 (fp32) --------
// 16-column CTAs: batch b, columns {c0..c0+7} U {120-c0..127-c0}.

__global__ __launch_bounds__(512) void k_colA() {
    __shared__ __align__(16) float ryA[18], ryB[18];
    __shared__ __align__(16) u64 tsc[256], tss[256];
    __shared__ __align__(16) u32 tin[16 * 513];
    __shared__ float scol[16];
    __shared__ float ssacc;
    float* tf = reinterpret_cast<float*>(tin);

    int tid = threadIdx.x;
    if (tid < 18)  { ryA[tid] = g_ry[tid]; ryB[tid] = g_ry[32 + tid]; }
    if (tid < 16)  scol[tid] = 0.f;
    if (tid == 0)  ssacc = 0.f;
    if (tid < 256) {
        int k = tid >> 5, l = tid & 31;
        float2 A = g_ps[1][l + 64*k], B = g_ps[1][l + 64*k + 32];
        tsc[tid] = pk2(A.x, B.x);
        tss[tid] = pk2(A.y, B.y);
    }
    int b = blockIdx.x >> 3, grp = blockIdx.x & 7, c0 = grp * 8;
    int i = tid & 7, strip = (tid >> 3) & 1, rb = tid >> 4;
    int gcolL = strip ? (120 - c0 + i) : (c0 + i);
    int cidxL = strip * 8 + i;
    int srcCol = gcolL ^ (gcolL >> 1);
    float inv0 = rsqrtf(g_norms[0][b]);
    const u32* st = g_state + (size_t)b * NDIM;
    #pragma unroll
    for (int it = 0; it < 16; it++) {
        int r = rb + it * 32;
        tin[cidxL * 513 + r] = st[r * NE + srcCol];
    }
    __syncthreads();
    int w = tid >> 5, lane = tid & 31;
    u64 Px[8], Py[8];
    #pragma unroll
    for (int k = 0; k < 8; k++) {
        float2 fa = h22f2(tin[w * 513 + lane + 64*k]);
        float2 fc = h22f2(tin[w * 513 + lane + 64*k + 32]);
        Px[k] = pk2(fa.x, fc.x);  Py[k] = pk2(fa.y, fc.y);
    }
    __syncthreads();

    col_butterflyR(ryA, Px, Py, lane);

    // CNOT perm + |.|*inv0 scatter
    int colw = (w < 8) ? (c0 + w) : (112 - c0 + w);
    #pragma unroll
    for (int k = 0; k < 8; k++) {
        float xr0, xr1, yi0, yi1;
        up2(Px[k], xr0, xr1);  up2(Py[k], yi0, yi1);
        #pragma unroll
        for (int h = 0; h < 2; h++) {
            int ss = lane + 64*k + 32*h;
            float xr = h ? xr1 : xr0, yi = h ? yi1 : yi0;
            int sp = ss; sp ^= sp >> 1; sp ^= sp >> 2; sp ^= sp >> 4; sp ^= sp >> 8;
            int par = sp & 1;
            int cO    = par ? (15 - w) : w;
            int gcolO = par ? (colw ^ 127) : colw;
            int sdd   = sp ^ ((gcolO & 1) << 8);
            tf[cO * 513 + sdd] = sqrtf(xr*xr + yi*yi) * inv0;
        }
    }
    __syncthreads();

    // residual + stats, in place (x0 now fp16)
    const __half* x0p = g_x0h + (size_t)b * NDIM;
    float cs = 0.f, sq = 0.f;
    #pragma unroll
    for (int it = 0; it < 16; it++) {
        int r = rb + it * 32;
        float v = tf[cidxL * 513 + r] + __half2float(x0p[r * NE + gcolL]);
        tf[cidxL * 513 + r] = v;
        cs += v;  sq += v * v;
    }
    atomicAdd(&scol[cidxL], cs);
    #pragma unroll
    for (int o = 16; o; o >>= 1) sq += __shfl_down_sync(0xffffffffu, sq, o);
    if (lane == 0) atomicAdd(&ssacc, sq);
    __syncthreads();

    if (tid == 0) atomicAdd(&g_norms[1][b], ssacc);
    if (tid < 16) {
        int gc = (tid < 8) ? (c0 + tid) : (112 - c0 + tid);
        atomicAdd(&g_m[b * NE + gc], scol[tid]);
    }

    // reload x1 + D(phi)_2
    float2 pev = g_pe[1][colw];
    u64 a2 = sp2(pev.x), b2 = sp2(pev.y), nb2 = sp2(-pev.y);
    #pragma unroll
    for (int k = 0; k < 8; k++) {
        u64 x1p = pk2(tf[w * 513 + lane + 64*k], tf[w * 513 + lane + 64*k + 32]);
        u64 tc = tsc[k*32 + lane], ts = tss[k*32 + lane];
        u64 c12 = ffma2(a2, tc, fmul2(nb2, ts));
        u64 s12 = ffma2(b2, tc, fmul2(a2,  ts));
        Px[k] = fmul2(x1p, c12);
        Py[k] = fmul2(x1p, s12);
    }
    __syncthreads();

    col_butterflyR(ryB, Px, Py, lane);

    #pragma unroll
    for (int k = 0; k < 8; k++) {
        float x0, x1, y0, y1;
        up2(Px[k], x0, x1);  up2(Py[k], y0, y1);
        tin[w * 513 + lane + 64*k]      = h2u(__floats2half2_rn(x0, y0));
        tin[w * 513 + lane + 64*k + 32] = h2u(__floats2half2_rn(x1, y1));
    }
    __syncthreads();
    u32* yp = g_state + (size_t)b * NDIM;
    #pragma unroll
    for (int it = 0; it < 16; it++) {
        int r = rb + it * 32;
        yp[r * NE + gcolL] = tin[cidxL * 513 + r];
    }
}

// ---------------- rowB: B2 emb butterfly (half2) + column-sum reduction ----

__global__ __launch_bounds__(256) void k_rowB() {
    __shared__ __align__(16) u32 srow[32][68];   // 64 half2 words + pad
    __shared__ __align__(16) float ry[14];
    int tid = threadIdx.x;
    if (tid < 14) ry[tid] = g_ry[32 + 18 + tid];     // block1 wires 9..15
    __syncthreads();
    int warp = tid >> 5, lane = tid & 31, rl = lane >> 3, t = lane & 7;
    int rls = warp * 4 + rl;
    int row = blockIdx.x * 32 + rls;
    int b = row >> 9;
    float inv1 = rsqrtf(g_norms[1][b]);
    const uint4* src = (const uint4*)(g_state + (size_t)row * NE + 16 * t);
    u32 Hx[8], Hy[8];
    #pragma unroll
    for (int q = 0; q < 4; q++) {
        uint4 U = src[q];
        Hx[2*q]   = __byte_perm(U.x, U.y, 0x5410);
        Hy[2*q]   = __byte_perm(U.x, U.y, 0x7632);
        Hx[2*q+1] = __byte_perm(U.z, U.w, 0x5410);
        Hy[2*q+1] = __byte_perm(U.z, U.w, 0x7632);
    }

    row_butterflyH(ry, Hx, Hy, t);

    // magnitudes (half2), store linear; inv1 applied at accumulation
    u32 hm[8];
    #pragma unroll
    for (int k = 0; k < 8; k++) {
        u32 msq = hfma2u(Hx[k], Hx[k], hmul2u(Hy[k], Hy[k]));
        hm[k] = h2u(h2sqrt(u2h(msq)));
    }
    uint4* wp = (uint4*)&srow[rls][8 * t];
    wp[0] = make_uint4(hm[0], hm[1], hm[2], hm[3]);
    wp[1] = make_uint4(hm[4], hm[5], hm[6], hm[7]);
    __syncthreads();

    int e = tid & 127, half = tid >> 7;
    int sbase = (blockIdx.x * 32) & (NS - 1);
    const __half* srh = (const __half*)srow;
    float acc = 0.f;
    #pragma unroll
    for (int q = 0; q < 16; q++) {
        int r = half * 16 + q;
        int s = sbase + r;
        int mask = (__popc(s) & 1) ? 127 : 0;
        int g = e ^ mask;
        int es = g ^ (g >> 1);
        acc += __half2float(srh[r * 136 + es]);
    }
    atomicAdd(&g_m[b * NE + e], acc * inv1);
}

// ---------------- final ----------------

__global__ void k_final(const float* __restrict__ ffw, const float* __restrict__ ffb,
                        const float* __restrict__ clsw, float* __restrict__ out) {
    int b = blockIdx.x, tid = threadIdx.x;
    __shared__ float mm[128], f[128];
    mm[tid] = g_m[b * NE + tid] * (1.f / 512.f);
    __syncthreads();
    float acc = ffb[tid];
    #pragma unroll 8
    for (int e = 0; e < 128; e++) acc += mm[e] * ffw[tid * 128 + e];
    f[tid] = acc;
    __syncthreads();
    if (tid < 4) {
        float o = 0.f;
        #pragma unroll 8
        for (int j = 0; j < 128; j++) o += f[j] * clsw[tid * 128 + j];
        out[b * 4 + tid] = o;
    }
}

// ---------------- launch ----------------

extern "C" void kernel_launch(void* const* d_in, const int* in_sizes, int n_in,
                              void* d_out, int out_size) {
    const int*   tokens = (const int*)  d_in[0];
    const float* temb   = (const float*)d_in[1];
    const float* pemb   = (const float*)d_in[2];
    const float* rotp   = (const float*)d_in[3];
    const float* ffw    = (const float*)d_in[4];
    const float* ffb    = (const float*)d_in[5];
    const float* clsw   = (const float*)d_in[6];
    float* out = (float*)d_out;

    k_init<<<128, 256>>>(rotp);
    k_embed_row<<<NB * NS / 32, 256>>>(tokens, temb, pemb);
    k_colA<<<NB * 8, 512>>>();
    k_rowB<<<NB * NS / 32, 256>>>();
    k_final<<<NB, 128>>>(ffw, ffb, clsw, out);
}

// round 9
// speedup vs baseline: 3.2783x; 1.1871x over previous
#include <cuda_runtime.h>
#include <cuda_fp16.h>
#include <cstdint>

// ----------------------------------------------------------------------------
// QFNet classifier, round 9:
//  - ALL butterflies now half2 (colA converted): halves regs/SHFL/cvts there
//  - scatter + reduction addresses via GF(2)-linear prefix-xor decomposition:
//    per-element address = XOR + ADD (compile-time constants from unroll)
//  - residual / stats / phase multiplies stay fp32
// ----------------------------------------------------------------------------

#define NB   256
#define NS   512
#define NE   128
#define NDIM 65536

typedef unsigned long long u64;
typedef unsigned int u32;

__device__ __align__(16) __half g_x0h[NB * NDIM];   // x0 fp16
__device__ u32    g_state[NB * NDIM];               // half2(re,im) per element
__device__ float  g_norms[2][NB];
__device__ float  g_m[NB * NE];
__device__ float  g_ry[2 * 32];          // [blk][wire]{c,s}, c=cos(th/2)
__device__ float2 g_ps[2][NS];           // seq D(phi) phase (cos,sin)
__device__ float2 g_pe[2][NE];           // emb D(phi) phase

// ---------------- helpers ----------------

__device__ __forceinline__ u32 h2u(__half2 h) { return *reinterpret_cast<u32*>(&h); }
__device__ __forceinline__ __half2 u2h(u32 u) { return *reinterpret_cast<__half2*>(&u); }
__device__ __forceinline__ float2 h22f2(u32 u) { return __half22float2(u2h(u)); }
__device__ __forceinline__ u64 pk2(float lo, float hi) {
    u64 r; asm("mov.b64 %0, {%1, %2};" : "=l"(r) : "f"(lo), "f"(hi)); return r;
}
__device__ __forceinline__ void up2(u64 v, float& lo, float& hi) {
    asm("mov.b64 {%0, %1}, %2;" : "=f"(lo), "=f"(hi) : "l"(v));
}
__device__ __forceinline__ u64 sp2(float v) { return pk2(v, v); }
__device__ __forceinline__ u64 ffma2(u64 a, u64 b, u64 c) {
    u64 d; asm("fma.rn.f32x2 %0, %1, %2, %3;" : "=l"(d) : "l"(a), "l"(b), "l"(c)); return d;
}
__device__ __forceinline__ u64 fmul2(u64 a, u64 b) {
    u64 d; asm("mul.rn.f32x2 %0, %1, %2;" : "=l"(d) : "l"(a), "l"(b)); return d;
}

// compile-time 9-bit suffix-xor (prefix from MSB) transform
__device__ __forceinline__ constexpr int px9c(int x) {
    x ^= x >> 1; x ^= x >> 2; x ^= x >> 4; x ^= x >> 8; return x;
}

// ---------------- half2 Ry butterfly primitives ----------------

__device__ __forceinline__ u32 hfma2u(u32 a, u32 b, u32 c) {
    return h2u(__hfma2(u2h(a), u2h(b), u2h(c)));
}
__device__ __forceinline__ u32 hmul2u(u32 a, u32 b) {
    return h2u(__hmul2(u2h(a), u2h(b)));
}
__device__ __forceinline__ u32 hswap(u32 v) { return (v >> 16) | (v << 16); }
__device__ __forceinline__ u32 hsplat(float v) { return h2u(__float2half2_rn(v)); }
__device__ __forceinline__ u32 hpack(float lo, float hi) {
    return h2u(__floats2half2_rn(lo, hi));
}

__device__ __forceinline__ void bpairH(u32 c2, u32 s2, u32 ns2,
                                       u32& Lx, u32& Ly, u32& Hx, u32& Hy) {
    u32 ox = hfma2u(c2, Lx, hmul2u(ns2, Hx));
    u32 oy = hfma2u(c2, Ly, hmul2u(ns2, Hy));
    u32 px = hfma2u(c2, Hx, hmul2u(s2,  Lx));
    u32 py = hfma2u(c2, Hy, hmul2u(s2,  Ly));
    Lx = ox; Ly = oy; Hx = px; Hy = py;
}
__device__ __forceinline__ void bshufH(u32 c2, u32 B2, u32& X, u32& Y, int ls) {
    u32 px = __shfl_xor_sync(0xffffffffu, X, ls);
    u32 py = __shfl_xor_sync(0xffffffffu, Y, ls);
    X = hfma2u(c2, X, hmul2u(B2, px));
    Y = hfma2u(c2, Y, hmul2u(B2, py));
}
__device__ __forceinline__ void bpackH(u32 c2, u32 Bp, u32& X, u32& Y) {
    X = hfma2u(c2, X, hmul2u(Bp, hswap(X)));
    Y = hfma2u(c2, Y, hmul2u(Bp, hswap(Y)));
}

// 7-stage embed Ry butterfly in half2. e = 16*t + j (t = lane&7), pack k: j=2k,2k+1.
__device__ __forceinline__ void row_butterflyH(const float* ry, u32 Hx[8], u32 Hy[8], int t) {
    { u32 c2=hsplat(ry[6]), s2=hsplat(ry[7]), ns2=hsplat(-ry[7]);   // wire12, e bit3
      #pragma unroll
      for (int k = 0; k < 4; k++) bpairH(c2,s2,ns2, Hx[k],Hy[k], Hx[k+4],Hy[k+4]); }
    { u32 c2=hsplat(ry[8]), s2=hsplat(ry[9]), ns2=hsplat(-ry[9]);   // wire13, e bit2
      bpairH(c2,s2,ns2,Hx[0],Hy[0],Hx[2],Hy[2]); bpairH(c2,s2,ns2,Hx[1],Hy[1],Hx[3],Hy[3]);
      bpairH(c2,s2,ns2,Hx[4],Hy[4],Hx[6],Hy[6]); bpairH(c2,s2,ns2,Hx[5],Hy[5],Hx[7],Hy[7]); }
    { u32 c2=hsplat(ry[10]), s2=hsplat(ry[11]), ns2=hsplat(-ry[11]); // wire14, e bit1
      bpairH(c2,s2,ns2,Hx[0],Hy[0],Hx[1],Hy[1]); bpairH(c2,s2,ns2,Hx[2],Hy[2],Hx[3],Hy[3]);
      bpairH(c2,s2,ns2,Hx[4],Hy[4],Hx[5],Hy[5]); bpairH(c2,s2,ns2,Hx[6],Hy[6],Hx[7],Hy[7]); }
    { u32 c2 = hsplat(ry[12]); u32 Bp = hpack(-ry[13], ry[13]);      // wire15, e bit0
      #pragma unroll
      for (int k = 0; k < 8; k++) bpackH(c2, Bp, Hx[k], Hy[k]); }
    { u32 c2 = hsplat(ry[4]); u32 B2 = hsplat((t&1) ? ry[5] : -ry[5]);  // wire11, bit4
      #pragma unroll
      for (int k = 0; k < 8; k++) bshufH(c2, B2, Hx[k], Hy[k], 1); }
    { u32 c2 = hsplat(ry[2]); u32 B2 = hsplat((t&2) ? ry[3] : -ry[3]);  // wire10, bit5
      #pragma unroll
      for (int k = 0; k < 8; k++) bshufH(c2, B2, Hx[k], Hy[k], 2); }
    { u32 c2 = hsplat(ry[0]); u32 B2 = hsplat((t&4) ? ry[1] : -ry[1]);  // wire9, bit6
      #pragma unroll
      for (int k = 0; k < 8; k++) bshufH(c2, B2, Hx[k], Hy[k], 4); }
}

// 9-stage seq Ry butterfly in half2. s = lane + 32*j, pack k: j=2k (lo), 2k+1 (hi).
// ry = 18 floats: (c,s) wires 0..8 at offsets 0..16.
__device__ __forceinline__ void col_butterflyH(const float* ry, u32 Hx[8], u32 Hy[8], int lane) {
    { u32 c2=hsplat(ry[0]), s2=hsplat(ry[1]), ns2=hsplat(-ry[1]);   // wire0, s bit8
      #pragma unroll
      for (int k = 0; k < 4; k++) bpairH(c2,s2,ns2, Hx[k],Hy[k], Hx[k+4],Hy[k+4]); }
    { u32 c2=hsplat(ry[2]), s2=hsplat(ry[3]), ns2=hsplat(-ry[3]);   // wire1, s bit7
      bpairH(c2,s2,ns2,Hx[0],Hy[0],Hx[2],Hy[2]); bpairH(c2,s2,ns2,Hx[1],Hy[1],Hx[3],Hy[3]);
      bpairH(c2,s2,ns2,Hx[4],Hy[4],Hx[6],Hy[6]); bpairH(c2,s2,ns2,Hx[5],Hy[5],Hx[7],Hy[7]); }
    { u32 c2=hsplat(ry[4]), s2=hsplat(ry[5]), ns2=hsplat(-ry[5]);   // wire2, s bit6
      bpairH(c2,s2,ns2,Hx[0],Hy[0],Hx[1],Hy[1]); bpairH(c2,s2,ns2,Hx[2],Hy[2],Hx[3],Hy[3]);
      bpairH(c2,s2,ns2,Hx[4],Hy[4],Hx[5],Hy[5]); bpairH(c2,s2,ns2,Hx[6],Hy[6],Hx[7],Hy[7]); }
    { u32 c2 = hsplat(ry[6]); u32 Bp = hpack(-ry[7], ry[7]);        // wire3, s bit5
      #pragma unroll
      for (int k = 0; k < 8; k++) bpackH(c2, Bp, Hx[k], Hy[k]); }
    #pragma unroll
    for (int st = 0; st < 5; st++) {                                // wires 4..8
        int ls = 16 >> st;
        const float* p = ry + 8 + st * 2;
        u32 c2 = hsplat(p[0]); u32 B2 = hsplat((lane & ls) ? p[1] : -p[1]);
        #pragma unroll
        for (int k = 0; k < 8; k++) bshufH(c2, B2, Hx[k], Hy[k], ls);
    }
}

// ---------------- init ----------------

__global__ void k_init(const float* __restrict__ rp) {
    int i = blockIdx.x * 256 + threadIdx.x;
    if (i < NB * NE) g_m[i] = 0.f;
    if (i < 2 * NB)  ((float*)g_norms)[i] = 0.f;
    if (blockIdx.x < 2) {
        int blk = blockIdx.x, tid = threadIdx.x;
        for (int s = tid; s < NS; s += 256) {
            float ang = 0.f;
            #pragma unroll
            for (int w = 0; w < 9; w++) {
                float ph = rp[blk * 48 + w * 3 + 1];
                ang += ((s >> (8 - w)) & 1) ? ph : -ph;
            }
            float c, sn; sincosf(0.5f * ang, &sn, &c);
            g_ps[blk][s] = make_float2(c, sn);
        }
        if (tid < NE) {
            float ang = 0.f;
            #pragma unroll
            for (int w = 9; w < 16; w++) {
                float ph = rp[blk * 48 + w * 3 + 1];
                ang += ((tid >> (15 - w)) & 1) ? ph : -ph;
            }
            float c, sn; sincosf(0.5f * ang, &sn, &c);
            g_pe[blk][tid] = make_float2(c, sn);
        }
        if (tid < 16) {
            float c, sn; sincosf(0.5f * rp[blk * 48 + tid * 3], &sn, &c);
            g_ry[blk * 32 + tid * 2]     = c;
            g_ry[blk * 32 + tid * 2 + 1] = sn;
        }
    }
}

// ---------------- embed + D(phi)_1 + B1 emb butterfly (half2) ----------------

__global__ __launch_bounds__(256) void k_embed_row(const int* __restrict__ tokens,
                                                   const float* __restrict__ temb,
                                                   const float* __restrict__ pemb) {
    __shared__ __align__(16) float ry[14];
    __shared__ __align__(16) u64 epc[64], eps_[64];   // packed emb-phase, idx t*8+k
    __shared__ float wss[8];
    int tid = threadIdx.x;
    if (tid < 14) ry[tid] = g_ry[18 + tid];          // block0 wires 9..15
    if (tid < 64) {
        int t0 = tid >> 3, k0 = tid & 7, e0 = 16 * t0 + 2 * k0;
        float2 A = g_pe[0][e0], B = g_pe[0][e0 + 1];
        epc[tid]  = pk2(A.x, B.x);
        eps_[tid] = pk2(A.y, B.y);
    }
    __syncthreads();
    int warp = tid >> 5, lane = tid & 31, rl = lane >> 3, t = lane & 7;
    int row = blockIdx.x * 32 + warp * 4 + rl;
    int s = row & (NS - 1);
    int tok = tokens[row];
    const float4* te  = (const float4*)(temb + (size_t)tok * NE + 16 * t);
    const float4* pe4 = (const float4*)(pemb + (size_t)s * NE + 16 * t);
    float v[16];
    float ss = 0.f;
    #pragma unroll
    for (int q = 0; q < 4; q++) {
        float4 a = te[q], b = pe4[q];
        float v0 = a.x + b.x, v1 = a.y + b.y, v2 = a.z + b.z, v3 = a.w + b.w;
        ss += v0*v0 + v1*v1 + v2*v2 + v3*v3;
        v[4*q] = v0; v[4*q+1] = v1; v[4*q+2] = v2; v[4*q+3] = v3;
    }
    // x0 store (fp16)
    u32 xh[8];
    #pragma unroll
    for (int k = 0; k < 8; k++) xh[k] = hpack(v[2*k], v[2*k+1]);
    uint4* gx = (uint4*)(g_x0h + (size_t)row * NE + 16 * t);
    gx[0] = make_uint4(xh[0], xh[1], xh[2], xh[3]);
    gx[1] = make_uint4(xh[4], xh[5], xh[6], xh[7]);

    #pragma unroll
    for (int o = 16; o; o >>= 1) ss += __shfl_down_sync(0xffffffffu, ss, o);
    if (lane == 0) wss[warp] = ss;

    // D(phi)_1 in fp32, then convert to half2 packs
    float2 psv = g_ps[0][s];
    u64 a2 = sp2(psv.x), b2 = sp2(psv.y), nb2 = sp2(-psv.y);
    u32 Hx[8], Hy[8];
    #pragma unroll
    for (int k = 0; k < 8; k++) {
        u64 xp = pk2(v[2*k], v[2*k+1]);
        u64 tc = epc[t*8+k], ts = eps_[t*8+k];
        u64 c1 = ffma2(a2, tc, fmul2(nb2, ts));
        u64 s1 = ffma2(b2, tc, fmul2(a2,  ts));
        u64 Pr = fmul2(xp, c1), Pi = fmul2(xp, s1);
        float r0, r1, i0, i1;
        up2(Pr, r0, r1);  up2(Pi, i0, i1);
        Hx[k] = hpack(r0, r1);
        Hy[k] = hpack(i0, i1);
    }

    row_butterflyH(ry, Hx, Hy, t);

    u32 hv[16];
    #pragma unroll
    for (int k = 0; k < 8; k++) {
        hv[2*k]   = __byte_perm(Hx[k], Hy[k], 0x5410);
        hv[2*k+1] = __byte_perm(Hx[k], Hy[k], 0x7632);
    }
    uint4* dst = (uint4*)(g_state + (size_t)row * NE + 16 * t);
    #pragma unroll
    for (int q = 0; q < 4; q++)
        dst[q] = make_uint4(hv[4*q], hv[4*q+1], hv[4*q+2], hv[4*q+3]);

    __syncthreads();
    if (tid == 0) {
        float tot = 0.f;
        #pragma unroll
        for (int q = 0; q < 8; q++) tot += wss[q];
        atomicAdd(&g_norms[0][blockIdx.x >> 4], tot);
    }
}

// ---------------- colA: A1 + perm + residual + D(phi)_2 + A2 (half2) -------
// 16-column CTAs: batch b, columns {c0..c0+7} U {120-c0..127-c0}.

__global__ __launch_bounds__(512) void k_colA() {
    __shared__ __align__(16) float ryA[18], ryB[18];
    __shared__ __align__(16) u64 tsc[256], tss[256];
    __shared__ __align__(16) u32 tin[16 * 513];
    __shared__ float scol[16];
    __shared__ float ssacc;
    float* tf = reinterpret_cast<float*>(tin);

    int tid = threadIdx.x;
    if (tid < 18)  { ryA[tid] = g_ry[tid]; ryB[tid] = g_ry[32 + tid]; }
    if (tid < 16)  scol[tid] = 0.f;
    if (tid == 0)  ssacc = 0.f;
    if (tid < 256) {
        int k = tid >> 5, l = tid & 31;
        float2 A = g_ps[1][l + 64*k], B = g_ps[1][l + 64*k + 32];
        tsc[tid] = pk2(A.x, B.x);
        tss[tid] = pk2(A.y, B.y);
    }
    int b = blockIdx.x >> 3, grp = blockIdx.x & 7, c0 = grp * 8;
    int i = tid & 7, strip = (tid >> 3) & 1, rb = tid >> 4;
    int gcolL = strip ? (120 - c0 + i) : (c0 + i);
    int cidxL = strip * 8 + i;
    int srcCol = gcolL ^ (gcolL >> 1);
    float inv0 = rsqrtf(g_norms[0][b]);
    const u32* st = g_state + (size_t)b * NDIM;
    #pragma unroll
    for (int it = 0; it < 16; it++) {
        int r = rb + it * 32;
        tin[cidxL * 513 + r] = st[r * NE + srcCol];
    }
    __syncthreads();
    int w = tid >> 5, lane = tid & 31;
    u32 Hx[8], Hy[8];
    #pragma unroll
    for (int k = 0; k < 8; k++) {
        u32 w0 = tin[w * 513 + lane + 64*k];
        u32 w1 = tin[w * 513 + lane + 64*k + 32];
        Hx[k] = __byte_perm(w0, w1, 0x5410);
        Hy[k] = __byte_perm(w0, w1, 0x7632);
    }
    __syncthreads();

    col_butterflyH(ryA, Hx, Hy, lane);

    // CNOT perm + |.|*inv0 scatter; addresses via GF(2)-linear decomposition:
    // sp(lane+64k+32h) = px(lane) ^ px9c(64k+32h); par splits the same way.
    int colw = (w < 8) ? (c0 + w) : (112 - c0 + w);
    {
        int pxl = lane ^ (lane >> 1); pxl ^= pxl >> 2; pxl ^= pxl >> 4;
        int parl = __popc(lane) & 1;
        int lowb = colw & 1;
        int c_sel0 = (parl ? (15 - w) : w) * 513;          // for PAR_KH = 0
        int c_sel1 = (parl ? w : (15 - w)) * 513;          // for PAR_KH = 1
        int sel0 = pxl ^ ((lowb ^ parl) << 8);
        int sel1 = pxl ^ ((lowb ^ parl ^ 1) << 8);
        #pragma unroll
        for (int k = 0; k < 8; k++) {
            u32 m2 = hfma2u(Hx[k], Hx[k], hmul2u(Hy[k], Hy[k]));
            float2 mf = h22f2(m2);
            float mag0 = sqrtf(mf.x) * inv0;               // h=0: ss = lane+64k
            float mag1 = sqrtf(mf.y) * inv0;               // h=1: ss = lane+64k+32
            const int PXC0 = px9c(64 * k);
            const int PXC1 = px9c(64 * k + 32);
            const int P0 = __popc(k) & 1;                  // PAR_KH for h=0; h=1 flips
            int addr0 = (P0 ? c_sel1 : c_sel0) + ((P0 ? sel1 : sel0) ^ PXC0);
            int addr1 = (P0 ? c_sel0 : c_sel1) + ((P0 ? sel0 : sel1) ^ PXC1);
            tf[addr0] = mag0;
            tf[addr1] = mag1;
        }
    }
    __syncthreads();

    // residual + stats, in place (fp32)
    const __half* x0p = g_x0h + (size_t)b * NDIM;
    float cs = 0.f, sq = 0.f;
    #pragma unroll
    for (int it = 0; it < 16; it++) {
        int r = rb + it * 32;
        float v = tf[cidxL * 513 + r] + __half2float(x0p[r * NE + gcolL]);
        tf[cidxL * 513 + r] = v;
        cs += v;  sq += v * v;
    }
    atomicAdd(&scol[cidxL], cs);
    #pragma unroll
    for (int o = 16; o; o >>= 1) sq += __shfl_down_sync(0xffffffffu, sq, o);
    if (lane == 0) atomicAdd(&ssacc, sq);
    __syncthreads();

    if (tid == 0) atomicAdd(&g_norms[1][b], ssacc);
    if (tid < 16) {
        int gc = (tid < 8) ? (c0 + tid) : (112 - c0 + tid);
        atomicAdd(&g_m[b * NE + gc], scol[tid]);
    }

    // reload x1 + D(phi)_2 in fp32, pack to half2
    float2 pev = g_pe[1][colw];
    u64 a2 = sp2(pev.x), b2 = sp2(pev.y), nb2 = sp2(-pev.y);
    #pragma unroll
    for (int k = 0; k < 8; k++) {
        u64 x1p = pk2(tf[w * 513 + lane + 64*k], tf[w * 513 + lane + 64*k + 32]);
        u64 tc = tsc[k*32 + lane], ts = tss[k*32 + lane];
        u64 c12 = ffma2(a2, tc, fmul2(nb2, ts));
        u64 s12 = ffma2(b2, tc, fmul2(a2,  ts));
        u64 Pr = fmul2(x1p, c12), Pi = fmul2(x1p, s12);
        float r0, r1, i0, i1;
        up2(Pr, r0, r1);  up2(Pi, i0, i1);
        Hx[k] = hpack(r0, r1);
        Hy[k] = hpack(i0, i1);
    }
    __syncthreads();

    col_butterflyH(ryB, Hx, Hy, lane);

    #pragma unroll
    for (int k = 0; k < 8; k++) {
        tin[w * 513 + lane + 64*k]      = __byte_perm(Hx[k], Hy[k], 0x5410);
        tin[w * 513 + lane + 64*k + 32] = __byte_perm(Hx[k], Hy[k], 0x7632);
    }
    __syncthreads();
    u32* yp = g_state + (size_t)b * NDIM;
    #pragma unroll
    for (int it = 0; it < 16; it++) {
        int r = rb + it * 32;
        yp[r * NE + gcolL] = tin[cidxL * 513 + r];
    }
}

// ---------------- rowB: B2 emb butterfly (half2) + column-sum reduction ----

__global__ __launch_bounds__(256) void k_rowB() {
    __shared__ __align__(16) u32 srow[32][68];   // 64 half2 words + pad
    __shared__ __align__(16) float ry[14];
    int tid = threadIdx.x;
    if (tid < 14) ry[tid] = g_ry[32 + 18 + tid];     // block1 wires 9..15
    __syncthreads();
    int warp = tid >> 5, lane = tid & 31, rl = lane >> 3, t = lane & 7;
    int rls = warp * 4 + rl;
    int row = blockIdx.x * 32 + rls;
    int b = row >> 9;
    float inv1 = rsqrtf(g_norms[1][b]);
    const uint4* src = (const uint4*)(g_state + (size_t)row * NE + 16 * t);
    u32 Hx[8], Hy[8];
    #pragma unroll
    for (int q = 0; q < 4; q++) {
        uint4 U = src[q];
        Hx[2*q]   = __byte_perm(U.x, U.y, 0x5410);
        Hy[2*q]   = __byte_perm(U.x, U.y, 0x7632);
        Hx[2*q+1] = __byte_perm(U.z, U.w, 0x5410);
        Hy[2*q+1] = __byte_perm(U.z, U.w, 0x7632);
    }

    row_butterflyH(ry, Hx, Hy, t);

    u32 hm[8];
    #pragma unroll
    for (int k = 0; k < 8; k++) {
        u32 msq = hfma2u(Hx[k], Hx[k], hmul2u(Hy[k], Hy[k]));
        hm[k] = h2u(h2sqrt(u2h(msq)));
    }
    uint4* wp = (uint4*)&srow[rls][8 * t];
    wp[0] = make_uint4(hm[0], hm[1], hm[2], hm[3]);
    wp[1] = make_uint4(hm[4], hm[5], hm[6], hm[7]);
    __syncthreads();

    // reduction: es = (e^(e>>1)) ^ 64*par(s); par(s)=par(sbase)^half^par(q)
    int e = tid & 127, half = tid >> 7;
    int sbase = (blockIdx.x * 32) & (NS - 1);
    int ebase = e ^ (e >> 1);
    int p0 = (__popc(sbase) ^ half) & 1;
    int esA = ebase ^ (p0 << 6);     // par(q) even
    int esB = esA ^ 64;              // par(q) odd
    const __half* srh = (const __half*)srow;
    float acc = 0.f;
    #pragma unroll
    for (int q = 0; q < 16; q++) {
        int r = half * 16 + q;
        int es = ((0x6996 >> q) & 1) ? esB : esA;
        acc += __half2float(srh[r * 136 + es]);
    }
    atomicAdd(&g_m[b * NE + e], acc * inv1);
}

// ---------------- final ----------------

__global__ void k_final(const float* __restrict__ ffw, const float* __restrict__ ffb,
                        const float* __restrict__ clsw, float* __restrict__ out) {
    int b = blockIdx.x, tid = threadIdx.x;
    __shared__ float mm[128], f[128];
    mm[tid] = g_m[b * NE + tid] * (1.f / 512.f);
    __syncthreads();
    float acc = ffb[tid];
    #pragma unroll 8
    for (int e = 0; e < 128; e++) acc += mm[e] * ffw[tid * 128 + e];
    f[tid] = acc;
    __syncthreads();
    if (tid < 4) {
        float o = 0.f;
        #pragma unroll 8
        for (int j = 0; j < 128; j++) o += f[j] * clsw[tid * 128 + j];
        out[b * 4 + tid] = o;
    }
}

// ---------------- launch ----------------

extern "C" void kernel_launch(void* const* d_in, const int* in_sizes, int n_in,
                              void* d_out, int out_size) {
    const int*   tokens = (const int*)  d_in[0];
    const float* temb   = (const float*)d_in[1];
    const float* pemb   = (const float*)d_in[2];
    const float* rotp   = (const float*)d_in[3];
    const float* ffw    = (const float*)d_in[4];
    const float* ffb    = (const float*)d_in[5];
    const float* clsw   = (const float*)d_in[6];
    float* out = (float*)d_out;

    k_init<<<128, 256>>>(rotp);
    k_embed_row<<<NB * NS / 32, 256>>>(tokens, temb, pemb);
    k_colA<<<NB * 8, 512>>>();
    k_rowB<<<NB * NS / 32, 256>>>();
    k_final<<<NB, 128>>>(ffw, ffb, clsw, out);
}

// round 10
// speedup vs baseline: 3.3953x; 1.0357x over previous
#include <cuda_runtime.h>
#include <cuda_fp16.h>
#include <cstdint>

// ----------------------------------------------------------------------------
// QFNet classifier, round 10:
//  - k_init removed: all gate/phase tables recomputed per-CTA (cheap sincosf)
//  - atomic-free: per-block partial sums (g_n0p/g_n1p/g_mA/g_mB), consumer sums
//  - D(phi) phase application in half2 (no f32x2 + cvt chains)
//  - butterflies all half2 (R9-verified), scatter GF(2) addressing (R9-verified)
// ----------------------------------------------------------------------------

#define NB   256
#define NS   512
#define NE   128
#define NDIM 65536

typedef unsigned long long u64;
typedef unsigned int u32;

__device__ __align__(16) __half g_x0h[NB * NDIM];   // x0 fp16
__device__ u32    g_state[NB * NDIM];               // half2(re,im) per element
__device__ float  g_n0p[NB * 16];                   // embed norm0 partials
__device__ float  g_n1p[NB * 8];                    // colA norm1 partials
__device__ float  g_mA[NB * NE];                    // colA column sums (written)
__device__ float  g_mB[NB * 16 * NE];               // rowB per-block column sums

// ---------------- helpers ----------------

__device__ __forceinline__ u32 h2u(__half2 h) { return *reinterpret_cast<u32*>(&h); }
__device__ __forceinline__ __half2 u2h(u32 u) { return *reinterpret_cast<__half2*>(&u); }
__device__ __forceinline__ float2 h22f2(u32 u) { return __half22float2(u2h(u)); }

// compile-time 9-bit prefix-xor (from MSB) transform
__device__ __forceinline__ constexpr int px9c(int x) {
    x ^= x >> 1; x ^= x >> 2; x ^= x >> 4; x ^= x >> 8; return x;
}

// separable D(phi) phase factors, computed from rot_params directly
__device__ __forceinline__ float2 phase_s(const float* rp, int blk, int s) {
    float ang = 0.f;
    #pragma unroll
    for (int w = 0; w < 9; w++) {
        float ph = rp[blk * 48 + w * 3 + 1];
        ang += ((s >> (8 - w)) & 1) ? ph : -ph;
    }
    float c, sn; sincosf(0.5f * ang, &sn, &c);
    return make_float2(c, sn);
}
__device__ __forceinline__ float2 phase_e(const float* rp, int blk, int e) {
    float ang = 0.f;
    #pragma unroll
    for (int w = 9; w < 16; w++) {
        float ph = rp[blk * 48 + w * 3 + 1];
        ang += ((e >> (15 - w)) & 1) ? ph : -ph;
    }
    float c, sn; sincosf(0.5f * ang, &sn, &c);
    return make_float2(c, sn);
}

// ---------------- half2 Ry butterfly primitives ----------------

__device__ __forceinline__ u32 hfma2u(u32 a, u32 b, u32 c) {
    return h2u(__hfma2(u2h(a), u2h(b), u2h(c)));
}
__device__ __forceinline__ u32 hmul2u(u32 a, u32 b) {
    return h2u(__hmul2(u2h(a), u2h(b)));
}
__device__ __forceinline__ u32 hswap(u32 v) { return (v >> 16) | (v << 16); }
__device__ __forceinline__ u32 hsplat(float v) { return h2u(__float2half2_rn(v)); }
__device__ __forceinline__ u32 hpack(float lo, float hi) {
    return h2u(__floats2half2_rn(lo, hi));
}

__device__ __forceinline__ void bpairH(u32 c2, u32 s2, u32 ns2,
                                       u32& Lx, u32& Ly, u32& Hx, u32& Hy) {
    u32 ox = hfma2u(c2, Lx, hmul2u(ns2, Hx));
    u32 oy = hfma2u(c2, Ly, hmul2u(ns2, Hy));
    u32 px = hfma2u(c2, Hx, hmul2u(s2,  Lx));
    u32 py = hfma2u(c2, Hy, hmul2u(s2,  Ly));
    Lx = ox; Ly = oy; Hx = px; Hy = py;
}
__device__ __forceinline__ void bshufH(u32 c2, u32 B2, u32& X, u32& Y, int ls) {
    u32 px = __shfl_xor_sync(0xffffffffu, X, ls);
    u32 py = __shfl_xor_sync(0xffffffffu, Y, ls);
    X = hfma2u(c2, X, hmul2u(B2, px));
    Y = hfma2u(c2, Y, hmul2u(B2, py));
}
__device__ __forceinline__ void bpackH(u32 c2, u32 Bp, u32& X, u32& Y) {
    X = hfma2u(c2, X, hmul2u(Bp, hswap(X)));
    Y = hfma2u(c2, Y, hmul2u(Bp, hswap(Y)));
}

// 7-stage embed Ry butterfly. e = 16*t + j (t = lane&7), pack k: j=2k,2k+1.
// ry = 14 floats: (c,s) wires 9..15 at offsets 0..12.
__device__ __forceinline__ void row_butterflyH(const float* ry, u32 Hx[8], u32 Hy[8], int t) {
    { u32 c2=hsplat(ry[6]), s2=hsplat(ry[7]), ns2=hsplat(-ry[7]);   // wire12, e bit3
      #pragma unroll
      for (int k = 0; k < 4; k++) bpairH(c2,s2,ns2, Hx[k],Hy[k], Hx[k+4],Hy[k+4]); }
    { u32 c2=hsplat(ry[8]), s2=hsplat(ry[9]), ns2=hsplat(-ry[9]);   // wire13, e bit2
      bpairH(c2,s2,ns2,Hx[0],Hy[0],Hx[2],Hy[2]); bpairH(c2,s2,ns2,Hx[1],Hy[1],Hx[3],Hy[3]);
      bpairH(c2,s2,ns2,Hx[4],Hy[4],Hx[6],Hy[6]); bpairH(c2,s2,ns2,Hx[5],Hy[5],Hx[7],Hy[7]); }
    { u32 c2=hsplat(ry[10]), s2=hsplat(ry[11]), ns2=hsplat(-ry[11]); // wire14, e bit1
      bpairH(c2,s2,ns2,Hx[0],Hy[0],Hx[1],Hy[1]); bpairH(c2,s2,ns2,Hx[2],Hy[2],Hx[3],Hy[3]);
      bpairH(c2,s2,ns2,Hx[4],Hy[4],Hx[5],Hy[5]); bpairH(c2,s2,ns2,Hx[6],Hy[6],Hx[7],Hy[7]); }
    { u32 c2 = hsplat(ry[12]); u32 Bp = hpack(-ry[13], ry[13]);      // wire15, e bit0
      #pragma unroll
      for (int k = 0; k < 8; k++) bpackH(c2, Bp, Hx[k], Hy[k]); }
    { u32 c2 = hsplat(ry[4]); u32 B2 = hsplat((t&1) ? ry[5] : -ry[5]);  // wire11, bit4
      #pragma unroll
      for (int k = 0; k < 8; k++) bshufH(c2, B2, Hx[k], Hy[k], 1); }
    { u32 c2 = hsplat(ry[2]); u32 B2 = hsplat((t&2) ? ry[3] : -ry[3]);  // wire10, bit5
      #pragma unroll
      for (int k = 0; k < 8; k++) bshufH(c2, B2, Hx[k], Hy[k], 2); }
    { u32 c2 = hsplat(ry[0]); u32 B2 = hsplat((t&4) ? ry[1] : -ry[1]);  // wire9, bit6
      #pragma unroll
      for (int k = 0; k < 8; k++) bshufH(c2, B2, Hx[k], Hy[k], 4); }
}

// 9-stage seq Ry butterfly. s = lane + 32*j, pack k: j=2k (lo), 2k+1 (hi).
// ry = 18 floats: (c,s) wires 0..8 at offsets 0..16.
__device__ __forceinline__ void col_butterflyH(const float* ry, u32 Hx[8], u32 Hy[8], int lane) {
    { u32 c2=hsplat(ry[0]), s2=hsplat(ry[1]), ns2=hsplat(-ry[1]);   // wire0, s bit8
      #pragma unroll
      for (int k = 0; k < 4; k++) bpairH(c2,s2,ns2, Hx[k],Hy[k], Hx[k+4],Hy[k+4]); }
    { u32 c2=hsplat(ry[2]), s2=hsplat(ry[3]), ns2=hsplat(-ry[3]);   // wire1, s bit7
      bpairH(c2,s2,ns2,Hx[0],Hy[0],Hx[2],Hy[2]); bpairH(c2,s2,ns2,Hx[1],Hy[1],Hx[3],Hy[3]);
      bpairH(c2,s2,ns2,Hx[4],Hy[4],Hx[6],Hy[6]); bpairH(c2,s2,ns2,Hx[5],Hy[5],Hx[7],Hy[7]); }
    { u32 c2=hsplat(ry[4]), s2=hsplat(ry[5]), ns2=hsplat(-ry[5]);   // wire2, s bit6
      bpairH(c2,s2,ns2,Hx[0],Hy[0],Hx[1],Hy[1]); bpairH(c2,s2,ns2,Hx[2],Hy[2],Hx[3],Hy[3]);
      bpairH(c2,s2,ns2,Hx[4],Hy[4],Hx[5],Hy[5]); bpairH(c2,s2,ns2,Hx[6],Hy[6],Hx[7],Hy[7]); }
    { u32 c2 = hsplat(ry[6]); u32 Bp = hpack(-ry[7], ry[7]);        // wire3, s bit5
      #pragma unroll
      for (int k = 0; k < 8; k++) bpackH(c2, Bp, Hx[k], Hy[k]); }
    #pragma unroll
    for (int st = 0; st < 5; st++) {                                // wires 4..8
        int ls = 16 >> st;
        const float* p = ry + 8 + st * 2;
        u32 c2 = hsplat(p[0]); u32 B2 = hsplat((lane & ls) ? p[1] : -p[1]);
        #pragma unroll
        for (int k = 0; k < 8; k++) bshufH(c2, B2, Hx[k], Hy[k], ls);
    }
}

// ---------------- embed + D(phi)_1 + B1 emb butterfly (half2) ----------------
// 4096 blocks x 256 threads; block = 32 rows (16 blocks per batch).

__global__ __launch_bounds__(256) void k_embed_row(const int* __restrict__ tokens,
                                                   const float* __restrict__ temb,
                                                   const float* __restrict__ pemb,
                                                   const float* __restrict__ rp) {
    __shared__ __align__(16) float ry[14];
    __shared__ __align__(8) u32 epcH[64], epsH[64];   // half2 emb-phase, idx t*8+k
    __shared__ float2 psrow[32];
    __shared__ float wss[8];
    int tid = threadIdx.x;
    if (tid < 7) {
        float c, sn; sincosf(0.5f * rp[(9 + tid) * 3], &sn, &c);
        ry[2*tid] = c; ry[2*tid+1] = sn;
    }
    if (tid < 64) {
        int e0 = 16 * (tid >> 3) + 2 * (tid & 7);
        float2 A = phase_e(rp, 0, e0), B = phase_e(rp, 0, e0 + 1);
        epcH[tid] = hpack(A.x, B.x);
        epsH[tid] = hpack(A.y, B.y);
    }
    if (tid >= 64 && tid < 96) {
        int r = tid - 64;
        psrow[r] = phase_s(rp, 0, (blockIdx.x * 32 + r) & (NS - 1));
    }
    __syncthreads();
    int warp = tid >> 5, lane = tid & 31, rl = lane >> 3, t = lane & 7;
    int row = blockIdx.x * 32 + warp * 4 + rl;
    int s = row & (NS - 1);
    int tok = tokens[row];
    const float4* te  = (const float4*)(temb + (size_t)tok * NE + 16 * t);
    const float4* pe4 = (const float4*)(pemb + (size_t)s * NE + 16 * t);
    float v[16];
    float ss = 0.f;
    #pragma unroll
    for (int q = 0; q < 4; q++) {
        float4 a = te[q], b = pe4[q];
        float v0 = a.x + b.x, v1 = a.y + b.y, v2 = a.z + b.z, v3 = a.w + b.w;
        ss += v0*v0 + v1*v1 + v2*v2 + v3*v3;
        v[4*q] = v0; v[4*q+1] = v1; v[4*q+2] = v2; v[4*q+3] = v3;
    }
    // x0 store (fp16)
    u32 xh[8];
    #pragma unroll
    for (int k = 0; k < 8; k++) xh[k] = hpack(v[2*k], v[2*k+1]);
    uint4* gx = (uint4*)(g_x0h + (size_t)row * NE + 16 * t);
    gx[0] = make_uint4(xh[0], xh[1], xh[2], xh[3]);
    gx[1] = make_uint4(xh[4], xh[5], xh[6], xh[7]);

    #pragma unroll
    for (int o = 16; o; o >>= 1) ss += __shfl_down_sync(0xffffffffu, ss, o);
    if (lane == 0) wss[warp] = ss;

    // D(phi)_1 in half2: phase = ps[s]*pe[e]
    float2 psv = psrow[warp * 4 + rl];
    u32 a2h = hsplat(psv.x), b2h = hsplat(psv.y), nb2h = hsplat(-psv.y);
    u32 Hx[8], Hy[8];
    #pragma unroll
    for (int k = 0; k < 8; k++) {
        u32 tc = epcH[t*8+k], ts = epsH[t*8+k];
        u32 c1 = hfma2u(a2h, tc, hmul2u(nb2h, ts));
        u32 s1 = hfma2u(b2h, tc, hmul2u(a2h,  ts));
        u32 vh = hpack(v[2*k], v[2*k+1]);
        Hx[k] = hmul2u(vh, c1);
        Hy[k] = hmul2u(vh, s1);
    }

    row_butterflyH(ry, Hx, Hy, t);

    u32 hv[16];
    #pragma unroll
    for (int k = 0; k < 8; k++) {
        hv[2*k]   = __byte_perm(Hx[k], Hy[k], 0x5410);
        hv[2*k+1] = __byte_perm(Hx[k], Hy[k], 0x7632);
    }
    uint4* dst = (uint4*)(g_state + (size_t)row * NE + 16 * t);
    #pragma unroll
    for (int q = 0; q < 4; q++)
        dst[q] = make_uint4(hv[4*q], hv[4*q+1], hv[4*q+2], hv[4*q+3]);

    __syncthreads();
    if (tid == 0) {
        float tot = 0.f;
        #pragma unroll
        for (int q = 0; q < 8; q++) tot += wss[q];
        g_n0p[blockIdx.x] = tot;      // blockIdx = b*16 + grp
    }
}

// ---------------- colA: A1 + perm + residual + D(phi)_2 + A2 (half2) -------
// 2048 blocks x 512 threads; CTA = batch b, columns {c0..c0+7} U {120-c0..127-c0}.

__global__ __launch_bounds__(512) void k_colA(const float* __restrict__ rp) {
    __shared__ __align__(16) float ryA[18], ryB[18];
    __shared__ __align__(8) u32 tscH[256], tssH[256];   // half2 seq-phase blk2
    __shared__ __align__(16) u32 tin[16 * 513];
    __shared__ float scol[16];
    __shared__ float ssacc;
    __shared__ float s_inv0;
    __shared__ float2 pe2t[16];
    float* tf = reinterpret_cast<float*>(tin);

    int tid = threadIdx.x;
    int b = blockIdx.x >> 3, grp = blockIdx.x & 7, c0 = grp * 8;
    if (tid < 18) {
        int blk = tid / 9, wi = tid % 9;
        float c, sn; sincosf(0.5f * rp[blk * 48 + wi * 3], &sn, &c);
        if (blk == 0) { ryA[2*wi] = c; ryA[2*wi+1] = sn; }
        else          { ryB[2*wi] = c; ryB[2*wi+1] = sn; }
    }
    if (tid < 16)  scol[tid] = 0.f;
    if (tid == 0)  ssacc = 0.f;
    if (tid < 256) {
        int k = tid >> 5, l = tid & 31;
        float2 A = phase_s(rp, 1, l + 64*k), B = phase_s(rp, 1, l + 64*k + 32);
        tscH[tid] = hpack(A.x, B.x);
        tssH[tid] = hpack(A.y, B.y);
    }
    if (tid >= 256 && tid < 272) {
        int i2 = tid - 256;
        int gc = (i2 < 8) ? (c0 + i2) : (112 - c0 + i2);
        pe2t[i2] = phase_e(rp, 1, gc);
    }
    if (tid == 272) {
        float t0 = 0.f;
        #pragma unroll
        for (int j = 0; j < 16; j++) t0 += g_n0p[b * 16 + j];
        s_inv0 = rsqrtf(t0);
    }

    int i = tid & 7, strip = (tid >> 3) & 1, rb = tid >> 4;
    int gcolL = strip ? (120 - c0 + i) : (c0 + i);
    int cidxL = strip * 8 + i;
    int srcCol = gcolL ^ (gcolL >> 1);
    const u32* st = g_state + (size_t)b * NDIM;
    #pragma unroll
    for (int it = 0; it < 16; it++) {
        int r = rb + it * 32;
        tin[cidxL * 513 + r] = st[r * NE + srcCol];
    }
    __syncthreads();
    float inv0 = s_inv0;
    int w = tid >> 5, lane = tid & 31;
    u32 Hx[8], Hy[8];
    #pragma unroll
    for (int k = 0; k < 8; k++) {
        u32 w0 = tin[w * 513 + lane + 64*k];
        u32 w1 = tin[w * 513 + lane + 64*k + 32];
        Hx[k] = __byte_perm(w0, w1, 0x5410);
        Hy[k] = __byte_perm(w0, w1, 0x7632);
    }
    __syncthreads();

    col_butterflyH(ryA, Hx, Hy, lane);

    // CNOT perm + |.|*inv0 scatter (R9-verified GF(2) addressing)
    int colw = (w < 8) ? (c0 + w) : (112 - c0 + w);
    {
        int pxl = lane ^ (lane >> 1); pxl ^= pxl >> 2; pxl ^= pxl >> 4;
        int parl = __popc(lane) & 1;
        int lowb = colw & 1;
        int c_sel0 = (parl ? (15 - w) : w) * 513;
        int c_sel1 = (parl ? w : (15 - w)) * 513;
        int sel0 = pxl ^ ((lowb ^ parl) << 8);
        int sel1 = pxl ^ ((lowb ^ parl ^ 1) << 8);
        #pragma unroll
        for (int k = 0; k < 8; k++) {
            u32 m2 = hfma2u(Hx[k], Hx[k], hmul2u(Hy[k], Hy[k]));
            float2 mf = h22f2(m2);
            float mag0 = sqrtf(mf.x) * inv0;
            float mag1 = sqrtf(mf.y) * inv0;
            const int PXC0 = px9c(64 * k);
            const int PXC1 = px9c(64 * k + 32);
            const int P0 = __popc(k) & 1;
            int addr0 = (P0 ? c_sel1 : c_sel0) + ((P0 ? sel1 : sel0) ^ PXC0);
            int addr1 = (P0 ? c_sel0 : c_sel1) + ((P0 ? sel0 : sel1) ^ PXC1);
            tf[addr0] = mag0;
            tf[addr1] = mag1;
        }
    }
    __syncthreads();

    // residual + stats, in place (fp32)
    const __half* x0p = g_x0h + (size_t)b * NDIM;
    float cs = 0.f, sq = 0.f;
    #pragma unroll
    for (int it = 0; it < 16; it++) {
        int r = rb + it * 32;
        float vv = tf[cidxL * 513 + r] + __half2float(x0p[r * NE + gcolL]);
        tf[cidxL * 513 + r] = vv;
        cs += vv;  sq += vv * vv;
    }
    atomicAdd(&scol[cidxL], cs);
    #pragma unroll
    for (int o = 16; o; o >>= 1) sq += __shfl_down_sync(0xffffffffu, sq, o);
    if (lane == 0) atomicAdd(&ssacc, sq);
    __syncthreads();

    if (tid == 0) g_n1p[blockIdx.x] = ssacc;          // blockIdx = b*8 + grp
    if (tid < 16) {
        int gc = (tid < 8) ? (c0 + tid) : (112 - c0 + tid);
        g_mA[b * NE + gc] = scol[tid];
    }

    // reload x1 + D(phi)_2 in half2: phase = ps2[s] * pe2[colw]
    u32 pa2 = hsplat(pe2t[w].x), pb2 = hsplat(pe2t[w].y), pnb2 = hsplat(-pe2t[w].y);
    #pragma unroll
    for (int k = 0; k < 8; k++) {
        float a = tf[w * 513 + lane + 64*k];
        float c = tf[w * 513 + lane + 64*k + 32];
        u32 x1h = hpack(a, c);
        u32 tc = tscH[k*32 + lane], ts = tssH[k*32 + lane];
        u32 c12 = hfma2u(pa2, tc, hmul2u(pnb2, ts));
        u32 s12 = hfma2u(pb2, tc, hmul2u(pa2,  ts));
        Hx[k] = hmul2u(x1h, c12);
        Hy[k] = hmul2u(x1h, s12);
    }
    __syncthreads();

    col_butterflyH(ryB, Hx, Hy, lane);

    #pragma unroll
    for (int k = 0; k < 8; k++) {
        tin[w * 513 + lane + 64*k]      = __byte_perm(Hx[k], Hy[k], 0x5410);
        tin[w * 513 + lane + 64*k + 32] = __byte_perm(Hx[k], Hy[k], 0x7632);
    }
    __syncthreads();
    u32* yp = g_state + (size_t)b * NDIM;
    #pragma unroll
    for (int it = 0; it < 16; it++) {
        int r = rb + it * 32;
        yp[r * NE + gcolL] = tin[cidxL * 513 + r];
    }
}

// ---------------- rowB: B2 emb butterfly (half2) + column-sum reduction ----
// 4096 blocks x 256 threads; 16 blocks per batch.

__global__ __launch_bounds__(256) void k_rowB(const float* __restrict__ rp) {
    __shared__ __align__(16) u32 srow[32][68];   // 64 half2 words + pad
    __shared__ __align__(16) float ry[14];
    __shared__ float sred[128];
    __shared__ float s_inv1;
    int tid = threadIdx.x;
    int b = blockIdx.x >> 4;
    if (tid < 7) {
        float c, sn; sincosf(0.5f * rp[48 + (9 + tid) * 3], &sn, &c);
        ry[2*tid] = c; ry[2*tid+1] = sn;
    }
    if (tid == 32) {
        float t1 = 0.f;
        #pragma unroll
        for (int j = 0; j < 8; j++) t1 += g_n1p[b * 8 + j];
        s_inv1 = rsqrtf(t1);
    }
    __syncthreads();
    int warp = tid >> 5, lane = tid & 31, rl = lane >> 3, t = lane & 7;
    int rls = warp * 4 + rl;
    int row = blockIdx.x * 32 + rls;
    const uint4* src = (const uint4*)(g_state + (size_t)row * NE + 16 * t);
    u32 Hx[8], Hy[8];
    #pragma unroll
    for (int q = 0; q < 4; q++) {
        uint4 U = src[q];
        Hx[2*q]   = __byte_perm(U.x, U.y, 0x5410);
        Hy[2*q]   = __byte_perm(U.x, U.y, 0x7632);
        Hx[2*q+1] = __byte_perm(U.z, U.w, 0x5410);
        Hy[2*q+1] = __byte_perm(U.z, U.w, 0x7632);
    }

    row_butterflyH(ry, Hx, Hy, t);

    u32 hm[8];
    #pragma unroll
    for (int k = 0; k < 8; k++) {
        u32 msq = hfma2u(Hx[k], Hx[k], hmul2u(Hy[k], Hy[k]));
        hm[k] = h2u(h2sqrt(u2h(msq)));
    }
    uint4* wp = (uint4*)&srow[rls][8 * t];
    wp[0] = make_uint4(hm[0], hm[1], hm[2], hm[3]);
    wp[1] = make_uint4(hm[4], hm[5], hm[6], hm[7]);
    __syncthreads();

    // reduction: es = (e^(e>>1)) ^ 64*par(s); par(s)=par(sbase)^half^par(q)
    int e = tid & 127, half = tid >> 7;
    int sbase = (blockIdx.x * 32) & (NS - 1);
    int ebase = e ^ (e >> 1);
    int p0 = (__popc(sbase) ^ half) & 1;
    int esA = ebase ^ (p0 << 6);
    int esB = esA ^ 64;
    const __half* srh = (const __half*)srow;
    float acc = 0.f;
    #pragma unroll
    for (int q = 0; q < 16; q++) {
        int r = half * 16 + q;
        int es = ((0x6996 >> q) & 1) ? esB : esA;
        acc += __half2float(srh[r * 136 + es]);
    }
    if (half == 1) sred[e] = acc;
    __syncthreads();
    if (half == 0) g_mB[blockIdx.x * NE + e] = (acc + sred[e]) * s_inv1;
}

// ---------------- final: assemble mean + linear + classifier ----------------

__global__ void k_final(const float* __restrict__ ffw, const float* __restrict__ ffb,
                        const float* __restrict__ clsw, float* __restrict__ out) {
    int b = blockIdx.x, tid = threadIdx.x;
    __shared__ float mm[128], f[128];
    float m = g_mA[b * NE + tid];
    #pragma unroll
    for (int i = 0; i < 16; i++) m += g_mB[(b * 16 + i) * NE + tid];
    mm[tid] = m * (1.f / 512.f);
    __syncthreads();
    float acc = ffb[tid];
    #pragma unroll 8
    for (int e = 0; e < 128; e++) acc += mm[e] * ffw[tid * 128 + e];
    f[tid] = acc;
    __syncthreads();
    if (tid < 4) {
        float o = 0.f;
        #pragma unroll 8
        for (int j = 0; j < 128; j++) o += f[j] * clsw[tid * 128 + j];
        out[b * 4 + tid] = o;
    }
}

// ---------------- launch ----------------

extern "C" void kernel_launch(void* const* d_in, const int* in_sizes, int n_in,
                              void* d_out, int out_size) {
    const int*   tokens = (const int*)  d_in[0];
    const float* temb   = (const float*)d_in[1];
    const float* pemb   = (const float*)d_in[2];
    const float* rotp   = (const float*)d_in[3];
    const float* ffw    = (const float*)d_in[4];
    const float* ffb    = (const float*)d_in[5];
    const float* clsw   = (const float*)d_in[6];
    float* out = (float*)d_out;

    k_embed_row<<<NB * NS / 32, 256>>>(tokens, temb, pemb, rotp);
    k_colA<<<NB * 8, 512>>>(rotp);
    k_rowB<<<NB * NS / 32, 256>>>(rotp);
    k_final<<<NB, 128>>>(ffw, ffb, clsw, out);
}

// round 12
// speedup vs baseline: 3.4552x; 1.0176x over previous
#include <cuda_runtime.h>
#include <cuda_fp16.h>
#include <cstdint>

// ----------------------------------------------------------------------------
// QFNet classifier, round 12 (= round 11 resubmit after infra failure):
//  - classifier collapsed to W2 = clsw@ffw (4x128, computed once in k_w2);
//    k_final is a coalesced 16-partial reduction + 4x128 shuffle dot
//  - half2 butterflies everywhere, GF(2) scatter addressing, atomic-free
//    partials, no init kernel (all R9/R10-verified)
// ----------------------------------------------------------------------------

#define NB   256
#define NS   512
#define NE   128
#define NDIM 65536

typedef unsigned long long u64;
typedef unsigned int u32;

__device__ __align__(16) __half g_x0h[NB * NDIM];   // x0 fp16
__device__ u32    g_state[NB * NDIM];               // half2(re,im) per element
__device__ float  g_n0p[NB * 16];                   // embed norm0 partials
__device__ float  g_n1p[NB * 8];                    // colA norm1 partials
__device__ float  g_mA[NB * NE];                    // colA column sums (written)
__device__ float  g_mB[NB * 16 * NE];               // rowB per-block column sums
__device__ float  g_W2[4 * NE];                     // clsw @ ffw
__device__ float  g_b2[4];                          // clsw @ ffb

// ---------------- helpers ----------------

__device__ __forceinline__ u32 h2u(__half2 h) { return *reinterpret_cast<u32*>(&h); }
__device__ __forceinline__ __half2 u2h(u32 u) { return *reinterpret_cast<__half2*>(&u); }
__device__ __forceinline__ float2 h22f2(u32 u) { return __half22float2(u2h(u)); }

// compile-time 9-bit prefix-xor (from MSB) transform
__device__ __forceinline__ constexpr int px9c(int x) {
    x ^= x >> 1; x ^= x >> 2; x ^= x >> 4; x ^= x >> 8; return x;
}

// separable D(phi) phase factors, computed from rot_params directly
__device__ __forceinline__ float2 phase_s(const float* rp, int blk, int s) {
    float ang = 0.f;
    #pragma unroll
    for (int w = 0; w < 9; w++) {
        float ph = rp[blk * 48 + w * 3 + 1];
        ang += ((s >> (8 - w)) & 1) ? ph : -ph;
    }
    float c, sn; sincosf(0.5f * ang, &sn, &c);
    return make_float2(c, sn);
}
__device__ __forceinline__ float2 phase_e(const float* rp, int blk, int e) {
    float ang = 0.f;
    #pragma unroll
    for (int w = 9; w < 16; w++) {
        float ph = rp[blk * 48 + w * 3 + 1];
        ang += ((e >> (15 - w)) & 1) ? ph : -ph;
    }
    float c, sn; sincosf(0.5f * ang, &sn, &c);
    return make_float2(c, sn);
}

// ---------------- half2 Ry butterfly primitives ----------------

__device__ __forceinline__ u32 hfma2u(u32 a, u32 b, u32 c) {
    return h2u(__hfma2(u2h(a), u2h(b), u2h(c)));
}
__device__ __forceinline__ u32 hmul2u(u32 a, u32 b) {
    return h2u(__hmul2(u2h(a), u2h(b)));
}
__device__ __forceinline__ u32 hswap(u32 v) { return (v >> 16) | (v << 16); }
__device__ __forceinline__ u32 hsplat(float v) { return h2u(__float2half2_rn(v)); }
__device__ __forceinline__ u32 hpack(float lo, float hi) {
    return h2u(__floats2half2_rn(lo, hi));
}

__device__ __forceinline__ void bpairH(u32 c2, u32 s2, u32 ns2,
                                       u32& Lx, u32& Ly, u32& Hx, u32& Hy) {
    u32 ox = hfma2u(c2, Lx, hmul2u(ns2, Hx));
    u32 oy = hfma2u(c2, Ly, hmul2u(ns2, Hy));
    u32 px = hfma2u(c2, Hx, hmul2u(s2,  Lx));
    u32 py = hfma2u(c2, Hy, hmul2u(s2,  Ly));
    Lx = ox; Ly = oy; Hx = px; Hy = py;
}
__device__ __forceinline__ void bshufH(u32 c2, u32 B2, u32& X, u32& Y, int ls) {
    u32 px = __shfl_xor_sync(0xffffffffu, X, ls);
    u32 py = __shfl_xor_sync(0xffffffffu, Y, ls);
    X = hfma2u(c2, X, hmul2u(B2, px));
    Y = hfma2u(c2, Y, hmul2u(B2, py));
}
__device__ __forceinline__ void bpackH(u32 c2, u32 Bp, u32& X, u32& Y) {
    X = hfma2u(c2, X, hmul2u(Bp, hswap(X)));
    Y = hfma2u(c2, Y, hmul2u(Bp, hswap(Y)));
}

// 7-stage embed Ry butterfly. e = 16*t + j (t = lane&7), pack k: j=2k,2k+1.
// ry = 14 floats: (c,s) wires 9..15 at offsets 0..12.
__device__ __forceinline__ void row_butterflyH(const float* ry, u32 Hx[8], u32 Hy[8], int t) {
    { u32 c2=hsplat(ry[6]), s2=hsplat(ry[7]), ns2=hsplat(-ry[7]);   // wire12, e bit3
      #pragma unroll
      for (int k = 0; k < 4; k++) bpairH(c2,s2,ns2, Hx[k],Hy[k], Hx[k+4],Hy[k+4]); }
    { u32 c2=hsplat(ry[8]), s2=hsplat(ry[9]), ns2=hsplat(-ry[9]);   // wire13, e bit2
      bpairH(c2,s2,ns2,Hx[0],Hy[0],Hx[2],Hy[2]); bpairH(c2,s2,ns2,Hx[1],Hy[1],Hx[3],Hy[3]);
      bpairH(c2,s2,ns2,Hx[4],Hy[4],Hx[6],Hy[6]); bpairH(c2,s2,ns2,Hx[5],Hy[5],Hx[7],Hy[7]); }
    { u32 c2=hsplat(ry[10]), s2=hsplat(ry[11]), ns2=hsplat(-ry[11]); // wire14, e bit1
      bpairH(c2,s2,ns2,Hx[0],Hy[0],Hx[1],Hy[1]); bpairH(c2,s2,ns2,Hx[2],Hy[2],Hx[3],Hy[3]);
      bpairH(c2,s2,ns2,Hx[4],Hy[4],Hx[5],Hy[5]); bpairH(c2,s2,ns2,Hx[6],Hy[6],Hx[7],Hy[7]); }
    { u32 c2 = hsplat(ry[12]); u32 Bp = hpack(-ry[13], ry[13]);      // wire15, e bit0
      #pragma unroll
      for (int k = 0; k < 8; k++) bpackH(c2, Bp, Hx[k], Hy[k]); }
    { u32 c2 = hsplat(ry[4]); u32 B2 = hsplat((t&1) ? ry[5] : -ry[5]);  // wire11, bit4
      #pragma unroll
      for (int k = 0; k < 8; k++) bshufH(c2, B2, Hx[k], Hy[k], 1); }
    { u32 c2 = hsplat(ry[2]); u32 B2 = hsplat((t&2) ? ry[3] : -ry[3]);  // wire10, bit5
      #pragma unroll
      for (int k = 0; k < 8; k++) bshufH(c2, B2, Hx[k], Hy[k], 2); }
    { u32 c2 = hsplat(ry[0]); u32 B2 = hsplat((t&4) ? ry[1] : -ry[1]);  // wire9, bit6
      #pragma unroll
      for (int k = 0; k < 8; k++) bshufH(c2, B2, Hx[k], Hy[k], 4); }
}

// 9-stage seq Ry butterfly. s = lane + 32*j, pack k: j=2k (lo), 2k+1 (hi).
// ry = 18 floats: (c,s) wires 0..8 at offsets 0..16.
__device__ __forceinline__ void col_butterflyH(const float* ry, u32 Hx[8], u32 Hy[8], int lane) {
    { u32 c2=hsplat(ry[0]), s2=hsplat(ry[1]), ns2=hsplat(-ry[1]);   // wire0, s bit8
      #pragma unroll
      for (int k = 0; k < 4; k++) bpairH(c2,s2,ns2, Hx[k],Hy[k], Hx[k+4],Hy[k+4]); }
    { u32 c2=hsplat(ry[2]), s2=hsplat(ry[3]), ns2=hsplat(-ry[3]);   // wire1, s bit7
      bpairH(c2,s2,ns2,Hx[0],Hy[0],Hx[2],Hy[2]); bpairH(c2,s2,ns2,Hx[1],Hy[1],Hx[3],Hy[3]);
      bpairH(c2,s2,ns2,Hx[4],Hy[4],Hx[6],Hy[6]); bpairH(c2,s2,ns2,Hx[5],Hy[5],Hx[7],Hy[7]); }
    { u32 c2=hsplat(ry[4]), s2=hsplat(ry[5]), ns2=hsplat(-ry[5]);   // wire2, s bit6
      bpairH(c2,s2,ns2,Hx[0],Hy[0],Hx[1],Hy[1]); bpairH(c2,s2,ns2,Hx[2],Hy[2],Hx[3],Hy[3]);
      bpairH(c2,s2,ns2,Hx[4],Hy[4],Hx[5],Hy[5]); bpairH(c2,s2,ns2,Hx[6],Hy[6],Hx[7],Hy[7]); }
    { u32 c2 = hsplat(ry[6]); u32 Bp = hpack(-ry[7], ry[7]);        // wire3, s bit5
      #pragma unroll
      for (int k = 0; k < 8; k++) bpackH(c2, Bp, Hx[k], Hy[k]); }
    #pragma unroll
    for (int st = 0; st < 5; st++) {                                // wires 4..8
        int ls = 16 >> st;
        const float* p = ry + 8 + st * 2;
        u32 c2 = hsplat(p[0]); u32 B2 = hsplat((lane & ls) ? p[1] : -p[1]);
        #pragma unroll
        for (int k = 0; k < 8; k++) bshufH(c2, B2, Hx[k], Hy[k], ls);
    }
}

// ---------------- embed + D(phi)_1 + B1 emb butterfly (half2) ----------------

__global__ __launch_bounds__(256) void k_embed_row(const int* __restrict__ tokens,
                                                   const float* __restrict__ temb,
                                                   const float* __restrict__ pemb,
                                                   const float* __restrict__ rp) {
    __shared__ __align__(16) float ry[14];
    __shared__ __align__(8) u32 epcH[64], epsH[64];   // half2 emb-phase, idx t*8+k
    __shared__ float2 psrow[32];
    __shared__ float wss[8];
    int tid = threadIdx.x;
    if (tid < 7) {
        float c, sn; sincosf(0.5f * rp[(9 + tid) * 3], &sn, &c);
        ry[2*tid] = c; ry[2*tid+1] = sn;
    }
    if (tid < 64) {
        int e0 = 16 * (tid >> 3) + 2 * (tid & 7);
        float2 A = phase_e(rp, 0, e0), B = phase_e(rp, 0, e0 + 1);
        epcH[tid] = hpack(A.x, B.x);
        epsH[tid] = hpack(A.y, B.y);
    }
    if (tid >= 64 && tid < 96) {
        int r = tid - 64;
        psrow[r] = phase_s(rp, 0, (blockIdx.x * 32 + r) & (NS - 1));
    }
    __syncthreads();
    int warp = tid >> 5, lane = tid & 31, rl = lane >> 3, t = lane & 7;
    int row = blockIdx.x * 32 + warp * 4 + rl;
    int s = row & (NS - 1);
    int tok = tokens[row];
    const float4* te  = (const float4*)(temb + (size_t)tok * NE + 16 * t);
    const float4* pe4 = (const float4*)(pemb + (size_t)s * NE + 16 * t);
    float v[16];
    float ss = 0.f;
    #pragma unroll
    for (int q = 0; q < 4; q++) {
        float4 a = te[q], b = pe4[q];
        float v0 = a.x + b.x, v1 = a.y + b.y, v2 = a.z + b.z, v3 = a.w + b.w;
        ss += v0*v0 + v1*v1 + v2*v2 + v3*v3;
        v[4*q] = v0; v[4*q+1] = v1; v[4*q+2] = v2; v[4*q+3] = v3;
    }
    // x0 store (fp16)
    u32 xh[8];
    #pragma unroll
    for (int k = 0; k < 8; k++) xh[k] = hpack(v[2*k], v[2*k+1]);
    uint4* gx = (uint4*)(g_x0h + (size_t)row * NE + 16 * t);
    gx[0] = make_uint4(xh[0], xh[1], xh[2], xh[3]);
    gx[1] = make_uint4(xh[4], xh[5], xh[6], xh[7]);

    #pragma unroll
    for (int o = 16; o; o >>= 1) ss += __shfl_down_sync(0xffffffffu, ss, o);
    if (lane == 0) wss[warp] = ss;

    // D(phi)_1 in half2: phase = ps[s]*pe[e]
    float2 psv = psrow[warp * 4 + rl];
    u32 a2h = hsplat(psv.x), b2h = hsplat(psv.y), nb2h = hsplat(-psv.y);
    u32 Hx[8], Hy[8];
    #pragma unroll
    for (int k = 0; k < 8; k++) {
        u32 tc = epcH[t*8+k], ts = epsH[t*8+k];
        u32 c1 = hfma2u(a2h, tc, hmul2u(nb2h, ts));
        u32 s1 = hfma2u(b2h, tc, hmul2u(a2h,  ts));
        u32 vh = hpack(v[2*k], v[2*k+1]);
        Hx[k] = hmul2u(vh, c1);
        Hy[k] = hmul2u(vh, s1);
    }

    row_butterflyH(ry, Hx, Hy, t);

    u32 hv[16];
    #pragma unroll
    for (int k = 0; k < 8; k++) {
        hv[2*k]   = __byte_perm(Hx[k], Hy[k], 0x5410);
        hv[2*k+1] = __byte_perm(Hx[k], Hy[k], 0x7632);
    }
    uint4* dst = (uint4*)(g_state + (size_t)row * NE + 16 * t);
    #pragma unroll
    for (int q = 0; q < 4; q++)
        dst[q] = make_uint4(hv[4*q], hv[4*q+1], hv[4*q+2], hv[4*q+3]);

    __syncthreads();
    if (tid == 0) {
        float tot = 0.f;
        #pragma unroll
        for (int q = 0; q < 8; q++) tot += wss[q];
        g_n0p[blockIdx.x] = tot;      // blockIdx = b*16 + grp
    }
}

// ---------------- colA: A1 + perm + residual + D(phi)_2 + A2 (half2) -------

__global__ __launch_bounds__(512) void k_colA(const float* __restrict__ rp) {
    __shared__ __align__(16) float ryA[18], ryB[18];
    __shared__ __align__(8) u32 tscH[256], tssH[256];   // half2 seq-phase blk2
    __shared__ __align__(16) u32 tin[16 * 513];
    __shared__ float scol[16];
    __shared__ float ssacc;
    __shared__ float s_inv0;
    __shared__ float2 pe2t[16];
    float* tf = reinterpret_cast<float*>(tin);

    int tid = threadIdx.x;
    int b = blockIdx.x >> 3, grp = blockIdx.x & 7, c0 = grp * 8;
    if (tid < 18) {
        int blk = tid / 9, wi = tid % 9;
        float c, sn; sincosf(0.5f * rp[blk * 48 + wi * 3], &sn, &c);
        if (blk == 0) { ryA[2*wi] = c; ryA[2*wi+1] = sn; }
        else          { ryB[2*wi] = c; ryB[2*wi+1] = sn; }
    }
    if (tid < 16)  scol[tid] = 0.f;
    if (tid == 0)  ssacc = 0.f;
    if (tid < 256) {
        int k = tid >> 5, l = tid & 31;
        float2 A = phase_s(rp, 1, l + 64*k), B = phase_s(rp, 1, l + 64*k + 32);
        tscH[tid] = hpack(A.x, B.x);
        tssH[tid] = hpack(A.y, B.y);
    }
    if (tid >= 256 && tid < 272) {
        int i2 = tid - 256;
        int gc = (i2 < 8) ? (c0 + i2) : (112 - c0 + i2);
        pe2t[i2] = phase_e(rp, 1, gc);
    }
    if (tid == 272) {
        float t0 = 0.f;
        #pragma unroll
        for (int j = 0; j < 16; j++) t0 += g_n0p[b * 16 + j];
        s_inv0 = rsqrtf(t0);
    }

    int i = tid & 7, strip = (tid >> 3) & 1, rb = tid >> 4;
    int gcolL = strip ? (120 - c0 + i) : (c0 + i);
    int cidxL = strip * 8 + i;
    int srcCol = gcolL ^ (gcolL >> 1);
    const u32* st = g_state + (size_t)b * NDIM;
    #pragma unroll
    for (int it = 0; it < 16; it++) {
        int r = rb + it * 32;
        tin[cidxL * 513 + r] = st[r * NE + srcCol];
    }
    __syncthreads();
    float inv0 = s_inv0;
    int w = tid >> 5, lane = tid & 31;
    u32 Hx[8], Hy[8];
    #pragma unroll
    for (int k = 0; k < 8; k++) {
        u32 w0 = tin[w * 513 + lane + 64*k];
        u32 w1 = tin[w * 513 + lane + 64*k + 32];
        Hx[k] = __byte_perm(w0, w1, 0x5410);
        Hy[k] = __byte_perm(w0, w1, 0x7632);
    }
    __syncthreads();

    col_butterflyH(ryA, Hx, Hy, lane);

    // CNOT perm + |.|*inv0 scatter (R9-verified GF(2) addressing)
    int colw = (w < 8) ? (c0 + w) : (112 - c0 + w);
    {
        int pxl = lane ^ (lane >> 1); pxl ^= pxl >> 2; pxl ^= pxl >> 4;
        int parl = __popc(lane) & 1;
        int lowb = colw & 1;
        int c_sel0 = (parl ? (15 - w) : w) * 513;
        int c_sel1 = (parl ? w : (15 - w)) * 513;
        int sel0 = pxl ^ ((lowb ^ parl) << 8);
        int sel1 = pxl ^ ((lowb ^ parl ^ 1) << 8);
        #pragma unroll
        for (int k = 0; k < 8; k++) {
            u32 m2 = hfma2u(Hx[k], Hx[k], hmul2u(Hy[k], Hy[k]));
            float2 mf = h22f2(m2);
            float mag0 = sqrtf(mf.x) * inv0;
            float mag1 = sqrtf(mf.y) * inv0;
            const int PXC0 = px9c(64 * k);
            const int PXC1 = px9c(64 * k + 32);
            const int P0 = __popc(k) & 1;
            int addr0 = (P0 ? c_sel1 : c_sel0) + ((P0 ? sel1 : sel0) ^ PXC0);
            int addr1 = (P0 ? c_sel0 : c_sel1) + ((P0 ? sel0 : sel1) ^ PXC1);
            tf[addr0] = mag0;
            tf[addr1] = mag1;
        }
    }
    __syncthreads();

    // residual + stats, in place (fp32)
    const __half* x0p = g_x0h + (size_t)b * NDIM;
    float cs = 0.f, sq = 0.f;
    #pragma unroll
    for (int it = 0; it < 16; it++) {
        int r = rb + it * 32;
        float vv = tf[cidxL * 513 + r] + __half2float(x0p[r * NE + gcolL]);
        tf[cidxL * 513 + r] = vv;
        cs += vv;  sq += vv * vv;
    }
    atomicAdd(&scol[cidxL], cs);
    #pragma unroll
    for (int o = 16; o; o >>= 1) sq += __shfl_down_sync(0xffffffffu, sq, o);
    if (lane == 0) atomicAdd(&ssacc, sq);
    __syncthreads();

    if (tid == 0) g_n1p[blockIdx.x] = ssacc;          // blockIdx = b*8 + grp
    if (tid < 16) {
        int gc = (tid < 8) ? (c0 + tid) : (112 - c0 + tid);
        g_mA[b * NE + gc] = scol[tid];
    }

    // reload x1 + D(phi)_2 in half2: phase = ps2[s] * pe2[colw]
    u32 pa2 = hsplat(pe2t[w].x), pb2 = hsplat(pe2t[w].y), pnb2 = hsplat(-pe2t[w].y);
    #pragma unroll
    for (int k = 0; k < 8; k++) {
        float a = tf[w * 513 + lane + 64*k];
        float c = tf[w * 513 + lane + 64*k + 32];
        u32 x1h = hpack(a, c);
        u32 tc = tscH[k*32 + lane], ts = tssH[k*32 + lane];
        u32 c12 = hfma2u(pa2, tc, hmul2u(pnb2, ts));
        u32 s12 = hfma2u(pb2, tc, hmul2u(pa2,  ts));
        Hx[k] = hmul2u(x1h, c12);
        Hy[k] = hmul2u(x1h, s12);
    }
    __syncthreads();

    col_butterflyH(ryB, Hx, Hy, lane);

    #pragma unroll
    for (int k = 0; k < 8; k++) {
        tin[w * 513 + lane + 64*k]      = __byte_perm(Hx[k], Hy[k], 0x5410);
        tin[w * 513 + lane + 64*k + 32] = __byte_perm(Hx[k], Hy[k], 0x7632);
    }
    __syncthreads();
    u32* yp = g_state + (size_t)b * NDIM;
    #pragma unroll
    for (int it = 0; it < 16; it++) {
        int r = rb + it * 32;
        yp[r * NE + gcolL] = tin[cidxL * 513 + r];
    }
}

// ---------------- rowB: B2 emb butterfly (half2) + column-sum reduction ----

__global__ __launch_bounds__(256) void k_rowB(const float* __restrict__ rp) {
    __shared__ __align__(16) u32 srow[32][68];   // 64 half2 words + pad
    __shared__ __align__(16) float ry[14];
    __shared__ float sred[128];
    __shared__ float s_inv1;
    int tid = threadIdx.x;
    int b = blockIdx.x >> 4;
    if (tid < 7) {
        float c, sn; sincosf(0.5f * rp[48 + (9 + tid) * 3], &sn, &c);
        ry[2*tid] = c; ry[2*tid+1] = sn;
    }
    if (tid == 32) {
        float t1 = 0.f;
        #pragma unroll
        for (int j = 0; j < 8; j++) t1 += g_n1p[b * 8 + j];
        s_inv1 = rsqrtf(t1);
    }
    __syncthreads();
    int warp = tid >> 5, lane = tid & 31, rl = lane >> 3, t = lane & 7;
    int rls = warp * 4 + rl;
    int row = blockIdx.x * 32 + rls;
    const uint4* src = (const uint4*)(g_state + (size_t)row * NE + 16 * t);
    u32 Hx[8], Hy[8];
    #pragma unroll
    for (int q = 0; q < 4; q++) {
        uint4 U = src[q];
        Hx[2*q]   = __byte_perm(U.x, U.y, 0x5410);
        Hy[2*q]   = __byte_perm(U.x, U.y, 0x7632);
        Hx[2*q+1] = __byte_perm(U.z, U.w, 0x5410);
        Hy[2*q+1] = __byte_perm(U.z, U.w, 0x7632);
    }

    row_butterflyH(ry, Hx, Hy, t);

    u32 hm[8];
    #pragma unroll
    for (int k = 0; k < 8; k++) {
        u32 msq = hfma2u(Hx[k], Hx[k], hmul2u(Hy[k], Hy[k]));
        hm[k] = h2u(h2sqrt(u2h(msq)));
    }
    uint4* wp = (uint4*)&srow[rls][8 * t];
    wp[0] = make_uint4(hm[0], hm[1], hm[2], hm[3]);
    wp[1] = make_uint4(hm[4], hm[5], hm[6], hm[7]);
    __syncthreads();

    // reduction: es = (e^(e>>1)) ^ 64*par(s); par(s)=par(sbase)^half^par(q)
    int e = tid & 127, half = tid >> 7;
    int sbase = (blockIdx.x * 32) & (NS - 1);
    int ebase = e ^ (e >> 1);
    int p0 = (__popc(sbase) ^ half) & 1;
    int esA = ebase ^ (p0 << 6);
    int esB = esA ^ 64;
    const __half* srh = (const __half*)srow;
    float acc = 0.f;
    #pragma unroll
    for (int q = 0; q < 16; q++) {
        int r = half * 16 + q;
        int es = ((0x6996 >> q) & 1) ? esB : esA;
        acc += __half2float(srh[r * 136 + es]);
    }
    if (half == 1) sred[e] = acc;
    __syncthreads();
    if (half == 0) g_mB[blockIdx.x * NE + e] = (acc + sred[e]) * s_inv1;
}

// ---------------- W2 = clsw @ ffw (4x128), b2 = clsw @ ffb ----------------

__global__ __launch_bounds__(128) void k_w2(const float* __restrict__ ffw,
                                            const float* __restrict__ ffb,
                                            const float* __restrict__ clsw) {
    int c = blockIdx.x, e = threadIdx.x;      // 4 blocks x 128 threads
    float acc = 0.f;
    #pragma unroll 4
    for (int j = 0; j < 128; j++) acc += clsw[c * 128 + j] * ffw[j * 128 + e];
    g_W2[c * 128 + e] = acc;
    __shared__ float sb[128];
    sb[e] = clsw[c * 128 + e] * ffb[e];
    __syncthreads();
    #pragma unroll
    for (int o = 64; o; o >>= 1) {
        if (e < o) sb[e] += sb[e + o];
        __syncthreads();
    }
    if (e == 0) g_b2[c] = sb[0];
}

// ---------------- final: mean assembly + 4x128 dot ----------------

__global__ __launch_bounds__(256) void k_final(float* __restrict__ out) {
    int b = blockIdx.x, tid = threadIdx.x;    // 256 threads
    __shared__ float mm[128];
    __shared__ float m2[256];
    int e = tid & 127, hi = tid >> 7;
    const float* mb = g_mB + (size_t)b * 16 * NE;
    float m = hi ? 0.f : g_mA[b * NE + e];
    #pragma unroll
    for (int i2 = 0; i2 < 8; i2++) m += mb[(hi * 8 + i2) * NE + e];
    m2[tid] = m;
    __syncthreads();
    if (hi == 0) mm[e] = (m + m2[e + 128]) * (1.f / 512.f);
    __syncthreads();
    int w = tid >> 5, lane = tid & 31;
    if (w < 4) {
        float acc = 0.f;
        #pragma unroll
        for (int q = 0; q < 4; q++) {
            int ee = lane + 32 * q;
            acc += mm[ee] * g_W2[w * 128 + ee];
        }
        #pragma unroll
        for (int o = 16; o; o >>= 1) acc += __shfl_down_sync(0xffffffffu, acc, o);
        if (lane == 0) out[b * 4 + w] = acc + g_b2[w];
    }
}

// ---------------- launch ----------------

extern "C" void kernel_launch(void* const* d_in, const int* in_sizes, int n_in,
                              void* d_out, int out_size) {
    const int*   tokens = (const int*)  d_in[0];
    const float* temb   = (const float*)d_in[1];
    const float* pemb   = (const float*)d_in[2];
    const float* rotp   = (const float*)d_in[3];
    const float* ffw    = (const float*)d_in[4];
    const float* ffb    = (const float*)d_in[5];
    const float* clsw   = (const float*)d_in[6];
    float* out = (float*)d_out;

    k_w2<<<4, 128>>>(ffw, ffb, clsw);
    k_embed_row<<<NB * NS / 32, 256>>>(tokens, temb, pemb, rotp);
    k_colA<<<NB * 8, 512>>>(rotp);
    k_rowB<<<NB * NS / 32, 256>>>(rotp);
    k_final<<<NB, 256>>>(out);
}

// round 13
// speedup vs baseline: 3.5043x; 1.0142x over previous
#include <cuda_runtime.h>
#include <cuda_fp16.h>
#include <cstdint>

// ----------------------------------------------------------------------------
// QFNet classifier, round 13:
//  - embed + rowB: 64 rows/block (amortized tables, half the partial traffic)
//  - colA: scol smem-atomics -> shuffle+array reduction; h2sqrt magnitudes
//  - all butterflies half2 (verified), GF(2) addressing (verified)
// ----------------------------------------------------------------------------

#define NB   256
#define NS   512
#define NE   128
#define NDIM 65536

typedef unsigned long long u64;
typedef unsigned int u32;

__device__ __align__(16) __half g_x0h[NB * NDIM];   // x0 fp16
__device__ u32    g_state[NB * NDIM];               // half2(re,im) per element
__device__ float  g_n0p[NB * 8];                    // embed norm0 partials
__device__ float  g_n1p[NB * 8];                    // colA norm1 partials
__device__ float  g_mA[NB * NE];                    // colA column sums
__device__ float  g_mB[NB * 8 * NE];                // rowB per-block column sums
__device__ float  g_W2[4 * NE];                     // clsw @ ffw
__device__ float  g_b2[4];                          // clsw @ ffb

// ---------------- helpers ----------------

__device__ __forceinline__ u32 h2u(__half2 h) { return *reinterpret_cast<u32*>(&h); }
__device__ __forceinline__ __half2 u2h(u32 u) { return *reinterpret_cast<__half2*>(&u); }
__device__ __forceinline__ float2 h22f2(u32 u) { return __half22float2(u2h(u)); }

__device__ __forceinline__ constexpr int px9c(int x) {
    x ^= x >> 1; x ^= x >> 2; x ^= x >> 4; x ^= x >> 8; return x;
}

__device__ __forceinline__ float2 phase_s(const float* rp, int blk, int s) {
    float ang = 0.f;
    #pragma unroll
    for (int w = 0; w < 9; w++) {
        float ph = rp[blk * 48 + w * 3 + 1];
        ang += ((s >> (8 - w)) & 1) ? ph : -ph;
    }
    float c, sn; sincosf(0.5f * ang, &sn, &c);
    return make_float2(c, sn);
}
__device__ __forceinline__ float2 phase_e(const float* rp, int blk, int e) {
    float ang = 0.f;
    #pragma unroll
    for (int w = 9; w < 16; w++) {
        float ph = rp[blk * 48 + w * 3 + 1];
        ang += ((e >> (15 - w)) & 1) ? ph : -ph;
    }
    float c, sn; sincosf(0.5f * ang, &sn, &c);
    return make_float2(c, sn);
}

// ---------------- half2 Ry butterfly primitives ----------------

__device__ __forceinline__ u32 hfma2u(u32 a, u32 b, u32 c) {
    return h2u(__hfma2(u2h(a), u2h(b), u2h(c)));
}
__device__ __forceinline__ u32 hmul2u(u32 a, u32 b) {
    return h2u(__hmul2(u2h(a), u2h(b)));
}
__device__ __forceinline__ u32 hswap(u32 v) { return (v >> 16) | (v << 16); }
__device__ __forceinline__ u32 hsplat(float v) { return h2u(__float2half2_rn(v)); }
__device__ __forceinline__ u32 hpack(float lo, float hi) {
    return h2u(__floats2half2_rn(lo, hi));
}

__device__ __forceinline__ void bpairH(u32 c2, u32 s2, u32 ns2,
                                       u32& Lx, u32& Ly, u32& Hx, u32& Hy) {
    u32 ox = hfma2u(c2, Lx, hmul2u(ns2, Hx));
    u32 oy = hfma2u(c2, Ly, hmul2u(ns2, Hy));
    u32 px = hfma2u(c2, Hx, hmul2u(s2,  Lx));
    u32 py = hfma2u(c2, Hy, hmul2u(s2,  Ly));
    Lx = ox; Ly = oy; Hx = px; Hy = py;
}
__device__ __forceinline__ void bshufH(u32 c2, u32 B2, u32& X, u32& Y, int ls) {
    u32 px = __shfl_xor_sync(0xffffffffu, X, ls);
    u32 py = __shfl_xor_sync(0xffffffffu, Y, ls);
    X = hfma2u(c2, X, hmul2u(B2, px));
    Y = hfma2u(c2, Y, hmul2u(B2, py));
}
__device__ __forceinline__ void bpackH(u32 c2, u32 Bp, u32& X, u32& Y) {
    X = hfma2u(c2, X, hmul2u(Bp, hswap(X)));
    Y = hfma2u(c2, Y, hmul2u(Bp, hswap(Y)));
}

// 7-stage embed Ry butterfly. e = 16*t + j (t = lane&7), pack k: j=2k,2k+1.
__device__ __forceinline__ void row_butterflyH(const float* ry, u32 Hx[8], u32 Hy[8], int t) {
    { u32 c2=hsplat(ry[6]), s2=hsplat(ry[7]), ns2=hsplat(-ry[7]);   // wire12
      #pragma unroll
      for (int k = 0; k < 4; k++) bpairH(c2,s2,ns2, Hx[k],Hy[k], Hx[k+4],Hy[k+4]); }
    { u32 c2=hsplat(ry[8]), s2=hsplat(ry[9]), ns2=hsplat(-ry[9]);   // wire13
      bpairH(c2,s2,ns2,Hx[0],Hy[0],Hx[2],Hy[2]); bpairH(c2,s2,ns2,Hx[1],Hy[1],Hx[3],Hy[3]);
      bpairH(c2,s2,ns2,Hx[4],Hy[4],Hx[6],Hy[6]); bpairH(c2,s2,ns2,Hx[5],Hy[5],Hx[7],Hy[7]); }
    { u32 c2=hsplat(ry[10]), s2=hsplat(ry[11]), ns2=hsplat(-ry[11]); // wire14
      bpairH(c2,s2,ns2,Hx[0],Hy[0],Hx[1],Hy[1]); bpairH(c2,s2,ns2,Hx[2],Hy[2],Hx[3],Hy[3]);
      bpairH(c2,s2,ns2,Hx[4],Hy[4],Hx[5],Hy[5]); bpairH(c2,s2,ns2,Hx[6],Hy[6],Hx[7],Hy[7]); }
    { u32 c2 = hsplat(ry[12]); u32 Bp = hpack(-ry[13], ry[13]);      // wire15
      #pragma unroll
      for (int k = 0; k < 8; k++) bpackH(c2, Bp, Hx[k], Hy[k]); }
    { u32 c2 = hsplat(ry[4]); u32 B2 = hsplat((t&1) ? ry[5] : -ry[5]);
      #pragma unroll
      for (int k = 0; k < 8; k++) bshufH(c2, B2, Hx[k], Hy[k], 1); }
    { u32 c2 = hsplat(ry[2]); u32 B2 = hsplat((t&2) ? ry[3] : -ry[3]);
      #pragma unroll
      for (int k = 0; k < 8; k++) bshufH(c2, B2, Hx[k], Hy[k], 2); }
    { u32 c2 = hsplat(ry[0]); u32 B2 = hsplat((t&4) ? ry[1] : -ry[1]);
      #pragma unroll
      for (int k = 0; k < 8; k++) bshufH(c2, B2, Hx[k], Hy[k], 4); }
}

// 9-stage seq Ry butterfly. s = lane + 32*j, pack k: j=2k (lo), 2k+1 (hi).
__device__ __forceinline__ void col_butterflyH(const float* ry, u32 Hx[8], u32 Hy[8], int lane) {
    { u32 c2=hsplat(ry[0]), s2=hsplat(ry[1]), ns2=hsplat(-ry[1]);
      #pragma unroll
      for (int k = 0; k < 4; k++) bpairH(c2,s2,ns2, Hx[k],Hy[k], Hx[k+4],Hy[k+4]); }
    { u32 c2=hsplat(ry[2]), s2=hsplat(ry[3]), ns2=hsplat(-ry[3]);
      bpairH(c2,s2,ns2,Hx[0],Hy[0],Hx[2],Hy[2]); bpairH(c2,s2,ns2,Hx[1],Hy[1],Hx[3],Hy[3]);
      bpairH(c2,s2,ns2,Hx[4],Hy[4],Hx[6],Hy[6]); bpairH(c2,s2,ns2,Hx[5],Hy[5],Hx[7],Hy[7]); }
    { u32 c2=hsplat(ry[4]), s2=hsplat(ry[5]), ns2=hsplat(-ry[5]);
      bpairH(c2,s2,ns2,Hx[0],Hy[0],Hx[1],Hy[1]); bpairH(c2,s2,ns2,Hx[2],Hy[2],Hx[3],Hy[3]);
      bpairH(c2,s2,ns2,Hx[4],Hy[4],Hx[5],Hy[5]); bpairH(c2,s2,ns2,Hx[6],Hy[6],Hx[7],Hy[7]); }
    { u32 c2 = hsplat(ry[6]); u32 Bp = hpack(-ry[7], ry[7]);
      #pragma unroll
      for (int k = 0; k < 8; k++) bpackH(c2, Bp, Hx[k], Hy[k]); }
    #pragma unroll
    for (int st = 0; st < 5; st++) {
        int ls = 16 >> st;
        const float* p = ry + 8 + st * 2;
        u32 c2 = hsplat(p[0]); u32 B2 = hsplat((lane & ls) ? p[1] : -p[1]);
        #pragma unroll
        for (int k = 0; k < 8; k++) bshufH(c2, B2, Hx[k], Hy[k], ls);
    }
}

// ---------------- embed + D(phi)_1 + B1 emb butterfly (half2), 64 rows -----

__global__ __launch_bounds__(256) void k_embed_row(const int* __restrict__ tokens,
                                                   const float* __restrict__ temb,
                                                   const float* __restrict__ pemb,
                                                   const float* __restrict__ rp) {
    __shared__ __align__(16) float ry[14];
    __shared__ __align__(8) u32 epcH[64], epsH[64];
    __shared__ float2 psrow[64];
    __shared__ float wss[8];
    int tid = threadIdx.x;
    if (tid < 7) {
        float c, sn; sincosf(0.5f * rp[(9 + tid) * 3], &sn, &c);
        ry[2*tid] = c; ry[2*tid+1] = sn;
    }
    if (tid < 64) {
        int e0 = 16 * (tid >> 3) + 2 * (tid & 7);
        float2 A = phase_e(rp, 0, e0), B = phase_e(rp, 0, e0 + 1);
        epcH[tid] = hpack(A.x, B.x);
        epsH[tid] = hpack(A.y, B.y);
    }
    if (tid >= 64 && tid < 128) {
        int r = tid - 64;
        psrow[r] = phase_s(rp, 0, (blockIdx.x * 64 + r) & (NS - 1));
    }
    __syncthreads();
    int warp = tid >> 5, lane = tid & 31, rl = lane >> 3, t = lane & 7;
    float ss = 0.f;
    #pragma unroll
    for (int it2 = 0; it2 < 2; it2++) {
        int rlocal = it2 * 32 + warp * 4 + rl;
        int row = blockIdx.x * 64 + rlocal;
        int tok = tokens[row];
        const float4* te  = (const float4*)(temb + (size_t)tok * NE + 16 * t);
        const float4* pe4 = (const float4*)(pemb + (size_t)(row & (NS-1)) * NE + 16 * t);
        float v[16];
        #pragma unroll
        for (int q = 0; q < 4; q++) {
            float4 a = te[q], b = pe4[q];
            float v0 = a.x + b.x, v1 = a.y + b.y, v2 = a.z + b.z, v3 = a.w + b.w;
            ss += v0*v0 + v1*v1 + v2*v2 + v3*v3;
            v[4*q] = v0; v[4*q+1] = v1; v[4*q+2] = v2; v[4*q+3] = v3;
        }
        u32 xh[8];
        #pragma unroll
        for (int k = 0; k < 8; k++) xh[k] = hpack(v[2*k], v[2*k+1]);
        uint4* gx = (uint4*)(g_x0h + (size_t)row * NE + 16 * t);
        gx[0] = make_uint4(xh[0], xh[1], xh[2], xh[3]);
        gx[1] = make_uint4(xh[4], xh[5], xh[6], xh[7]);

        float2 psv = psrow[rlocal];
        u32 a2h = hsplat(psv.x), b2h = hsplat(psv.y), nb2h = hsplat(-psv.y);
        u32 Hx[8], Hy[8];
        #pragma unroll
        for (int k = 0; k < 8; k++) {
            u32 tc = epcH[t*8+k], ts = epsH[t*8+k];
            u32 c1 = hfma2u(a2h, tc, hmul2u(nb2h, ts));
            u32 s1 = hfma2u(b2h, tc, hmul2u(a2h,  ts));
            Hx[k] = hmul2u(xh[k], c1);
            Hy[k] = hmul2u(xh[k], s1);
        }

        row_butterflyH(ry, Hx, Hy, t);

        u32 hv[16];
        #pragma unroll
        for (int k = 0; k < 8; k++) {
            hv[2*k]   = __byte_perm(Hx[k], Hy[k], 0x5410);
            hv[2*k+1] = __byte_perm(Hx[k], Hy[k], 0x7632);
        }
        uint4* dst = (uint4*)(g_state + (size_t)row * NE + 16 * t);
        #pragma unroll
        for (int q = 0; q < 4; q++)
            dst[q] = make_uint4(hv[4*q], hv[4*q+1], hv[4*q+2], hv[4*q+3]);
    }
    #pragma unroll
    for (int o = 16; o; o >>= 1) ss += __shfl_down_sync(0xffffffffu, ss, o);
    if (lane == 0) wss[warp] = ss;
    __syncthreads();
    if (tid == 0) {
        float tot = 0.f;
        #pragma unroll
        for (int q = 0; q < 8; q++) tot += wss[q];
        g_n0p[blockIdx.x] = tot;      // blockIdx = b*8 + grp
    }
}

// ---------------- colA: A1 + perm + residual + D(phi)_2 + A2 (half2) -------

__global__ __launch_bounds__(512) void k_colA(const float* __restrict__ rp) {
    __shared__ __align__(16) float ryA[18], ryB[18];
    __shared__ __align__(8) u32 tscH[256], tssH[256];
    __shared__ __align__(16) u32 tin[16 * 513];
    __shared__ float scolp[16][17];
    __shared__ float ssacc;
    __shared__ float s_inv0;
    __shared__ float2 pe2t[16];
    float* tf = reinterpret_cast<float*>(tin);

    int tid = threadIdx.x;
    int b = blockIdx.x >> 3, grp = blockIdx.x & 7, c0 = grp * 8;
    if (tid < 18) {
        int blk = tid / 9, wi = tid % 9;
        float c, sn; sincosf(0.5f * rp[blk * 48 + wi * 3], &sn, &c);
        if (blk == 0) { ryA[2*wi] = c; ryA[2*wi+1] = sn; }
        else          { ryB[2*wi] = c; ryB[2*wi+1] = sn; }
    }
    if (tid == 0)  ssacc = 0.f;
    if (tid < 256) {
        int k = tid >> 5, l = tid & 31;
        float2 A = phase_s(rp, 1, l + 64*k), B = phase_s(rp, 1, l + 64*k + 32);
        tscH[tid] = hpack(A.x, B.x);
        tssH[tid] = hpack(A.y, B.y);
    }
    if (tid >= 256 && tid < 272) {
        int i2 = tid - 256;
        int gc = (i2 < 8) ? (c0 + i2) : (112 - c0 + i2);
        pe2t[i2] = phase_e(rp, 1, gc);
    }
    if (tid == 272) {
        float t0 = 0.f;
        #pragma unroll
        for (int j = 0; j < 8; j++) t0 += g_n0p[b * 8 + j];
        s_inv0 = rsqrtf(t0);
    }

    int i = tid & 7, strip = (tid >> 3) & 1, rb = tid >> 4;
    int gcolL = strip ? (120 - c0 + i) : (c0 + i);
    int cidxL = strip * 8 + i;
    int srcCol = gcolL ^ (gcolL >> 1);
    const u32* st = g_state + (size_t)b * NDIM;
    #pragma unroll
    for (int it = 0; it < 16; it++) {
        int r = rb + it * 32;
        tin[cidxL * 513 + r] = st[r * NE + srcCol];
    }
    __syncthreads();
    float inv0 = s_inv0;
    int w = tid >> 5, lane = tid & 31;
    u32 Hx[8], Hy[8];
    #pragma unroll
    for (int k = 0; k < 8; k++) {
        u32 w0 = tin[w * 513 + lane + 64*k];
        u32 w1 = tin[w * 513 + lane + 64*k + 32];
        Hx[k] = __byte_perm(w0, w1, 0x5410);
        Hy[k] = __byte_perm(w0, w1, 0x7632);
    }
    __syncthreads();

    col_butterflyH(ryA, Hx, Hy, lane);

    // CNOT perm + |.|*inv0 scatter (GF(2) addressing, verified)
    int colw = (w < 8) ? (c0 + w) : (112 - c0 + w);
    {
        int pxl = lane ^ (lane >> 1); pxl ^= pxl >> 2; pxl ^= pxl >> 4;
        int parl = __popc(lane) & 1;
        int lowb = colw & 1;
        int c_sel0 = (parl ? (15 - w) : w) * 513;
        int c_sel1 = (parl ? w : (15 - w)) * 513;
        int sel0 = pxl ^ ((lowb ^ parl) << 8);
        int sel1 = pxl ^ ((lowb ^ parl ^ 1) << 8);
        #pragma unroll
        for (int k = 0; k < 8; k++) {
            u32 m2 = hfma2u(Hx[k], Hx[k], hmul2u(Hy[k], Hy[k]));
            u32 hm = h2u(h2sqrt(u2h(m2)));
            float2 mf = h22f2(hm);
            float mag0 = mf.x * inv0;
            float mag1 = mf.y * inv0;
            const int PXC0 = px9c(64 * k);
            const int PXC1 = px9c(64 * k + 32);
            const int P0 = __popc(k) & 1;
            int addr0 = (P0 ? c_sel1 : c_sel0) + ((P0 ? sel1 : sel0) ^ PXC0);
            int addr1 = (P0 ? c_sel0 : c_sel1) + ((P0 ? sel0 : sel1) ^ PXC1);
            tf[addr0] = mag0;
            tf[addr1] = mag1;
        }
    }
    __syncthreads();

    // residual + stats, in place (fp32)
    const __half* x0p = g_x0h + (size_t)b * NDIM;
    float cs = 0.f, sq = 0.f;
    #pragma unroll
    for (int it = 0; it < 16; it++) {
        int r = rb + it * 32;
        float vv = tf[cidxL * 513 + r] + __half2float(x0p[r * NE + gcolL]);
        tf[cidxL * 513 + r] = vv;
        cs += vv;  sq += vv * vv;
    }
    // column-sum: lanes L and L+16 share cidxL == L (L<16)
    cs += __shfl_down_sync(0xffffffffu, cs, 16);
    if (lane < 16) scolp[lane][w] = cs;
    #pragma unroll
    for (int o = 16; o; o >>= 1) sq += __shfl_down_sync(0xffffffffu, sq, o);
    if (lane == 0) atomicAdd(&ssacc, sq);
    __syncthreads();

    if (tid == 0) g_n1p[blockIdx.x] = ssacc;          // blockIdx = b*8 + grp
    if (tid < 16) {
        float sc = 0.f;
        #pragma unroll
        for (int j = 0; j < 16; j++) sc += scolp[tid][j];
        int gc = (tid < 8) ? (c0 + tid) : (112 - c0 + tid);
        g_mA[b * NE + gc] = sc;
    }

    // reload x1 + D(phi)_2 in half2
    u32 pa2 = hsplat(pe2t[w].x), pb2 = hsplat(pe2t[w].y), pnb2 = hsplat(-pe2t[w].y);
    #pragma unroll
    for (int k = 0; k < 8; k++) {
        float a = tf[w * 513 + lane + 64*k];
        float c = tf[w * 513 + lane + 64*k + 32];
        u32 x1h = hpack(a, c);
        u32 tc = tscH[k*32 + lane], ts = tssH[k*32 + lane];
        u32 c12 = hfma2u(pa2, tc, hmul2u(pnb2, ts));
        u32 s12 = hfma2u(pb2, tc, hmul2u(pa2,  ts));
        Hx[k] = hmul2u(x1h, c12);
        Hy[k] = hmul2u(x1h, s12);
    }
    __syncthreads();

    col_butterflyH(ryB, Hx, Hy, lane);

    #pragma unroll
    for (int k = 0; k < 8; k++) {
        tin[w * 513 + lane + 64*k]      = __byte_perm(Hx[k], Hy[k], 0x5410);
        tin[w * 513 + lane + 64*k + 32] = __byte_perm(Hx[k], Hy[k], 0x7632);
    }
    __syncthreads();
    u32* yp = g_state + (size_t)b * NDIM;
    #pragma unroll
    for (int it = 0; it < 16; it++) {
        int r = rb + it * 32;
        yp[r * NE + gcolL] = tin[cidxL * 513 + r];
    }
}

// ---------------- rowB: B2 emb butterfly (half2), 64 rows + reduction ------

__global__ __launch_bounds__(256) void k_rowB(const float* __restrict__ rp) {
    __shared__ __align__(16) u32 srow[64][68];
    __shared__ __align__(16) float ry[14];
    __shared__ float sred[128];
    __shared__ float s_inv1;
    int tid = threadIdx.x;
    int b = blockIdx.x >> 3;
    if (tid < 7) {
        float c, sn; sincosf(0.5f * rp[48 + (9 + tid) * 3], &sn, &c);
        ry[2*tid] = c; ry[2*tid+1] = sn;
    }
    if (tid == 32) {
        float t1 = 0.f;
        #pragma unroll
        for (int j = 0; j < 8; j++) t1 += g_n1p[b * 8 + j];
        s_inv1 = rsqrtf(t1);
    }
    __syncthreads();
    int warp = tid >> 5, lane = tid & 31, rl = lane >> 3, t = lane & 7;
    int rls = warp * 4 + rl;
    #pragma unroll
    for (int it2 = 0; it2 < 2; it2++) {
        int rlocal = it2 * 32 + rls;
        int row = blockIdx.x * 64 + rlocal;
        const uint4* src = (const uint4*)(g_state + (size_t)row * NE + 16 * t);
        u32 Hx[8], Hy[8];
        #pragma unroll
        for (int q = 0; q < 4; q++) {
            uint4 U = src[q];
            Hx[2*q]   = __byte_perm(U.x, U.y, 0x5410);
            Hy[2*q]   = __byte_perm(U.x, U.y, 0x7632);
            Hx[2*q+1] = __byte_perm(U.z, U.w, 0x5410);
            Hy[2*q+1] = __byte_perm(U.z, U.w, 0x7632);
        }

        row_butterflyH(ry, Hx, Hy, t);

        u32 hm[8];
        #pragma unroll
        for (int k = 0; k < 8; k++) {
            u32 msq = hfma2u(Hx[k], Hx[k], hmul2u(Hy[k], Hy[k]));
            hm[k] = h2u(h2sqrt(u2h(msq)));
        }
        uint4* wp = (uint4*)&srow[rlocal][8 * t];
        wp[0] = make_uint4(hm[0], hm[1], hm[2], hm[3]);
        wp[1] = make_uint4(hm[4], hm[5], hm[6], hm[7]);
    }
    __syncthreads();

    // reduction over 64 rows: es = (e^(e>>1)) ^ 64*par(s)
    // par(s) = par(sbase) ^ half ^ par(q)  (r = half*32 + q)
    int e = tid & 127, half = tid >> 7;
    int sbase = (blockIdx.x * 64) & (NS - 1);
    int ebase = e ^ (e >> 1);
    int p0 = (__popc(sbase) ^ half) & 1;
    int esA = ebase ^ (p0 << 6);
    int esB = esA ^ 64;
    const __half* srh = (const __half*)srow;
    float acc = 0.f;
    #pragma unroll
    for (int q = 0; q < 32; q++) {
        int r = half * 32 + q;
        int es = ((0x96696996u >> q) & 1) ? esB : esA;
        acc += __half2float(srh[r * 136 + es]);
    }
    if (half == 1) sred[e] = acc;
    __syncthreads();
    if (half == 0) g_mB[blockIdx.x * NE + e] = (acc + sred[e]) * s_inv1;
}

// ---------------- W2 = clsw @ ffw (4x128), b2 = clsw @ ffb ----------------

__global__ __launch_bounds__(128) void k_w2(const float* __restrict__ ffw,
                                            const float* __restrict__ ffb,
                                            const float* __restrict__ clsw) {
    int c = blockIdx.x, e = threadIdx.x;
    float acc = 0.f;
    #pragma unroll 4
    for (int j = 0; j < 128; j++) acc += clsw[c * 128 + j] * ffw[j * 128 + e];
    g_W2[c * 128 + e] = acc;
    __shared__ float sb[128];
    sb[e] = clsw[c * 128 + e] * ffb[e];
    __syncthreads();
    #pragma unroll
    for (int o = 64; o; o >>= 1) {
        if (e < o) sb[e] += sb[e + o];
        __syncthreads();
    }
    if (e == 0) g_b2[c] = sb[0];
}

// ---------------- final: mean assembly + 4x128 dot ----------------

__global__ __launch_bounds__(256) void k_final(float* __restrict__ out) {
    int b = blockIdx.x, tid = threadIdx.x;
    __shared__ float mm[128];
    __shared__ float m2[256];
    int e = tid & 127, hi = tid >> 7;
    const float* mb = g_mB + (size_t)b * 8 * NE;
    float m = hi ? 0.f : g_mA[b * NE + e];
    #pragma unroll
    for (int i2 = 0; i2 < 4; i2++) m += mb[(hi * 4 + i2) * NE + e];
    m2[tid] = m;
    __syncthreads();
    if (hi == 0) mm[e] = (m + m2[e + 128]) * (1.f / 512.f);
    __syncthreads();
    int w = tid >> 5, lane = tid & 31;
    if (w < 4) {
        float acc = 0.f;
        #pragma unroll
        for (int q = 0; q < 4; q++) {
            int ee = lane + 32 * q;
            acc += mm[ee] * g_W2[w * 128 + ee];
        }
        #pragma unroll
        for (int o = 16; o; o >>= 1) acc += __shfl_down_sync(0xffffffffu, acc, o);
        if (lane == 0) out[b * 4 + w] = acc + g_b2[w];
    }
}

// ---------------- launch ----------------

extern "C" void kernel_launch(void* const* d_in, const int* in_sizes, int n_in,
                              void* d_out, int out_size) {
    const int*   tokens = (const int*)  d_in[0];
    const float* temb   = (const float*)d_in[1];
    const float* pemb   = (const float*)d_in[2];
    const float* rotp   = (const float*)d_in[3];
    const float* ffw    = (const float*)d_in[4];
    const float* ffb    = (const float*)d_in[5];
    const float* clsw   = (const float*)d_in[6];
    float* out = (float*)d_out;

    k_w2<<<4, 128>>>(ffw, ffb, clsw);
    k_embed_row<<<NB * NS / 64, 256>>>(tokens, temb, pemb, rotp);
    k_colA<<<NB * 8, 512>>>(rotp);
    k_rowB<<<NB * NS / 64, 256>>>(rotp);
    k_final<<<NB, 256>>>(out);
}

// round 15
// speedup vs baseline: 3.9956x; 1.1402x over previous
#include <cuda_runtime.h>
#include <cuda_fp16.h>
#include <cstdint>

// ----------------------------------------------------------------------------
// QFNet classifier, round 15 (R14 + smem fix):
//  - inter-kernel state in FP8 (e4m3 re,im per element; 32MB total)
//  - k_colA: tin16 (e4m3 staging) and tf (fp32 work) ALIAS one 32.8KB buffer
//    (disjoint live ranges, guarded by restored __syncthreads at the two
//    read->write transitions); static smem now ~36KB < 48KB limit
//  - rowB 32-row form; embed 64-row form (both measured-best)
// ----------------------------------------------------------------------------

#define NB   256
#define NS   512
#define NE   128
#define NDIM 65536

typedef unsigned long long u64;
typedef unsigned int u32;
typedef unsigned short u16;

__device__ __align__(16) __half g_x0h[NB * NDIM];     // x0 fp16
__device__ __align__(16) u32 g_state[NB * NDIM / 2];  // e4m3 (re,im) x2 elems/word
__device__ float  g_n0p[NB * 8];
__device__ float  g_n1p[NB * 8];
__device__ float  g_mA[NB * NE];
__device__ float  g_mB[NB * 16 * NE];
__device__ float  g_W2[4 * NE];
__device__ float  g_b2[4];

// ---------------- helpers ----------------

__device__ __forceinline__ u32 h2u(__half2 h) { return *reinterpret_cast<u32*>(&h); }
__device__ __forceinline__ __half2 u2h(u32 u) { return *reinterpret_cast<__half2*>(&u); }
__device__ __forceinline__ float2 h22f2(u32 u) { return __half22float2(u2h(u)); }

__device__ __forceinline__ u16 h2e(u32 h) {
    u16 r;
    asm("cvt.rn.satfinite.e4m3x2.f16x2 %0, %1;" : "=h"(r) : "r"(h));
    return r;
}
__device__ __forceinline__ u32 e2h(u16 e) {
    u32 r;
    asm("cvt.rn.f16x2.e4m3x2 %0, %1;" : "=r"(r) : "h"(e));
    return r;
}

__device__ __forceinline__ constexpr int px9c(int x) {
    x ^= x >> 1; x ^= x >> 2; x ^= x >> 4; x ^= x >> 8; return x;
}

__device__ __forceinline__ float2 phase_s(const float* rp, int blk, int s) {
    float ang = 0.f;
    #pragma unroll
    for (int w = 0; w < 9; w++) {
        float ph = rp[blk * 48 + w * 3 + 1];
        ang += ((s >> (8 - w)) & 1) ? ph : -ph;
    }
    float c, sn; sincosf(0.5f * ang, &sn, &c);
    return make_float2(c, sn);
}
__device__ __forceinline__ float2 phase_e(const float* rp, int blk, int e) {
    float ang = 0.f;
    #pragma unroll
    for (int w = 9; w < 16; w++) {
        float ph = rp[blk * 48 + w * 3 + 1];
        ang += ((e >> (15 - w)) & 1) ? ph : -ph;
    }
    float c, sn; sincosf(0.5f * ang, &sn, &c);
    return make_float2(c, sn);
}

// ---------------- half2 Ry butterfly primitives ----------------

__device__ __forceinline__ u32 hfma2u(u32 a, u32 b, u32 c) {
    return h2u(__hfma2(u2h(a), u2h(b), u2h(c)));
}
__device__ __forceinline__ u32 hmul2u(u32 a, u32 b) {
    return h2u(__hmul2(u2h(a), u2h(b)));
}
__device__ __forceinline__ u32 hswap(u32 v) { return (v >> 16) | (v << 16); }
__device__ __forceinline__ u32 hsplat(float v) { return h2u(__float2half2_rn(v)); }
__device__ __forceinline__ u32 hpack(float lo, float hi) {
    return h2u(__floats2half2_rn(lo, hi));
}

__device__ __forceinline__ void bpairH(u32 c2, u32 s2, u32 ns2,
                                       u32& Lx, u32& Ly, u32& Hx, u32& Hy) {
    u32 ox = hfma2u(c2, Lx, hmul2u(ns2, Hx));
    u32 oy = hfma2u(c2, Ly, hmul2u(ns2, Hy));
    u32 px = hfma2u(c2, Hx, hmul2u(s2,  Lx));
    u32 py = hfma2u(c2, Hy, hmul2u(s2,  Ly));
    Lx = ox; Ly = oy; Hx = px; Hy = py;
}
__device__ __forceinline__ void bshufH(u32 c2, u32 B2, u32& X, u32& Y, int ls) {
    u32 px = __shfl_xor_sync(0xffffffffu, X, ls);
    u32 py = __shfl_xor_sync(0xffffffffu, Y, ls);
    X = hfma2u(c2, X, hmul2u(B2, px));
    Y = hfma2u(c2, Y, hmul2u(B2, py));
}
__device__ __forceinline__ void bpackH(u32 c2, u32 Bp, u32& X, u32& Y) {
    X = hfma2u(c2, X, hmul2u(Bp, hswap(X)));
    Y = hfma2u(c2, Y, hmul2u(Bp, hswap(Y)));
}

// 7-stage embed Ry butterfly. e = 16*t + j (t = lane&7), pack k: j=2k,2k+1.
__device__ __forceinline__ void row_butterflyH(const float* ry, u32 Hx[8], u32 Hy[8], int t) {
    { u32 c2=hsplat(ry[6]), s2=hsplat(ry[7]), ns2=hsplat(-ry[7]);
      #pragma unroll
      for (int k = 0; k < 4; k++) bpairH(c2,s2,ns2, Hx[k],Hy[k], Hx[k+4],Hy[k+4]); }
    { u32 c2=hsplat(ry[8]), s2=hsplat(ry[9]), ns2=hsplat(-ry[9]);
      bpairH(c2,s2,ns2,Hx[0],Hy[0],Hx[2],Hy[2]); bpairH(c2,s2,ns2,Hx[1],Hy[1],Hx[3],Hy[3]);
      bpairH(c2,s2,ns2,Hx[4],Hy[4],Hx[6],Hy[6]); bpairH(c2,s2,ns2,Hx[5],Hy[5],Hx[7],Hy[7]); }
    { u32 c2=hsplat(ry[10]), s2=hsplat(ry[11]), ns2=hsplat(-ry[11]);
      bpairH(c2,s2,ns2,Hx[0],Hy[0],Hx[1],Hy[1]); bpairH(c2,s2,ns2,Hx[2],Hy[2],Hx[3],Hy[3]);
      bpairH(c2,s2,ns2,Hx[4],Hy[4],Hx[5],Hy[5]); bpairH(c2,s2,ns2,Hx[6],Hy[6],Hx[7],Hy[7]); }
    { u32 c2 = hsplat(ry[12]); u32 Bp = hpack(-ry[13], ry[13]);
      #pragma unroll
      for (int k = 0; k < 8; k++) bpackH(c2, Bp, Hx[k], Hy[k]); }
    { u32 c2 = hsplat(ry[4]); u32 B2 = hsplat((t&1) ? ry[5] : -ry[5]);
      #pragma unroll
      for (int k = 0; k < 8; k++) bshufH(c2, B2, Hx[k], Hy[k], 1); }
    { u32 c2 = hsplat(ry[2]); u32 B2 = hsplat((t&2) ? ry[3] : -ry[3]);
      #pragma unroll
      for (int k = 0; k < 8; k++) bshufH(c2, B2, Hx[k], Hy[k], 2); }
    { u32 c2 = hsplat(ry[0]); u32 B2 = hsplat((t&4) ? ry[1] : -ry[1]);
      #pragma unroll
      for (int k = 0; k < 8; k++) bshufH(c2, B2, Hx[k], Hy[k], 4); }
}

// 9-stage seq Ry butterfly. s = lane + 32*j, pack k: j=2k (lo), 2k+1 (hi).
__device__ __forceinline__ void col_butterflyH(const float* ry, u32 Hx[8], u32 Hy[8], int lane) {
    { u32 c2=hsplat(ry[0]), s2=hsplat(ry[1]), ns2=hsplat(-ry[1]);
      #pragma unroll
      for (int k = 0; k < 4; k++) bpairH(c2,s2,ns2, Hx[k],Hy[k], Hx[k+4],Hy[k+4]); }
    { u32 c2=hsplat(ry[2]), s2=hsplat(ry[3]), ns2=hsplat(-ry[3]);
      bpairH(c2,s2,ns2,Hx[0],Hy[0],Hx[2],Hy[2]); bpairH(c2,s2,ns2,Hx[1],Hy[1],Hx[3],Hy[3]);
      bpairH(c2,s2,ns2,Hx[4],Hy[4],Hx[6],Hy[6]); bpairH(c2,s2,ns2,Hx[5],Hy[5],Hx[7],Hy[7]); }
    { u32 c2=hsplat(ry[4]), s2=hsplat(ry[5]), ns2=hsplat(-ry[5]);
      bpairH(c2,s2,ns2,Hx[0],Hy[0],Hx[1],Hy[1]); bpairH(c2,s2,ns2,Hx[2],Hy[2],Hx[3],Hy[3]);
      bpairH(c2,s2,ns2,Hx[4],Hy[4],Hx[5],Hy[5]); bpairH(c2,s2,ns2,Hx[6],Hy[6],Hx[7],Hy[7]); }
    { u32 c2 = hsplat(ry[6]); u32 Bp = hpack(-ry[7], ry[7]);
      #pragma unroll
      for (int k = 0; k < 8; k++) bpackH(c2, Bp, Hx[k], Hy[k]); }
    #pragma unroll
    for (int st = 0; st < 5; st++) {
        int ls = 16 >> st;
        const float* p = ry + 8 + st * 2;
        u32 c2 = hsplat(p[0]); u32 B2 = hsplat((lane & ls) ? p[1] : -p[1]);
        #pragma unroll
        for (int k = 0; k < 8; k++) bshufH(c2, B2, Hx[k], Hy[k], ls);
    }
}

// ---------------- embed + D(phi)_1 + B1 emb butterfly, 64 rows, fp8 out ----

__global__ __launch_bounds__(256) void k_embed_row(const int* __restrict__ tokens,
                                                   const float* __restrict__ temb,
                                                   const float* __restrict__ pemb,
                                                   const float* __restrict__ rp) {
    __shared__ __align__(16) float ry[14];
    __shared__ __align__(8) u32 epcH[64], epsH[64];
    __shared__ float2 psrow[64];
    __shared__ float wss[8];
    int tid = threadIdx.x;
    if (tid < 7) {
        float c, sn; sincosf(0.5f * rp[(9 + tid) * 3], &sn, &c);
        ry[2*tid] = c; ry[2*tid+1] = sn;
    }
    if (tid < 64) {
        int e0 = 16 * (tid >> 3) + 2 * (tid & 7);
        float2 A = phase_e(rp, 0, e0), B = phase_e(rp, 0, e0 + 1);
        epcH[tid] = hpack(A.x, B.x);
        epsH[tid] = hpack(A.y, B.y);
    }
    if (tid >= 64 && tid < 128) {
        int r = tid - 64;
        psrow[r] = phase_s(rp, 0, (blockIdx.x * 64 + r) & (NS - 1));
    }
    __syncthreads();
    int warp = tid >> 5, lane = tid & 31, rl = lane >> 3, t = lane & 7;
    float ss = 0.f;
    #pragma unroll
    for (int it2 = 0; it2 < 2; it2++) {
        int rlocal = it2 * 32 + warp * 4 + rl;
        int row = blockIdx.x * 64 + rlocal;
        int tok = tokens[row];
        const float4* te  = (const float4*)(temb + (size_t)tok * NE + 16 * t);
        const float4* pe4 = (const float4*)(pemb + (size_t)(row & (NS-1)) * NE + 16 * t);
        float v[16];
        #pragma unroll
        for (int q = 0; q < 4; q++) {
            float4 a = te[q], b = pe4[q];
            float v0 = a.x + b.x, v1 = a.y + b.y, v2 = a.z + b.z, v3 = a.w + b.w;
            ss += v0*v0 + v1*v1 + v2*v2 + v3*v3;
            v[4*q] = v0; v[4*q+1] = v1; v[4*q+2] = v2; v[4*q+3] = v3;
        }
        u32 xh[8];
        #pragma unroll
        for (int k = 0; k < 8; k++) xh[k] = hpack(v[2*k], v[2*k+1]);
        uint4* gx = (uint4*)(g_x0h + (size_t)row * NE + 16 * t);
        gx[0] = make_uint4(xh[0], xh[1], xh[2], xh[3]);
        gx[1] = make_uint4(xh[4], xh[5], xh[6], xh[7]);

        float2 psv = psrow[rlocal];
        u32 a2h = hsplat(psv.x), b2h = hsplat(psv.y), nb2h = hsplat(-psv.y);
        u32 Hx[8], Hy[8];
        #pragma unroll
        for (int k = 0; k < 8; k++) {
            u32 tc = epcH[t*8+k], ts = epsH[t*8+k];
            u32 c1 = hfma2u(a2h, tc, hmul2u(nb2h, ts));
            u32 s1 = hfma2u(b2h, tc, hmul2u(a2h,  ts));
            Hx[k] = hmul2u(xh[k], c1);
            Hy[k] = hmul2u(xh[k], s1);
        }

        row_butterflyH(ry, Hx, Hy, t);

        u32 wd[8];
        #pragma unroll
        for (int k = 0; k < 8; k++) {
            u32 hv0 = __byte_perm(Hx[k], Hy[k], 0x5410);
            u32 hv1 = __byte_perm(Hx[k], Hy[k], 0x7632);
            wd[k] = (u32)h2e(hv0) | ((u32)h2e(hv1) << 16);
        }
        uint4* dst = (uint4*)(g_state + (size_t)row * 64 + 8 * t);
        dst[0] = make_uint4(wd[0], wd[1], wd[2], wd[3]);
        dst[1] = make_uint4(wd[4], wd[5], wd[6], wd[7]);
    }
    #pragma unroll
    for (int o = 16; o; o >>= 1) ss += __shfl_down_sync(0xffffffffu, ss, o);
    if (lane == 0) wss[warp] = ss;
    __syncthreads();
    if (tid == 0) {
        float tot = 0.f;
        #pragma unroll
        for (int q = 0; q < 8; q++) tot += wss[q];
        g_n0p[blockIdx.x] = tot;      // blockIdx = b*8 + grp
    }
}

// ---------------- colA: A1 + perm + residual + D(phi)_2 + A2 ----------------
// tin16 (e4m3 staging, 16.7KB) and tf (fp32 work, 32.8KB) alias one buffer.

__global__ __launch_bounds__(512) void k_colA(const float* __restrict__ rp) {
    __shared__ __align__(16) float ryA[18], ryB[18];
    __shared__ __align__(8) u32 tscH[256], tssH[256];
    __shared__ __align__(16) char sbuf[16 * 513 * 4];   // union: tin16 / tf
    __shared__ float scolp[16][17];
    __shared__ float ssacc;
    __shared__ float s_inv0;
    __shared__ float2 pe2t[16];
    u16*   tin16 = reinterpret_cast<u16*>(sbuf);        // stride 522, 16704 B
    float* tf    = reinterpret_cast<float*>(sbuf);      // stride 513, 32832 B

    int tid = threadIdx.x;
    int b = blockIdx.x >> 3, grp = blockIdx.x & 7, c0 = grp * 8;
    if (tid < 18) {
        int blk = tid / 9, wi = tid % 9;
        float c, sn; sincosf(0.5f * rp[blk * 48 + wi * 3], &sn, &c);
        if (blk == 0) { ryA[2*wi] = c; ryA[2*wi+1] = sn; }
        else          { ryB[2*wi] = c; ryB[2*wi+1] = sn; }
    }
    if (tid == 0)  ssacc = 0.f;
    if (tid < 256) {
        int k = tid >> 5, l = tid & 31;
        float2 A = phase_s(rp, 1, l + 64*k), B = phase_s(rp, 1, l + 64*k + 32);
        tscH[tid] = hpack(A.x, B.x);
        tssH[tid] = hpack(A.y, B.y);
    }
    if (tid >= 256 && tid < 272) {
        int i2 = tid - 256;
        int gc = (i2 < 8) ? (c0 + i2) : (112 - c0 + i2);
        pe2t[i2] = phase_e(rp, 1, gc);
    }
    if (tid == 272) {
        float t0 = 0.f;
        #pragma unroll
        for (int j = 0; j < 8; j++) t0 += g_n0p[b * 8 + j];
        s_inv0 = rsqrtf(t0);
    }

    // staging-in: u32 = 2 adjacent SOURCE cols; dest slot via inverse-gray
    int i2 = tid & 7, rb8 = tid >> 3;          // rb8: 0..63
    int gg = grp ^ (grp >> 1);
    int widx = (i2 < 4) ? (4*gg + i2) : (4*gg + 32 + (i2 - 4));
    int sc = widx * 2;
    int gc0 = sc; gc0 ^= gc0 >> 1; gc0 ^= gc0 >> 2; gc0 ^= gc0 >> 4;   // invgray
    int ci0 = (i2 < 4) ? (gc0 - c0) : (8 + gc0 - (120 - c0));
    const u32* stw = g_state + (size_t)b * (NDIM / 2);
    #pragma unroll
    for (int it = 0; it < 8; it++) {
        int r = rb8 + 64 * it;
        u32 wv = stw[r * 64 + widx];
        tin16[ci0 * 522 + r]       = (u16)wv;
        tin16[(ci0^1) * 522 + r]   = (u16)(wv >> 16);
    }
    __syncthreads();
    float inv0 = s_inv0;
    int w = tid >> 5, lane = tid & 31;
    u32 Hx[8], Hy[8];
    #pragma unroll
    for (int k = 0; k < 8; k++) {
        u32 ha = e2h(tin16[w * 522 + lane + 64*k]);
        u32 hb = e2h(tin16[w * 522 + lane + 64*k + 32]);
        Hx[k] = __byte_perm(ha, hb, 0x5410);
        Hy[k] = __byte_perm(ha, hb, 0x7632);
    }
    __syncthreads();   // tin16 fully consumed before tf (aliased) is written

    col_butterflyH(ryA, Hx, Hy, lane);

    // CNOT perm + |.|*inv0 scatter into tf (GF(2) addressing, verified)
    int colw = (w < 8) ? (c0 + w) : (112 - c0 + w);
    {
        int pxl = lane ^ (lane >> 1); pxl ^= pxl >> 2; pxl ^= pxl >> 4;
        int parl = __popc(lane) & 1;
        int lowb = colw & 1;
        int c_sel0 = (parl ? (15 - w) : w) * 513;
        int c_sel1 = (parl ? w : (15 - w)) * 513;
        int sel0 = pxl ^ ((lowb ^ parl) << 8);
        int sel1 = pxl ^ ((lowb ^ parl ^ 1) << 8);
        #pragma unroll
        for (int k = 0; k < 8; k++) {
            u32 m2 = hfma2u(Hx[k], Hx[k], hmul2u(Hy[k], Hy[k]));
            u32 hm = h2u(h2sqrt(u2h(m2)));
            float2 mf = h22f2(hm);
            float mag0 = mf.x * inv0;
            float mag1 = mf.y * inv0;
            const int PXC0 = px9c(64 * k);
            const int PXC1 = px9c(64 * k + 32);
            const int P0 = __popc(k) & 1;
            int addr0 = (P0 ? c_sel1 : c_sel0) + ((P0 ? sel1 : sel0) ^ PXC0);
            int addr1 = (P0 ? c_sel0 : c_sel1) + ((P0 ? sel0 : sel1) ^ PXC1);
            tf[addr0] = mag0;
            tf[addr1] = mag1;
        }
    }
    __syncthreads();

    // residual + stats, in place (fp32)
    int i = tid & 7, strip = (tid >> 3) & 1, rb = tid >> 4;
    int gcolL = strip ? (120 - c0 + i) : (c0 + i);
    int cidxL = strip * 8 + i;
    const __half* x0p = g_x0h + (size_t)b * NDIM;
    float cs = 0.f, sq = 0.f;
    #pragma unroll
    for (int it = 0; it < 16; it++) {
        int r = rb + it * 32;
        float vv = tf[cidxL * 513 + r] + __half2float(x0p[r * NE + gcolL]);
        tf[cidxL * 513 + r] = vv;
        cs += vv;  sq += vv * vv;
    }
    cs += __shfl_down_sync(0xffffffffu, cs, 16);
    if (lane < 16) scolp[lane][w] = cs;
    #pragma unroll
    for (int o = 16; o; o >>= 1) sq += __shfl_down_sync(0xffffffffu, sq, o);
    if (lane == 0) atomicAdd(&ssacc, sq);
    __syncthreads();

    if (tid == 0) g_n1p[blockIdx.x] = ssacc;
    if (tid < 16) {
        float scv = 0.f;
        #pragma unroll
        for (int j = 0; j < 16; j++) scv += scolp[tid][j];
        int gc = (tid < 8) ? (c0 + tid) : (112 - c0 + tid);
        g_mA[b * NE + gc] = scv;
    }

    // reload x1 + D(phi)_2 in half2
    u32 pa2 = hsplat(pe2t[w].x), pb2 = hsplat(pe2t[w].y), pnb2 = hsplat(-pe2t[w].y);
    #pragma unroll
    for (int k = 0; k < 8; k++) {
        float a = tf[w * 513 + lane + 64*k];
        float c = tf[w * 513 + lane + 64*k + 32];
        u32 x1h = hpack(a, c);
        u32 tc = tscH[k*32 + lane], ts = tssH[k*32 + lane];
        u32 c12 = hfma2u(pa2, tc, hmul2u(pnb2, ts));
        u32 s12 = hfma2u(pb2, tc, hmul2u(pa2,  ts));
        Hx[k] = hmul2u(x1h, c12);
        Hy[k] = hmul2u(x1h, s12);
    }
    __syncthreads();   // tf fully consumed before tin16 (aliased) is written

    col_butterflyH(ryB, Hx, Hy, lane);

    // encode e4m3 into tin16 (warp w = output column cidx w)
    #pragma unroll
    for (int k = 0; k < 8; k++) {
        u32 hv0 = __byte_perm(Hx[k], Hy[k], 0x5410);
        u32 hv1 = __byte_perm(Hx[k], Hy[k], 0x7632);
        tin16[w * 522 + lane + 64*k]      = h2e(hv0);
        tin16[w * 522 + lane + 64*k + 32] = h2e(hv1);
    }
    __syncthreads();

    // staging-out: output cols are natural aligned pairs
    int m = i2 & 3;
    int cio  = (i2 < 4) ? (2*m) : (8 + 2*m);
    int wout = (i2 < 4) ? (c0/2 + m) : ((120 - c0)/2 + m);
    u32* stwo = g_state + (size_t)b * (NDIM / 2);
    #pragma unroll
    for (int it = 0; it < 8; it++) {
        int r = rb8 + 64 * it;
        u32 lo = tin16[cio * 522 + r];
        u32 hi = tin16[(cio+1) * 522 + r];
        stwo[r * 64 + wout] = lo | (hi << 16);
    }
}

// ---------------- rowB: B2 emb butterfly, 32 rows, fp8 in ----------------

__global__ __launch_bounds__(256) void k_rowB(const float* __restrict__ rp) {
    __shared__ __align__(16) u32 srow[32][68];
    __shared__ __align__(16) float ry[14];
    __shared__ float sred[128];
    __shared__ float s_inv1;
    int tid = threadIdx.x;
    int b = blockIdx.x >> 4;
    if (tid < 7) {
        float c, sn; sincosf(0.5f * rp[48 + (9 + tid) * 3], &sn, &c);
        ry[2*tid] = c; ry[2*tid+1] = sn;
    }
    if (tid == 32) {
        float t1 = 0.f;
        #pragma unroll
        for (int j = 0; j < 8; j++) t1 += g_n1p[b * 8 + j];
        s_inv1 = rsqrtf(t1);
    }
    __syncthreads();
    int warp = tid >> 5, lane = tid & 31, rl = lane >> 3, t = lane & 7;
    int rls = warp * 4 + rl;
    int row = blockIdx.x * 32 + rls;
    const uint4* src = (const uint4*)(g_state + (size_t)row * 64 + 8 * t);
    uint4 U0 = src[0], U1 = src[1];
    u32 wd[8] = {U0.x, U0.y, U0.z, U0.w, U1.x, U1.y, U1.z, U1.w};
    u32 Hx[8], Hy[8];
    #pragma unroll
    for (int k = 0; k < 8; k++) {
        u32 ha = e2h((u16)wd[k]);
        u32 hb = e2h((u16)(wd[k] >> 16));
        Hx[k] = __byte_perm(ha, hb, 0x5410);
        Hy[k] = __byte_perm(ha, hb, 0x7632);
    }

    row_butterflyH(ry, Hx, Hy, t);

    u32 hm[8];
    #pragma unroll
    for (int k = 0; k < 8; k++) {
        u32 msq = hfma2u(Hx[k], Hx[k], hmul2u(Hy[k], Hy[k]));
        hm[k] = h2u(h2sqrt(u2h(msq)));
    }
    uint4* wp = (uint4*)&srow[rls][8 * t];
    wp[0] = make_uint4(hm[0], hm[1], hm[2], hm[3]);
    wp[1] = make_uint4(hm[4], hm[5], hm[6], hm[7]);
    __syncthreads();

    int e = tid & 127, half = tid >> 7;
    int sbase = (blockIdx.x * 32) & (NS - 1);
    int ebase = e ^ (e >> 1);
    int p0 = (__popc(sbase) ^ half) & 1;
    int esA = ebase ^ (p0 << 6);
    int esB = esA ^ 64;
    const __half* srh = (const __half*)srow;
    float acc = 0.f;
    #pragma unroll
    for (int q = 0; q < 16; q++) {
        int r = half * 16 + q;
        int es = ((0x6996 >> q) & 1) ? esB : esA;
        acc += __half2float(srh[r * 136 + es]);
    }
    if (half == 1) sred[e] = acc;
    __syncthreads();
    if (half == 0) g_mB[blockIdx.x * NE + e] = (acc + sred[e]) * s_inv1;
}

// ---------------- W2 = clsw @ ffw (4x128), b2 = clsw @ ffb ----------------

__global__ __launch_bounds__(128) void k_w2(const float* __restrict__ ffw,
                                            const float* __restrict__ ffb,
                                            const float* __restrict__ clsw) {
    int c = blockIdx.x, e = threadIdx.x;
    float acc = 0.f;
    #pragma unroll 4
    for (int j = 0; j < 128; j++) acc += clsw[c * 128 + j] * ffw[j * 128 + e];
    g_W2[c * 128 + e] = acc;
    __shared__ float sb[128];
    sb[e] = clsw[c * 128 + e] * ffb[e];
    __syncthreads();
    #pragma unroll
    for (int o = 64; o; o >>= 1) {
        if (e < o) sb[e] += sb[e + o];
        __syncthreads();
    }
    if (e == 0) g_b2[c] = sb[0];
}

// ---------------- final: mean assembly + 4x128 dot ----------------

__global__ __launch_bounds__(256) void k_final(float* __restrict__ out) {
    int b = blockIdx.x, tid = threadIdx.x;
    __shared__ float mm[128];
    __shared__ float m2[256];
    int e = tid & 127, hi = tid >> 7;
    const float* mb = g_mB + (size_t)b * 16 * NE;
    float m = hi ? 0.f : g_mA[b * NE + e];
    #pragma unroll
    for (int i2 = 0; i2 < 8; i2++) m += mb[(hi * 8 + i2) * NE + e];
    m2[tid] = m;
    __syncthreads();
    if (hi == 0) mm[e] = (m + m2[e + 128]) * (1.f / 512.f);
    __syncthreads();
    int w = tid >> 5, lane = tid & 31;
    if (w < 4) {
        float acc = 0.f;
        #pragma unroll
        for (int q = 0; q < 4; q++) {
            int ee = lane + 32 * q;
            acc += mm[ee] * g_W2[w * 128 + ee];
        }
        #pragma unroll
        for (int o = 16; o; o >>= 1) acc += __shfl_down_sync(0xffffffffu, acc, o);
        if (lane == 0) out[b * 4 + w] = acc + g_b2[w];
    }
}

// ---------------- launch ----------------

extern "C" void kernel_launch(void* const* d_in, const int* in_sizes, int n_in,
                              void* d_out, int out_size) {
    const int*   tokens = (const int*)  d_in[0];
    const float* temb   = (const float*)d_in[1];
    const float* pemb   = (const float*)d_in[2];
    const float* rotp   = (const float*)d_in[3];
    const float* ffw    = (const float*)d_in[4];
    const float* ffb    = (const float*)d_in[5];
    const float* clsw   = (const float*)d_in[6];
    float* out = (float*)d_out;

    k_w2<<<4, 128>>>(ffw, ffb, clsw);
    k_embed_row<<<NB * NS / 64, 256>>>(tokens, temb, pemb, rotp);
    k_colA<<<NB * 8, 512>>>(rotp);
    k_rowB<<<NB * NS / 32, 256>>>(rotp);
    k_final<<<NB, 256>>>(out);
}

// round 16
// speedup vs baseline: 4.0076x; 1.0030x over previous
#include <cuda_runtime.h>
#include <cuda_fp16.h>
#include <cstdint>

// ----------------------------------------------------------------------------
// QFNet classifier, round 16: tan-form Givens butterflies.
//  Each Ry stage = c*(lo - t*hi), c*(hi + t*lo). The uniform per-stage c is
//  deferred: folded into phase tables (embed B1, colA A2 - free & prescaled)
//  or into the fp8-decode prescale (colA A1, rowB B2 - 1 mul/pack).
//  Stage update: 1 HFMA2 instead of HFMA2+HMUL2 -> ~2x fewer butterfly slots.
//  Everything else = R15 (fp8 state, smem aliasing, GF(2) addressing).
// ----------------------------------------------------------------------------

#define NB   256
#define NS   512
#define NE   128
#define NDIM 65536

typedef unsigned long long u64;
typedef unsigned int u32;
typedef unsigned short u16;

__device__ __align__(16) __half g_x0h[NB * NDIM];     // x0 fp16
__device__ __align__(16) u32 g_state[NB * NDIM / 2];  // e4m3 (re,im) x2 elems/word
__device__ float  g_n0p[NB * 8];
__device__ float  g_n1p[NB * 8];
__device__ float  g_mA[NB * NE];
__device__ float  g_mB[NB * 16 * NE];
__device__ float  g_W2[4 * NE];
__device__ float  g_b2[4];

// ---------------- helpers ----------------

__device__ __forceinline__ u32 h2u(__half2 h) { return *reinterpret_cast<u32*>(&h); }
__device__ __forceinline__ __half2 u2h(u32 u) { return *reinterpret_cast<__half2*>(&u); }
__device__ __forceinline__ float2 h22f2(u32 u) { return __half22float2(u2h(u)); }

__device__ __forceinline__ u16 h2e(u32 h) {
    u16 r;
    asm("cvt.rn.satfinite.e4m3x2.f16x2 %0, %1;" : "=h"(r) : "r"(h));
    return r;
}
__device__ __forceinline__ u32 e2h(u16 e) {
    u32 r;
    asm("cvt.rn.f16x2.e4m3x2 %0, %1;" : "=r"(r) : "h"(e));
    return r;
}

__device__ __forceinline__ constexpr int px9c(int x) {
    x ^= x >> 1; x ^= x >> 2; x ^= x >> 4; x ^= x >> 8; return x;
}

__device__ __forceinline__ float2 phase_s(const float* rp, int blk, int s) {
    float ang = 0.f;
    #pragma unroll
    for (int w = 0; w < 9; w++) {
        float ph = rp[blk * 48 + w * 3 + 1];
        ang += ((s >> (8 - w)) & 1) ? ph : -ph;
    }
    float c, sn; sincosf(0.5f * ang, &sn, &c);
    return make_float2(c, sn);
}
__device__ __forceinline__ float2 phase_e(const float* rp, int blk, int e) {
    float ang = 0.f;
    #pragma unroll
    for (int w = 9; w < 16; w++) {
        float ph = rp[blk * 48 + w * 3 + 1];
        ang += ((e >> (15 - w)) & 1) ? ph : -ph;
    }
    float c, sn; sincosf(0.5f * ang, &sn, &c);
    return make_float2(c, sn);
}

// ---------------- half2 primitives ----------------

__device__ __forceinline__ u32 hfma2u(u32 a, u32 b, u32 c) {
    return h2u(__hfma2(u2h(a), u2h(b), u2h(c)));
}
__device__ __forceinline__ u32 hmul2u(u32 a, u32 b) {
    return h2u(__hmul2(u2h(a), u2h(b)));
}
__device__ __forceinline__ u32 hswap(u32 v) { return (v >> 16) | (v << 16); }
__device__ __forceinline__ u32 hsplat(float v) { return h2u(__float2half2_rn(v)); }
__device__ __forceinline__ u32 hpack(float lo, float hi) {
    return h2u(__floats2half2_rn(lo, hi));
}

// ---------------- tan-form Ry butterfly stages ----------------
// lo' = lo - t*hi ; hi' = hi + t*lo   (true result scaled by 1/c; c deferred)

__device__ __forceinline__ void bpairT(u32 t2, u32 n2,
                                       u32& Lx, u32& Ly, u32& Hx, u32& Hy) {
    u32 ax = hfma2u(n2, Hx, Lx);
    u32 ay = hfma2u(n2, Hy, Ly);
    u32 bx = hfma2u(t2, Lx, Hx);
    u32 by = hfma2u(t2, Ly, Hy);
    Lx = ax; Ly = ay; Hx = bx; Hy = by;
}
__device__ __forceinline__ void bshufT(u32 Bt, u32& X, u32& Y, int ls) {
    u32 px = __shfl_xor_sync(0xffffffffu, X, ls);
    u32 py = __shfl_xor_sync(0xffffffffu, Y, ls);
    X = hfma2u(Bt, px, X);
    Y = hfma2u(Bt, py, Y);
}
__device__ __forceinline__ void bpackT(u32 Bp, u32& X, u32& Y) {
    X = hfma2u(Bp, hswap(X), X);
    Y = hfma2u(Bp, hswap(Y), Y);
}

// 7-stage embed butterfly (tan form). rt[w-9] = tan(theta_w/2), wires 9..15.
__device__ __forceinline__ void row_butterflyT(const float* rt, u32 Hx[8], u32 Hy[8], int t) {
    { u32 t2=hsplat(rt[3]), n2=hsplat(-rt[3]);      // wire12, e bit3
      #pragma unroll
      for (int k = 0; k < 4; k++) bpairT(t2,n2, Hx[k],Hy[k], Hx[k+4],Hy[k+4]); }
    { u32 t2=hsplat(rt[4]), n2=hsplat(-rt[4]);      // wire13, e bit2
      bpairT(t2,n2,Hx[0],Hy[0],Hx[2],Hy[2]); bpairT(t2,n2,Hx[1],Hy[1],Hx[3],Hy[3]);
      bpairT(t2,n2,Hx[4],Hy[4],Hx[6],Hy[6]); bpairT(t2,n2,Hx[5],Hy[5],Hx[7],Hy[7]); }
    { u32 t2=hsplat(rt[5]), n2=hsplat(-rt[5]);      // wire14, e bit1
      bpairT(t2,n2,Hx[0],Hy[0],Hx[1],Hy[1]); bpairT(t2,n2,Hx[2],Hy[2],Hx[3],Hy[3]);
      bpairT(t2,n2,Hx[4],Hy[4],Hx[5],Hy[5]); bpairT(t2,n2,Hx[6],Hy[6],Hx[7],Hy[7]); }
    { u32 Bp = hpack(-rt[6], rt[6]);                 // wire15, e bit0
      #pragma unroll
      for (int k = 0; k < 8; k++) bpackT(Bp, Hx[k], Hy[k]); }
    { u32 Bt = hsplat((t&1) ? rt[2] : -rt[2]);       // wire11, bit4
      #pragma unroll
      for (int k = 0; k < 8; k++) bshufT(Bt, Hx[k], Hy[k], 1); }
    { u32 Bt = hsplat((t&2) ? rt[1] : -rt[1]);       // wire10, bit5
      #pragma unroll
      for (int k = 0; k < 8; k++) bshufT(Bt, Hx[k], Hy[k], 2); }
    { u32 Bt = hsplat((t&4) ? rt[0] : -rt[0]);       // wire9, bit6
      #pragma unroll
      for (int k = 0; k < 8; k++) bshufT(Bt, Hx[k], Hy[k], 4); }
}

// 9-stage seq butterfly (tan form). ct[w] = tan(theta_w/2), wires 0..8.
__device__ __forceinline__ void col_butterflyT(const float* ct, u32 Hx[8], u32 Hy[8], int lane) {
    { u32 t2=hsplat(ct[0]), n2=hsplat(-ct[0]);      // wire0, s bit8
      #pragma unroll
      for (int k = 0; k < 4; k++) bpairT(t2,n2, Hx[k],Hy[k], Hx[k+4],Hy[k+4]); }
    { u32 t2=hsplat(ct[1]), n2=hsplat(-ct[1]);      // wire1, s bit7
      bpairT(t2,n2,Hx[0],Hy[0],Hx[2],Hy[2]); bpairT(t2,n2,Hx[1],Hy[1],Hx[3],Hy[3]);
      bpairT(t2,n2,Hx[4],Hy[4],Hx[6],Hy[6]); bpairT(t2,n2,Hx[5],Hy[5],Hx[7],Hy[7]); }
    { u32 t2=hsplat(ct[2]), n2=hsplat(-ct[2]);      // wire2, s bit6
      bpairT(t2,n2,Hx[0],Hy[0],Hx[1],Hy[1]); bpairT(t2,n2,Hx[2],Hy[2],Hx[3],Hy[3]);
      bpairT(t2,n2,Hx[4],Hy[4],Hx[5],Hy[5]); bpairT(t2,n2,Hx[6],Hy[6],Hx[7],Hy[7]); }
    { u32 Bp = hpack(-ct[3], ct[3]);                 // wire3, s bit5
      #pragma unroll
      for (int k = 0; k < 8; k++) bpackT(Bp, Hx[k], Hy[k]); }
    #pragma unroll
    for (int st = 0; st < 5; st++) {                 // wires 4..8, ls 16..1
        int ls = 16 >> st;
        float tv = ct[4 + st];
        u32 Bt = hsplat((lane & ls) ? tv : -tv);
        #pragma unroll
        for (int k = 0; k < 8; k++) bshufT(Bt, Hx[k], Hy[k], ls);
    }
}

// ---------------- embed + D(phi)_1 + B1 emb butterfly, 64 rows, fp8 out ----
// PC_B1 (prod of cos) folded into the emb-phase tables: inputs prescaled.

__global__ __launch_bounds__(256) void k_embed_row(const int* __restrict__ tokens,
                                                   const float* __restrict__ temb,
                                                   const float* __restrict__ pemb,
                                                   const float* __restrict__ rp) {
    __shared__ __align__(16) float ryt[7];
    __shared__ __align__(8) u32 epcH[64], epsH[64];
    __shared__ float2 psrow[64];
    __shared__ float wss[8];
    int tid = threadIdx.x;
    if (tid < 7) {
        float c, sn; sincosf(0.5f * rp[(9 + tid) * 3], &sn, &c);
        ryt[tid] = sn / c;
    }
    if (tid < 64) {
        float pc = 1.f;
        #pragma unroll
        for (int w = 9; w < 16; w++) pc *= cosf(0.5f * rp[w * 3]);
        int e0 = 16 * (tid >> 3) + 2 * (tid & 7);
        float2 A = phase_e(rp, 0, e0), B = phase_e(rp, 0, e0 + 1);
        epcH[tid] = hpack(A.x * pc, B.x * pc);
        epsH[tid] = hpack(A.y * pc, B.y * pc);
    }
    if (tid >= 64 && tid < 128) {
        int r = tid - 64;
        psrow[r] = phase_s(rp, 0, (blockIdx.x * 64 + r) & (NS - 1));
    }
    __syncthreads();
    int warp = tid >> 5, lane = tid & 31, rl = lane >> 3, t = lane & 7;
    float ss = 0.f;
    #pragma unroll
    for (int it2 = 0; it2 < 2; it2++) {
        int rlocal = it2 * 32 + warp * 4 + rl;
        int row = blockIdx.x * 64 + rlocal;
        int tok = tokens[row];
        const float4* te  = (const float4*)(temb + (size_t)tok * NE + 16 * t);
        const float4* pe4 = (const float4*)(pemb + (size_t)(row & (NS-1)) * NE + 16 * t);
        float v[16];
        #pragma unroll
        for (int q = 0; q < 4; q++) {
            float4 a = te[q], b = pe4[q];
            float v0 = a.x + b.x, v1 = a.y + b.y, v2 = a.z + b.z, v3 = a.w + b.w;
            ss += v0*v0 + v1*v1 + v2*v2 + v3*v3;
            v[4*q] = v0; v[4*q+1] = v1; v[4*q+2] = v2; v[4*q+3] = v3;
        }
        u32 xh[8];
        #pragma unroll
        for (int k = 0; k < 8; k++) xh[k] = hpack(v[2*k], v[2*k+1]);
        uint4* gx = (uint4*)(g_x0h + (size_t)row * NE + 16 * t);
        gx[0] = make_uint4(xh[0], xh[1], xh[2], xh[3]);
        gx[1] = make_uint4(xh[4], xh[5], xh[6], xh[7]);

        float2 psv = psrow[rlocal];
        u32 a2h = hsplat(psv.x), b2h = hsplat(psv.y), nb2h = hsplat(-psv.y);
        u32 Hx[8], Hy[8];
        #pragma unroll
        for (int k = 0; k < 8; k++) {
            u32 tc = epcH[t*8+k], ts = epsH[t*8+k];
            u32 c1 = hfma2u(a2h, tc, hmul2u(nb2h, ts));
            u32 s1 = hfma2u(b2h, tc, hmul2u(a2h,  ts));
            Hx[k] = hmul2u(xh[k], c1);
            Hy[k] = hmul2u(xh[k], s1);
        }

        row_butterflyT(ryt, Hx, Hy, t);

        u32 wd[8];
        #pragma unroll
        for (int k = 0; k < 8; k++) {
            u32 hv0 = __byte_perm(Hx[k], Hy[k], 0x5410);
            u32 hv1 = __byte_perm(Hx[k], Hy[k], 0x7632);
            wd[k] = (u32)h2e(hv0) | ((u32)h2e(hv1) << 16);
        }
        uint4* dst = (uint4*)(g_state + (size_t)row * 64 + 8 * t);
        dst[0] = make_uint4(wd[0], wd[1], wd[2], wd[3]);
        dst[1] = make_uint4(wd[4], wd[5], wd[6], wd[7]);
    }
    #pragma unroll
    for (int o = 16; o; o >>= 1) ss += __shfl_down_sync(0xffffffffu, ss, o);
    if (lane == 0) wss[warp] = ss;
    __syncthreads();
    if (tid == 0) {
        float tot = 0.f;
        #pragma unroll
        for (int q = 0; q < 8; q++) tot += wss[q];
        g_n0p[blockIdx.x] = tot;      // blockIdx = b*8 + grp
    }
}

// ---------------- colA: A1 + perm + residual + D(phi)_2 + A2 ----------------
// A1: PC_A1 applied as fp8-decode prescale. A2: PC_A2 folded into pe2t.

__global__ __launch_bounds__(512) void k_colA(const float* __restrict__ rp) {
    __shared__ __align__(16) float ctA[9], ctB[9];
    __shared__ __align__(8) u32 tscH[256], tssH[256];
    __shared__ __align__(16) char sbuf[16 * 513 * 4];   // union: tin16 / tf
    __shared__ float scolp[16][17];
    __shared__ float ssacc;
    __shared__ float s_inv0;
    __shared__ float s_pcA1;
    __shared__ float2 pe2t[16];
    u16*   tin16 = reinterpret_cast<u16*>(sbuf);        // stride 522
    float* tf    = reinterpret_cast<float*>(sbuf);      // stride 513

    int tid = threadIdx.x;
    int b = blockIdx.x >> 3, grp = blockIdx.x & 7, c0 = grp * 8;
    if (tid < 18) {
        int blk = tid / 9, wi = tid % 9;
        float c, sn; sincosf(0.5f * rp[blk * 48 + wi * 3], &sn, &c);
        if (blk == 0) ctA[wi] = sn / c; else ctB[wi] = sn / c;
    }
    if (tid == 0)  ssacc = 0.f;
    if (tid < 256) {
        int k = tid >> 5, l = tid & 31;
        float2 A = phase_s(rp, 1, l + 64*k), B = phase_s(rp, 1, l + 64*k + 32);
        tscH[tid] = hpack(A.x, B.x);
        tssH[tid] = hpack(A.y, B.y);
    }
    if (tid >= 256 && tid < 272) {
        int i2 = tid - 256;
        float pc = 1.f;
        #pragma unroll
        for (int w = 0; w < 9; w++) pc *= cosf(0.5f * rp[48 + w * 3]);
        int gc = (i2 < 8) ? (c0 + i2) : (112 - c0 + i2);
        float2 P = phase_e(rp, 1, gc);
        pe2t[i2] = make_float2(P.x * pc, P.y * pc);
    }
    if (tid == 272) {
        float t0 = 0.f;
        #pragma unroll
        for (int j = 0; j < 8; j++) t0 += g_n0p[b * 8 + j];
        s_inv0 = rsqrtf(t0);
    }
    if (tid == 273) {
        float pc = 1.f;
        #pragma unroll
        for (int w = 0; w < 9; w++) pc *= cosf(0.5f * rp[w * 3]);
        s_pcA1 = pc;
    }

    // staging-in: u32 = 2 adjacent SOURCE cols; dest slot via inverse-gray
    int i2 = tid & 7, rb8 = tid >> 3;
    int gg = grp ^ (grp >> 1);
    int widx = (i2 < 4) ? (4*gg + i2) : (4*gg + 32 + (i2 - 4));
    int sc = widx * 2;
    int gc0 = sc; gc0 ^= gc0 >> 1; gc0 ^= gc0 >> 2; gc0 ^= gc0 >> 4;   // invgray
    int ci0 = (i2 < 4) ? (gc0 - c0) : (8 + gc0 - (120 - c0));
    const u32* stw = g_state + (size_t)b * (NDIM / 2);
    #pragma unroll
    for (int it = 0; it < 8; it++) {
        int r = rb8 + 64 * it;
        u32 wv = stw[r * 64 + widx];
        tin16[ci0 * 522 + r]       = (u16)wv;
        tin16[(ci0^1) * 522 + r]   = (u16)(wv >> 16);
    }
    __syncthreads();
    float inv0 = s_inv0;
    u32 pca = hsplat(s_pcA1);
    int w = tid >> 5, lane = tid & 31;
    u32 Hx[8], Hy[8];
    #pragma unroll
    for (int k = 0; k < 8; k++) {
        u32 ha = e2h(tin16[w * 522 + lane + 64*k]);
        u32 hb = e2h(tin16[w * 522 + lane + 64*k + 32]);
        Hx[k] = hmul2u(pca, __byte_perm(ha, hb, 0x5410));
        Hy[k] = hmul2u(pca, __byte_perm(ha, hb, 0x7632));
    }
    __syncthreads();   // tin16 fully consumed before tf (aliased) is written

    col_butterflyT(ctA, Hx, Hy, lane);

    // CNOT perm + |.|*inv0 scatter into tf (GF(2) addressing, verified)
    int colw = (w < 8) ? (c0 + w) : (112 - c0 + w);
    {
        int pxl = lane ^ (lane >> 1); pxl ^= pxl >> 2; pxl ^= pxl >> 4;
        int parl = __popc(lane) & 1;
        int lowb = colw & 1;
        int c_sel0 = (parl ? (15 - w) : w) * 513;
        int c_sel1 = (parl ? w : (15 - w)) * 513;
        int sel0 = pxl ^ ((lowb ^ parl) << 8);
        int sel1 = pxl ^ ((lowb ^ parl ^ 1) << 8);
        #pragma unroll
        for (int k = 0; k < 8; k++) {
            u32 m2 = hfma2u(Hx[k], Hx[k], hmul2u(Hy[k], Hy[k]));
            u32 hm = h2u(h2sqrt(u2h(m2)));
            float2 mf = h22f2(hm);
            float mag0 = mf.x * inv0;
            float mag1 = mf.y * inv0;
            const int PXC0 = px9c(64 * k);
            const int PXC1 = px9c(64 * k + 32);
            const int P0 = __popc(k) & 1;
            int addr0 = (P0 ? c_sel1 : c_sel0) + ((P0 ? sel1 : sel0) ^ PXC0);
            int addr1 = (P0 ? c_sel0 : c_sel1) + ((P0 ? sel0 : sel1) ^ PXC1);
            tf[addr0] = mag0;
            tf[addr1] = mag1;
        }
    }
    __syncthreads();

    // residual + stats, in place (fp32)
    int i = tid & 7, strip = (tid >> 3) & 1, rb = tid >> 4;
    int gcolL = strip ? (120 - c0 + i) : (c0 + i);
    int cidxL = strip * 8 + i;
    const __half* x0p = g_x0h + (size_t)b * NDIM;
    float cs = 0.f, sq = 0.f;
    #pragma unroll
    for (int it = 0; it < 16; it++) {
        int r = rb + it * 32;
        float vv = tf[cidxL * 513 + r] + __half2float(x0p[r * NE + gcolL]);
        tf[cidxL * 513 + r] = vv;
        cs += vv;  sq += vv * vv;
    }
    cs += __shfl_down_sync(0xffffffffu, cs, 16);
    if (lane < 16) scolp[lane][w] = cs;
    #pragma unroll
    for (int o = 16; o; o >>= 1) sq += __shfl_down_sync(0xffffffffu, sq, o);
    if (lane == 0) atomicAdd(&ssacc, sq);
    __syncthreads();

    if (tid == 0) g_n1p[blockIdx.x] = ssacc;
    if (tid < 16) {
        float scv = 0.f;
        #pragma unroll
        for (int j = 0; j < 16; j++) scv += scolp[tid][j];
        int gc = (tid < 8) ? (c0 + tid) : (112 - c0 + tid);
        g_mA[b * NE + gc] = scv;
    }

    // reload x1 + D(phi)_2 in half2 (pe2t pre-scaled by PC_A2)
    u32 pa2 = hsplat(pe2t[w].x), pb2 = hsplat(pe2t[w].y), pnb2 = hsplat(-pe2t[w].y);
    #pragma unroll
    for (int k = 0; k < 8; k++) {
        float a = tf[w * 513 + lane + 64*k];
        float c = tf[w * 513 + lane + 64*k + 32];
        u32 x1h = hpack(a, c);
        u32 tc = tscH[k*32 + lane], ts = tssH[k*32 + lane];
        u32 c12 = hfma2u(pa2, tc, hmul2u(pnb2, ts));
        u32 s12 = hfma2u(pb2, tc, hmul2u(pa2,  ts));
        Hx[k] = hmul2u(x1h, c12);
        Hy[k] = hmul2u(x1h, s12);
    }
    __syncthreads();   // tf fully consumed before tin16 (aliased) is written

    col_butterflyT(ctB, Hx, Hy, lane);

    // encode e4m3 into tin16 (warp w = output column cidx w)
    #pragma unroll
    for (int k = 0; k < 8; k++) {
        u32 hv0 = __byte_perm(Hx[k], Hy[k], 0x5410);
        u32 hv1 = __byte_perm(Hx[k], Hy[k], 0x7632);
        tin16[w * 522 + lane + 64*k]      = h2e(hv0);
        tin16[w * 522 + lane + 64*k + 32] = h2e(hv1);
    }
    __syncthreads();

    // staging-out: output cols are natural aligned pairs
    int m = i2 & 3;
    int cio  = (i2 < 4) ? (2*m) : (8 + 2*m);
    int wout = (i2 < 4) ? (c0/2 + m) : ((120 - c0)/2 + m);
    u32* stwo = g_state + (size_t)b * (NDIM / 2);
    #pragma unroll
    for (int it = 0; it < 8; it++) {
        int r = rb8 + 64 * it;
        u32 lo = tin16[cio * 522 + r];
        u32 hi = tin16[(cio+1) * 522 + r];
        stwo[r * 64 + wout] = lo | (hi << 16);
    }
}

// ---------------- rowB: B2 emb butterfly, 32 rows, fp8 in ----------------
// PC_B2 applied as fp8-decode prescale.

__global__ __launch_bounds__(256) void k_rowB(const float* __restrict__ rp) {
    __shared__ __align__(16) u32 srow[32][68];
    __shared__ __align__(16) float ryt[7];
    __shared__ float sred[128];
    __shared__ float s_inv1;
    __shared__ float s_pcB2;
    int tid = threadIdx.x;
    int b = blockIdx.x >> 4;
    if (tid < 7) {
        float c, sn; sincosf(0.5f * rp[48 + (9 + tid) * 3], &sn, &c);
        ryt[tid] = sn / c;
    }
    if (tid == 32) {
        float t1 = 0.f;
        #pragma unroll
        for (int j = 0; j < 8; j++) t1 += g_n1p[b * 8 + j];
        s_inv1 = rsqrtf(t1);
    }
    if (tid == 33) {
        float pc = 1.f;
        #pragma unroll
        for (int w = 9; w < 16; w++) pc *= cosf(0.5f * rp[48 + w * 3]);
        s_pcB2 = pc;
    }
    __syncthreads();
    int warp = tid >> 5, lane = tid & 31, rl = lane >> 3, t = lane & 7;
    int rls = warp * 4 + rl;
    int row = blockIdx.x * 32 + rls;
    u32 pcb = hsplat(s_pcB2);
    const uint4* src = (const uint4*)(g_state + (size_t)row * 64 + 8 * t);
    uint4 U0 = src[0], U1 = src[1];
    u32 wd[8] = {U0.x, U0.y, U0.z, U0.w, U1.x, U1.y, U1.z, U1.w};
    u32 Hx[8], Hy[8];
    #pragma unroll
    for (int k = 0; k < 8; k++) {
        u32 ha = e2h((u16)wd[k]);
        u32 hb = e2h((u16)(wd[k] >> 16));
        Hx[k] = hmul2u(pcb, __byte_perm(ha, hb, 0x5410));
        Hy[k] = hmul2u(pcb, __byte_perm(ha, hb, 0x7632));
    }

    row_butterflyT(ryt, Hx, Hy, t);

    u32 hm[8];
    #pragma unroll
    for (int k = 0; k < 8; k++) {
        u32 msq = hfma2u(Hx[k], Hx[k], hmul2u(Hy[k], Hy[k]));
        hm[k] = h2u(h2sqrt(u2h(msq)));
    }
    uint4* wp = (uint4*)&srow[rls][8 * t];
    wp[0] = make_uint4(hm[0], hm[1], hm[2], hm[3]);
    wp[1] = make_uint4(hm[4], hm[5], hm[6], hm[7]);
    __syncthreads();

    int e = tid & 127, half = tid >> 7;
    int sbase = (blockIdx.x * 32) & (NS - 1);
    int ebase = e ^ (e >> 1);
    int p0 = (__popc(sbase) ^ half) & 1;
    int esA = ebase ^ (p0 << 6);
    int esB = esA ^ 64;
    const __half* srh = (const __half*)srow;
    float acc = 0.f;
    #pragma unroll
    for (int q = 0; q < 16; q++) {
        int r = half * 16 + q;
        int es = ((0x6996 >> q) & 1) ? esB : esA;
        acc += __half2float(srh[r * 136 + es]);
    }
    if (half == 1) sred[e] = acc;
    __syncthreads();
    if (half == 0) g_mB[blockIdx.x * NE + e] = (acc + sred[e]) * s_inv1;
}

// ---------------- W2 = clsw @ ffw (4x128), b2 = clsw @ ffb ----------------

__global__ __launch_bounds__(128) void k_w2(const float* __restrict__ ffw,
                                            const float* __restrict__ ffb,
                                            const float* __restrict__ clsw) {
    int c = blockIdx.x, e = threadIdx.x;
    float acc = 0.f;
    #pragma unroll 4
    for (int j = 0; j < 128; j++) acc += clsw[c * 128 + j] * ffw[j * 128 + e];
    g_W2[c * 128 + e] = acc;
    __shared__ float sb[128];
    sb[e] = clsw[c * 128 + e] * ffb[e];
    __syncthreads();
    #pragma unroll
    for (int o = 64; o; o >>= 1) {
        if (e < o) sb[e] += sb[e + o];
        __syncthreads();
    }
    if (e == 0) g_b2[c] = sb[0];
}

// ---------------- final: mean assembly + 4x128 dot ----------------

__global__ __launch_bounds__(256) void k_final(float* __restrict__ out) {
    int b = blockIdx.x, tid = threadIdx.x;
    __shared__ float mm[128];
    __shared__ float m2[256];
    int e = tid & 127, hi = tid >> 7;
    const float* mb = g_mB + (size_t)b * 16 * NE;
    float m = hi ? 0.f : g_mA[b * NE + e];
    #pragma unroll
    for (int i2 = 0; i2 < 8; i2++) m += mb[(hi * 8 + i2) * NE + e];
    m2[tid] = m;
    __syncthreads();
    if (hi == 0) mm[e] = (m + m2[e + 128]) * (1.f / 512.f);
    __syncthreads();
    int w = tid >> 5, lane = tid & 31;
    if (w < 4) {
        float acc = 0.f;
        #pragma unroll
        for (int q = 0; q < 4; q++) {
            int ee = lane + 32 * q;
            acc += mm[ee] * g_W2[w * 128 + ee];
        }
        #pragma unroll
        for (int o = 16; o; o >>= 1) acc += __shfl_down_sync(0xffffffffu, acc, o);
        if (lane == 0) out[b * 4 + w] = acc + g_b2[w];
    }
}

// ---------------- launch ----------------

extern "C" void kernel_launch(void* const* d_in, const int* in_sizes, int n_in,
                              void* d_out, int out_size) {
    const int*   tokens = (const int*)  d_in[0];
    const float* temb   = (const float*)d_in[1];
    const float* pemb   = (const float*)d_in[2];
    const float* rotp   = (const float*)d_in[3];
    const float* ffw    = (const float*)d_in[4];
    const float* ffb    = (const float*)d_in[5];
    const float* clsw   = (const float*)d_in[6];
    float* out = (float*)d_out;

    k_w2<<<4, 128>>>(ffw, ffb, clsw);
    k_embed_row<<<NB * NS / 64, 256>>>(tokens, temb, pemb, rotp);
    k_colA<<<NB * 8, 512>>>(rotp);
    k_rowB<<<NB * NS / 32, 256>>>(rotp);
    k_final<<<NB, 256>>>(out);
}

// round 17
// speedup vs baseline: 4.6320x; 1.1558x over previous
#include <cuda_runtime.h>
#include <cuda_fp16.h>
#include <cstdint>

// ----------------------------------------------------------------------------
// QFNet classifier, round 17:
//  - Programmatic Dependent Launch across the chain: successor kernels carry
//    the PSS attribute, do their rp-only table prologues, then
//    griddepcontrol.wait before touching predecessor data. Predecessors issue
//    launch_dependents at kernel top. Overlaps prologues with drain tails.
//  - rowB reduction via gray-pair half2 word loads (8 LDS instead of 16).
//  - everything else = R16 (tan-form butterflies, fp8 state, smem aliasing).
// ----------------------------------------------------------------------------

#define NB   256
#define NS   512
#define NE   128
#define NDIM 65536

typedef unsigned long long u64;
typedef unsigned int u32;
typedef unsigned short u16;

#define GDC_LAUNCH() asm volatile("griddepcontrol.launch_dependents;" ::: "memory")
#define GDC_WAIT()   asm volatile("griddepcontrol.wait;" ::: "memory")

__device__ __align__(16) __half g_x0h[NB * NDIM];     // x0 fp16
__device__ __align__(16) u32 g_state[NB * NDIM / 2];  // e4m3 (re,im) x2 elems/word
__device__ float  g_n0p[NB * 8];
__device__ float  g_n1p[NB * 8];
__device__ float  g_mA[NB * NE];
__device__ float  g_mB[NB * 16 * NE];
__device__ float  g_W2[4 * NE];
__device__ float  g_b2[4];

// ---------------- helpers ----------------

__device__ __forceinline__ u32 h2u(__half2 h) { return *reinterpret_cast<u32*>(&h); }
__device__ __forceinline__ __half2 u2h(u32 u) { return *reinterpret_cast<__half2*>(&u); }
__device__ __forceinline__ float2 h22f2(u32 u) { return __half22float2(u2h(u)); }

__device__ __forceinline__ u16 h2e(u32 h) {
    u16 r;
    asm("cvt.rn.satfinite.e4m3x2.f16x2 %0, %1;" : "=h"(r) : "r"(h));
    return r;
}
__device__ __forceinline__ u32 e2h(u16 e) {
    u32 r;
    asm("cvt.rn.f16x2.e4m3x2 %0, %1;" : "=r"(r) : "h"(e));
    return r;
}

__device__ __forceinline__ constexpr int px9c(int x) {
    x ^= x >> 1; x ^= x >> 2; x ^= x >> 4; x ^= x >> 8; return x;
}

__device__ __forceinline__ float2 phase_s(const float* rp, int blk, int s) {
    float ang = 0.f;
    #pragma unroll
    for (int w = 0; w < 9; w++) {
        float ph = rp[blk * 48 + w * 3 + 1];
        ang += ((s >> (8 - w)) & 1) ? ph : -ph;
    }
    float c, sn; sincosf(0.5f * ang, &sn, &c);
    return make_float2(c, sn);
}
__device__ __forceinline__ float2 phase_e(const float* rp, int blk, int e) {
    float ang = 0.f;
    #pragma unroll
    for (int w = 9; w < 16; w++) {
        float ph = rp[blk * 48 + w * 3 + 1];
        ang += ((e >> (15 - w)) & 1) ? ph : -ph;
    }
    float c, sn; sincosf(0.5f * ang, &sn, &c);
    return make_float2(c, sn);
}

// ---------------- half2 primitives ----------------

__device__ __forceinline__ u32 hfma2u(u32 a, u32 b, u32 c) {
    return h2u(__hfma2(u2h(a), u2h(b), u2h(c)));
}
__device__ __forceinline__ u32 hmul2u(u32 a, u32 b) {
    return h2u(__hmul2(u2h(a), u2h(b)));
}
__device__ __forceinline__ u32 hadd2u(u32 a, u32 b) {
    return h2u(__hadd2(u2h(a), u2h(b)));
}
__device__ __forceinline__ u32 hswap(u32 v) { return (v >> 16) | (v << 16); }
__device__ __forceinline__ u32 hsplat(float v) { return h2u(__float2half2_rn(v)); }
__device__ __forceinline__ u32 hpack(float lo, float hi) {
    return h2u(__floats2half2_rn(lo, hi));
}

// ---------------- tan-form Ry butterfly stages ----------------

__device__ __forceinline__ void bpairT(u32 t2, u32 n2,
                                       u32& Lx, u32& Ly, u32& Hx, u32& Hy) {
    u32 ax = hfma2u(n2, Hx, Lx);
    u32 ay = hfma2u(n2, Hy, Ly);
    u32 bx = hfma2u(t2, Lx, Hx);
    u32 by = hfma2u(t2, Ly, Hy);
    Lx = ax; Ly = ay; Hx = bx; Hy = by;
}
__device__ __forceinline__ void bshufT(u32 Bt, u32& X, u32& Y, int ls) {
    u32 px = __shfl_xor_sync(0xffffffffu, X, ls);
    u32 py = __shfl_xor_sync(0xffffffffu, Y, ls);
    X = hfma2u(Bt, px, X);
    Y = hfma2u(Bt, py, Y);
}
__device__ __forceinline__ void bpackT(u32 Bp, u32& X, u32& Y) {
    X = hfma2u(Bp, hswap(X), X);
    Y = hfma2u(Bp, hswap(Y), Y);
}

// 7-stage embed butterfly (tan form). rt[w-9] = tan(theta_w/2), wires 9..15.
__device__ __forceinline__ void row_butterflyT(const float* rt, u32 Hx[8], u32 Hy[8], int t) {
    { u32 t2=hsplat(rt[3]), n2=hsplat(-rt[3]);      // wire12, e bit3
      #pragma unroll
      for (int k = 0; k < 4; k++) bpairT(t2,n2, Hx[k],Hy[k], Hx[k+4],Hy[k+4]); }
    { u32 t2=hsplat(rt[4]), n2=hsplat(-rt[4]);      // wire13, e bit2
      bpairT(t2,n2,Hx[0],Hy[0],Hx[2],Hy[2]); bpairT(t2,n2,Hx[1],Hy[1],Hx[3],Hy[3]);
      bpairT(t2,n2,Hx[4],Hy[4],Hx[6],Hy[6]); bpairT(t2,n2,Hx[5],Hy[5],Hx[7],Hy[7]); }
    { u32 t2=hsplat(rt[5]), n2=hsplat(-rt[5]);      // wire14, e bit1
      bpairT(t2,n2,Hx[0],Hy[0],Hx[1],Hy[1]); bpairT(t2,n2,Hx[2],Hy[2],Hx[3],Hy[3]);
      bpairT(t2,n2,Hx[4],Hy[4],Hx[5],Hy[5]); bpairT(t2,n2,Hx[6],Hy[6],Hx[7],Hy[7]); }
    { u32 Bp = hpack(-rt[6], rt[6]);                 // wire15, e bit0
      #pragma unroll
      for (int k = 0; k < 8; k++) bpackT(Bp, Hx[k], Hy[k]); }
    { u32 Bt = hsplat((t&1) ? rt[2] : -rt[2]);       // wire11, bit4
      #pragma unroll
      for (int k = 0; k < 8; k++) bshufT(Bt, Hx[k], Hy[k], 1); }
    { u32 Bt = hsplat((t&2) ? rt[1] : -rt[1]);       // wire10, bit5
      #pragma unroll
      for (int k = 0; k < 8; k++) bshufT(Bt, Hx[k], Hy[k], 2); }
    { u32 Bt = hsplat((t&4) ? rt[0] : -rt[0]);       // wire9, bit6
      #pragma unroll
      for (int k = 0; k < 8; k++) bshufT(Bt, Hx[k], Hy[k], 4); }
}

// 9-stage seq butterfly (tan form). ct[w] = tan(theta_w/2), wires 0..8.
__device__ __forceinline__ void col_butterflyT(const float* ct, u32 Hx[8], u32 Hy[8], int lane) {
    { u32 t2=hsplat(ct[0]), n2=hsplat(-ct[0]);      // wire0, s bit8
      #pragma unroll
      for (int k = 0; k < 4; k++) bpairT(t2,n2, Hx[k],Hy[k], Hx[k+4],Hy[k+4]); }
    { u32 t2=hsplat(ct[1]), n2=hsplat(-ct[1]);      // wire1, s bit7
      bpairT(t2,n2,Hx[0],Hy[0],Hx[2],Hy[2]); bpairT(t2,n2,Hx[1],Hy[1],Hx[3],Hy[3]);
      bpairT(t2,n2,Hx[4],Hy[4],Hx[6],Hy[6]); bpairT(t2,n2,Hx[5],Hy[5],Hx[7],Hy[7]); }
    { u32 t2=hsplat(ct[2]), n2=hsplat(-ct[2]);      // wire2, s bit6
      bpairT(t2,n2,Hx[0],Hy[0],Hx[1],Hy[1]); bpairT(t2,n2,Hx[2],Hy[2],Hx[3],Hy[3]);
      bpairT(t2,n2,Hx[4],Hy[4],Hx[5],Hy[5]); bpairT(t2,n2,Hx[6],Hy[6],Hx[7],Hy[7]); }
    { u32 Bp = hpack(-ct[3], ct[3]);                 // wire3, s bit5
      #pragma unroll
      for (int k = 0; k < 8; k++) bpackT(Bp, Hx[k], Hy[k]); }
    #pragma unroll
    for (int st = 0; st < 5; st++) {                 // wires 4..8, ls 16..1
        int ls = 16 >> st;
        float tv = ct[4 + st];
        u32 Bt = hsplat((lane & ls) ? tv : -tv);
        #pragma unroll
        for (int k = 0; k < 8; k++) bshufT(Bt, Hx[k], Hy[k], ls);
    }
}

// ---------------- embed + D(phi)_1 + B1 emb butterfly, 64 rows, fp8 out ----

__global__ __launch_bounds__(256) void k_embed_row(const int* __restrict__ tokens,
                                                   const float* __restrict__ temb,
                                                   const float* __restrict__ pemb,
                                                   const float* __restrict__ rp) {
    GDC_LAUNCH();                    // let colA pre-launch into our drain tail
    __shared__ __align__(16) float ryt[7];
    __shared__ __align__(8) u32 epcH[64], epsH[64];
    __shared__ float2 psrow[64];
    __shared__ float wss[8];
    int tid = threadIdx.x;
    if (tid < 7) {
        float c, sn; sincosf(0.5f * rp[(9 + tid) * 3], &sn, &c);
        ryt[tid] = sn / c;
    }
    if (tid < 64) {
        float pc = 1.f;
        #pragma unroll
        for (int w = 9; w < 16; w++) pc *= cosf(0.5f * rp[w * 3]);
        int e0 = 16 * (tid >> 3) + 2 * (tid & 7);
        float2 A = phase_e(rp, 0, e0), B = phase_e(rp, 0, e0 + 1);
        epcH[tid] = hpack(A.x * pc, B.x * pc);
        epsH[tid] = hpack(A.y * pc, B.y * pc);
    }
    if (tid >= 64 && tid < 128) {
        int r = tid - 64;
        psrow[r] = phase_s(rp, 0, (blockIdx.x * 64 + r) & (NS - 1));
    }
    __syncthreads();
    int warp = tid >> 5, lane = tid & 31, rl = lane >> 3, t = lane & 7;
    float ss = 0.f;
    #pragma unroll
    for (int it2 = 0; it2 < 2; it2++) {
        int rlocal = it2 * 32 + warp * 4 + rl;
        int row = blockIdx.x * 64 + rlocal;
        int tok = tokens[row];
        const float4* te  = (const float4*)(temb + (size_t)tok * NE + 16 * t);
        const float4* pe4 = (const float4*)(pemb + (size_t)(row & (NS-1)) * NE + 16 * t);
        float v[16];
        #pragma unroll
        for (int q = 0; q < 4; q++) {
            float4 a = te[q], b = pe4[q];
            float v0 = a.x + b.x, v1 = a.y + b.y, v2 = a.z + b.z, v3 = a.w + b.w;
            ss += v0*v0 + v1*v1 + v2*v2 + v3*v3;
            v[4*q] = v0; v[4*q+1] = v1; v[4*q+2] = v2; v[4*q+3] = v3;
        }
        u32 xh[8];
        #pragma unroll
        for (int k = 0; k < 8; k++) xh[k] = hpack(v[2*k], v[2*k+1]);
        uint4* gx = (uint4*)(g_x0h + (size_t)row * NE + 16 * t);
        gx[0] = make_uint4(xh[0], xh[1], xh[2], xh[3]);
        gx[1] = make_uint4(xh[4], xh[5], xh[6], xh[7]);

        float2 psv = psrow[rlocal];
        u32 a2h = hsplat(psv.x), b2h = hsplat(psv.y), nb2h = hsplat(-psv.y);
        u32 Hx[8], Hy[8];
        #pragma unroll
        for (int k = 0; k < 8; k++) {
            u32 tc = epcH[t*8+k], ts = epsH[t*8+k];
            u32 c1 = hfma2u(a2h, tc, hmul2u(nb2h, ts));
            u32 s1 = hfma2u(b2h, tc, hmul2u(a2h,  ts));
            Hx[k] = hmul2u(xh[k], c1);
            Hy[k] = hmul2u(xh[k], s1);
        }

        row_butterflyT(ryt, Hx, Hy, t);

        u32 wd[8];
        #pragma unroll
        for (int k = 0; k < 8; k++) {
            u32 hv0 = __byte_perm(Hx[k], Hy[k], 0x5410);
            u32 hv1 = __byte_perm(Hx[k], Hy[k], 0x7632);
            wd[k] = (u32)h2e(hv0) | ((u32)h2e(hv1) << 16);
        }
        uint4* dst = (uint4*)(g_state + (size_t)row * 64 + 8 * t);
        dst[0] = make_uint4(wd[0], wd[1], wd[2], wd[3]);
        dst[1] = make_uint4(wd[4], wd[5], wd[6], wd[7]);
    }
    #pragma unroll
    for (int o = 16; o; o >>= 1) ss += __shfl_down_sync(0xffffffffu, ss, o);
    if (lane == 0) wss[warp] = ss;
    __syncthreads();
    if (tid == 0) {
        float tot = 0.f;
        #pragma unroll
        for (int q = 0; q < 8; q++) tot += wss[q];
        g_n0p[blockIdx.x] = tot;      // blockIdx = b*8 + grp
    }
}

// ---------------- colA: A1 + perm + residual + D(phi)_2 + A2 ----------------

__global__ __launch_bounds__(512) void k_colA(const float* __restrict__ rp) {
    GDC_LAUNCH();
    __shared__ __align__(16) float ctA[9], ctB[9];
    __shared__ __align__(8) u32 tscH[256], tssH[256];
    __shared__ __align__(16) char sbuf[16 * 513 * 4];   // union: tin16 / tf
    __shared__ float scolp[16][17];
    __shared__ float ssacc;
    __shared__ float s_inv0;
    __shared__ float s_pcA1;
    __shared__ float2 pe2t[16];
    u16*   tin16 = reinterpret_cast<u16*>(sbuf);        // stride 522
    float* tf    = reinterpret_cast<float*>(sbuf);      // stride 513

    int tid = threadIdx.x;
    int b = blockIdx.x >> 3, grp = blockIdx.x & 7, c0 = grp * 8;
    // ---- rp-only prologue (overlaps predecessor via PDL) ----
    if (tid < 18) {
        int blk = tid / 9, wi = tid % 9;
        float c, sn; sincosf(0.5f * rp[blk * 48 + wi * 3], &sn, &c);
        if (blk == 0) ctA[wi] = sn / c; else ctB[wi] = sn / c;
    }
    if (tid == 0)  ssacc = 0.f;
    if (tid < 256) {
        int k = tid >> 5, l = tid & 31;
        float2 A = phase_s(rp, 1, l + 64*k), B = phase_s(rp, 1, l + 64*k + 32);
        tscH[tid] = hpack(A.x, B.x);
        tssH[tid] = hpack(A.y, B.y);
    }
    if (tid >= 256 && tid < 272) {
        int i2 = tid - 256;
        float pc = 1.f;
        #pragma unroll
        for (int w = 0; w < 9; w++) pc *= cosf(0.5f * rp[48 + w * 3]);
        int gc = (i2 < 8) ? (c0 + i2) : (112 - c0 + i2);
        float2 P = phase_e(rp, 1, gc);
        pe2t[i2] = make_float2(P.x * pc, P.y * pc);
    }
    if (tid == 273) {
        float pc = 1.f;
        #pragma unroll
        for (int w = 0; w < 9; w++) pc *= cosf(0.5f * rp[w * 3]);
        s_pcA1 = pc;
    }

    GDC_WAIT();   // predecessor (embed) data visible after this

    if (tid == 272) {
        float t0 = 0.f;
        #pragma unroll
        for (int j = 0; j < 8; j++) t0 += g_n0p[b * 8 + j];
        s_inv0 = rsqrtf(t0);
    }

    // staging-in: u32 = 2 adjacent SOURCE cols; dest slot via inverse-gray
    int i2 = tid & 7, rb8 = tid >> 3;
    int gg = grp ^ (grp >> 1);
    int widx = (i2 < 4) ? (4*gg + i2) : (4*gg + 32 + (i2 - 4));
    int sc = widx * 2;
    int gc0 = sc; gc0 ^= gc0 >> 1; gc0 ^= gc0 >> 2; gc0 ^= gc0 >> 4;   // invgray
    int ci0 = (i2 < 4) ? (gc0 - c0) : (8 + gc0 - (120 - c0));
    const u32* stw = g_state + (size_t)b * (NDIM / 2);
    #pragma unroll
    for (int it = 0; it < 8; it++) {
        int r = rb8 + 64 * it;
        u32 wv = stw[r * 64 + widx];
        tin16[ci0 * 522 + r]       = (u16)wv;
        tin16[(ci0^1) * 522 + r]   = (u16)(wv >> 16);
    }
    __syncthreads();
    float inv0 = s_inv0;
    u32 pca = hsplat(s_pcA1);
    int w = tid >> 5, lane = tid & 31;
    u32 Hx[8], Hy[8];
    #pragma unroll
    for (int k = 0; k < 8; k++) {
        u32 ha = e2h(tin16[w * 522 + lane + 64*k]);
        u32 hb = e2h(tin16[w * 522 + lane + 64*k + 32]);
        Hx[k] = hmul2u(pca, __byte_perm(ha, hb, 0x5410));
        Hy[k] = hmul2u(pca, __byte_perm(ha, hb, 0x7632));
    }
    __syncthreads();   // tin16 fully consumed before tf (aliased) is written

    col_butterflyT(ctA, Hx, Hy, lane);

    // CNOT perm + |.|*inv0 scatter into tf (GF(2) addressing, verified)
    int colw = (w < 8) ? (c0 + w) : (112 - c0 + w);
    {
        int pxl = lane ^ (lane >> 1); pxl ^= pxl >> 2; pxl ^= pxl >> 4;
        int parl = __popc(lane) & 1;
        int lowb = colw & 1;
        int c_sel0 = (parl ? (15 - w) : w) * 513;
        int c_sel1 = (parl ? w : (15 - w)) * 513;
        int sel0 = pxl ^ ((lowb ^ parl) << 8);
        int sel1 = pxl ^ ((lowb ^ parl ^ 1) << 8);
        #pragma unroll
        for (int k = 0; k < 8; k++) {
            u32 m2 = hfma2u(Hx[k], Hx[k], hmul2u(Hy[k], Hy[k]));
            u32 hm = h2u(h2sqrt(u2h(m2)));
            float2 mf = h22f2(hm);
            float mag0 = mf.x * inv0;
            float mag1 = mf.y * inv0;
            const int PXC0 = px9c(64 * k);
            const int PXC1 = px9c(64 * k + 32);
            const int P0 = __popc(k) & 1;
            int addr0 = (P0 ? c_sel1 : c_sel0) + ((P0 ? sel1 : sel0) ^ PXC0);
            int addr1 = (P0 ? c_sel0 : c_sel1) + ((P0 ? sel0 : sel1) ^ PXC1);
            tf[addr0] = mag0;
            tf[addr1] = mag1;
        }
    }
    __syncthreads();

    // residual + stats, in place (fp32)
    int i = tid & 7, strip = (tid >> 3) & 1, rb = tid >> 4;
    int gcolL = strip ? (120 - c0 + i) : (c0 + i);
    int cidxL = strip * 8 + i;
    const __half* x0p = g_x0h + (size_t)b * NDIM;
    float cs = 0.f, sq = 0.f;
    #pragma unroll
    for (int it = 0; it < 16; it++) {
        int r = rb + it * 32;
        float vv = tf[cidxL * 513 + r] + __half2float(x0p[r * NE + gcolL]);
        tf[cidxL * 513 + r] = vv;
        cs += vv;  sq += vv * vv;
    }
    cs += __shfl_down_sync(0xffffffffu, cs, 16);
    if (lane < 16) scolp[lane][w] = cs;
    #pragma unroll
    for (int o = 16; o; o >>= 1) sq += __shfl_down_sync(0xffffffffu, sq, o);
    if (lane == 0) atomicAdd(&ssacc, sq);
    __syncthreads();

    if (tid == 0) g_n1p[blockIdx.x] = ssacc;
    if (tid < 16) {
        float scv = 0.f;
        #pragma unroll
        for (int j = 0; j < 16; j++) scv += scolp[tid][j];
        int gc = (tid < 8) ? (c0 + tid) : (112 - c0 + tid);
        g_mA[b * NE + gc] = scv;
    }

    // reload x1 + D(phi)_2 in half2 (pe2t pre-scaled by PC_A2)
    u32 pa2 = hsplat(pe2t[w].x), pb2 = hsplat(pe2t[w].y), pnb2 = hsplat(-pe2t[w].y);
    #pragma unroll
    for (int k = 0; k < 8; k++) {
        float a = tf[w * 513 + lane + 64*k];
        float c = tf[w * 513 + lane + 64*k + 32];
        u32 x1h = hpack(a, c);
        u32 tc = tscH[k*32 + lane], ts = tssH[k*32 + lane];
        u32 c12 = hfma2u(pa2, tc, hmul2u(pnb2, ts));
        u32 s12 = hfma2u(pb2, tc, hmul2u(pa2,  ts));
        Hx[k] = hmul2u(x1h, c12);
        Hy[k] = hmul2u(x1h, s12);
    }
    __syncthreads();   // tf fully consumed before tin16 (aliased) is written

    col_butterflyT(ctB, Hx, Hy, lane);

    // encode e4m3 into tin16 (warp w = output column cidx w)
    #pragma unroll
    for (int k = 0; k < 8; k++) {
        u32 hv0 = __byte_perm(Hx[k], Hy[k], 0x5410);
        u32 hv1 = __byte_perm(Hx[k], Hy[k], 0x7632);
        tin16[w * 522 + lane + 64*k]      = h2e(hv0);
        tin16[w * 522 + lane + 64*k + 32] = h2e(hv1);
    }
    __syncthreads();

    // staging-out: output cols are natural aligned pairs
    int m = i2 & 3;
    int cio  = (i2 < 4) ? (2*m) : (8 + 2*m);
    int wout = (i2 < 4) ? (c0/2 + m) : ((120 - c0)/2 + m);
    u32* stwo = g_state + (size_t)b * (NDIM / 2);
    #pragma unroll
    for (int it = 0; it < 8; it++) {
        int r = rb8 + 64 * it;
        u32 lo = tin16[cio * 522 + r];
        u32 hi = tin16[(cio+1) * 522 + r];
        stwo[r * 64 + wout] = lo | (hi << 16);
    }
}

// ---------------- rowB: B2 emb butterfly, 32 rows, fp8 in ----------------
// Reduction v2: gray-pair u32 half2 loads. For even e, gray(e+1)=gray(e)^1,
// so outputs (e,e+1) live in one aligned u32 word; word = g(p) ^ (par<<5),
// halves swapped when p&1. 64 pairs x 4 row-quarters, 8 loads/thread.

__global__ __launch_bounds__(256) void k_rowB(const float* __restrict__ rp) {
    GDC_LAUNCH();
    __shared__ __align__(16) u32 srow[32][68];
    __shared__ __align__(16) float ryt[7];
    __shared__ __align__(8) u32 pacc[4][65];
    __shared__ float s_inv1;
    __shared__ float s_pcB2;
    int tid = threadIdx.x;
    int b = blockIdx.x >> 4;
    if (tid < 7) {
        float c, sn; sincosf(0.5f * rp[48 + (9 + tid) * 3], &sn, &c);
        ryt[tid] = sn / c;
    }
    if (tid == 33) {
        float pc = 1.f;
        #pragma unroll
        for (int w = 9; w < 16; w++) pc *= cosf(0.5f * rp[48 + w * 3]);
        s_pcB2 = pc;
    }

    GDC_WAIT();   // colA data visible after this

    if (tid == 32) {
        float t1 = 0.f;
        #pragma unroll
        for (int j = 0; j < 8; j++) t1 += g_n1p[b * 8 + j];
        s_inv1 = rsqrtf(t1);
    }
    __syncthreads();
    int warp = tid >> 5, lane = tid & 31, rl = lane >> 3, t = lane & 7;
    int rls = warp * 4 + rl;
    int row = blockIdx.x * 32 + rls;
    u32 pcb = hsplat(s_pcB2);
    const uint4* src = (const uint4*)(g_state + (size_t)row * 64 + 8 * t);
    uint4 U0 = src[0], U1 = src[1];
    u32 wd[8] = {U0.x, U0.y, U0.z, U0.w, U1.x, U1.y, U1.z, U1.w};
    u32 Hx[8], Hy[8];
    #pragma unroll
    for (int k = 0; k < 8; k++) {
        u32 ha = e2h((u16)wd[k]);
        u32 hb = e2h((u16)(wd[k] >> 16));
        Hx[k] = hmul2u(pcb, __byte_perm(ha, hb, 0x5410));
        Hy[k] = hmul2u(pcb, __byte_perm(ha, hb, 0x7632));
    }

    row_butterflyT(ryt, Hx, Hy, t);

    u32 hm[8];
    #pragma unroll
    for (int k = 0; k < 8; k++) {
        u32 msq = hfma2u(Hx[k], Hx[k], hmul2u(Hy[k], Hy[k]));
        hm[k] = h2u(h2sqrt(u2h(msq)));
    }
    uint4* wp = (uint4*)&srow[rls][8 * t];
    wp[0] = make_uint4(hm[0], hm[1], hm[2], hm[3]);
    wp[1] = make_uint4(hm[4], hm[5], hm[6], hm[7]);
    __syncthreads();

    // gray-pair reduction: p = pair id (e = 2p, 2p+1), qtr = row quarter
    int p = tid & 63, qtr = tid >> 6;
    int sbase = (blockIdx.x * 32) & (NS - 1);
    int wbase = p ^ (p >> 1);                         // g(p)
    int pq0 = (__popc(sbase) ^ __popc(qtr)) & 1;
    int wA = wbase ^ (pq0 << 5);
    int wB = wA ^ 32;
    u32 acc = 0;
    #pragma unroll
    for (int q = 0; q < 8; q++) {
        int r = qtr * 8 + q;
        int wq = ((0x96 >> q) & 1) ? wB : wA;
        acc = hadd2u(acc, srow[r][wq]);
    }
    if (p & 1) acc = hswap(acc);                      // lo = e even
    pacc[qtr][p] = acc;
    __syncthreads();
    if (tid < 64) {
        float2 s0 = h22f2(pacc[0][tid]), s1 = h22f2(pacc[1][tid]);
        float2 s2 = h22f2(pacc[2][tid]), s3 = h22f2(pacc[3][tid]);
        float2 o;
        o.x = (s0.x + s1.x + s2.x + s3.x) * s_inv1;
        o.y = (s0.y + s1.y + s2.y + s3.y) * s_inv1;
        *reinterpret_cast<float2*>(&g_mB[blockIdx.x * NE + 2 * tid]) = o;
    }
}

// ---------------- W2 = clsw @ ffw (4x128), b2 = clsw @ ffb ----------------

__global__ __launch_bounds__(128) void k_w2(const float* __restrict__ ffw,
                                            const float* __restrict__ ffb,
                                            const float* __restrict__ clsw) {
    GDC_LAUNCH();
    int c = blockIdx.x, e = threadIdx.x;
    float acc = 0.f;
    #pragma unroll 4
    for (int j = 0; j < 128; j++) acc += clsw[c * 128 + j] * ffw[j * 128 + e];
    g_W2[c * 128 + e] = acc;
    __shared__ float sb[128];
    sb[e] = clsw[c * 128 + e] * ffb[e];
    __syncthreads();
    #pragma unroll
    for (int o = 64; o; o >>= 1) {
        if (e < o) sb[e] += sb[e + o];
        __syncthreads();
    }
    if (e == 0) g_b2[c] = sb[0];
}

// ---------------- final: mean assembly + 4x128 dot ----------------

__global__ __launch_bounds__(256) void k_final(float* __restrict__ out) {
    GDC_WAIT();
    int b = blockIdx.x, tid = threadIdx.x;
    __shared__ float mm[128];
    __shared__ float m2[256];
    int e = tid & 127, hi = tid >> 7;
    const float* mb = g_mB + (size_t)b * 16 * NE;
    float m = hi ? 0.f : g_mA[b * NE + e];
    #pragma unroll
    for (int i2 = 0; i2 < 8; i2++) m += mb[(hi * 8 + i2) * NE + e];
    m2[tid] = m;
    __syncthreads();
    if (hi == 0) mm[e] = (m + m2[e + 128]) * (1.f / 512.f);
    __syncthreads();
    int w = tid >> 5, lane = tid & 31;
    if (w < 4) {
        float acc = 0.f;
        #pragma unroll
        for (int q = 0; q < 4; q++) {
            int ee = lane + 32 * q;
            acc += mm[ee] * g_W2[w * 128 + ee];
        }
        #pragma unroll
        for (int o = 16; o; o >>= 1) acc += __shfl_down_sync(0xffffffffu, acc, o);
        if (lane == 0) out[b * 4 + w] = acc + g_b2[w];
    }
}

// ---------------- launch (PDL chain) ----------------

extern "C" void kernel_launch(void* const* d_in, const int* in_sizes, int n_in,
                              void* d_out, int out_size) {
    const int*   tokens = (const int*)  d_in[0];
    const float* temb   = (const float*)d_in[1];
    const float* pemb   = (const float*)d_in[2];
    const float* rotp   = (const float*)d_in[3];
    const float* ffw    = (const float*)d_in[4];
    const float* ffb    = (const float*)d_in[5];
    const float* clsw   = (const float*)d_in[6];
    float* out = (float*)d_out;

    cudaLaunchAttribute pdl[1];
    pdl[0].id = cudaLaunchAttributeProgrammaticStreamSerialization;
    pdl[0].val.programmaticStreamSerializationAllowed = 1;

    k_w2<<<4, 128>>>(ffw, ffb, clsw);

    {   cudaLaunchConfig_t cfg = {};
        cfg.gridDim = dim3(NB * NS / 64); cfg.blockDim = dim3(256);
        cfg.attrs = pdl; cfg.numAttrs = 1;
        cudaLaunchKernelEx(&cfg, k_embed_row, tokens, temb, pemb, rotp);
    }
    {   cudaLaunchConfig_t cfg = {};
        cfg.gridDim = dim3(NB * 8); cfg.blockDim = dim3(512);
        cfg.attrs = pdl; cfg.numAttrs = 1;
        cudaLaunchKernelEx(&cfg, k_colA, rotp);
    }
    {   cudaLaunchConfig_t cfg = {};
        cfg.gridDim = dim3(NB * NS / 32); cfg.blockDim = dim3(256);
        cfg.attrs = pdl; cfg.numAttrs = 1;
        cudaLaunchKernelEx(&cfg, k_rowB, rotp);
    }
    {   cudaLaunchConfig_t cfg = {};
        cfg.gridDim = dim3(NB); cfg.blockDim = dim3(256);
        cfg.attrs = pdl; cfg.numAttrs = 1;
        cudaLaunchKernelEx(&cfg, k_final, out);
    }
}